// round 1
// baseline (speedup 1.0000x reference)
#include <cuda_runtime.h>
#include <cuda_bf16.h>

// ---------------------------------------------------------------------------
// GraphAttentionNet: 2-layer GAT (H=4) + BN/ELU, N=4096, dense adjacency.
//   x[4096,512], adj[4096,4096] int32
//   L1: h1=x@W1 [4096,4,128]; e=lrelu(es_i+ed_j) masked softmax; x1=attn@h1
//   x2 = BN_ELU(x1@lw1+lb1) [4096,64]
//   L2: h2=x2@W2 [4096,4,32]; same attention; x3 [4096,128]
//   out = BN_ELU(x3@lw2+lb2) [4096,16]
// ---------------------------------------------------------------------------

#define NN 4096
#define HH 4

// ---- scratch (static device allocations only) ----
__device__ unsigned g_adjbits[NN * 128];          // 2 MB bitmask
__device__ float g_h1[NN * 512];
__device__ float g_es1[HH * NN], g_ed1[HH * NN], g_maxed1[HH];
__device__ float g_x1[NN * 512];
__device__ float g_y1[NN * 64];
__device__ float g_x2[NN * 64];
__device__ float g_h2[NN * 128];
__device__ float g_es2[HH * NN], g_ed2[HH * NN], g_maxed2[HH];
__device__ float g_x3[NN * 128];
__device__ float g_y2[NN * 16];

// ---------------------------------------------------------------------------
// adj -> bitmask. One warp builds one 32-bit word via ballot (coalesced).
// ---------------------------------------------------------------------------
__global__ void pack_adj_kernel(const int* __restrict__ adj) {
    int gw = blockIdx.x * 8 + (threadIdx.x >> 5);     // global warp id
    int lane = threadIdx.x & 31;
    int row = gw >> 7, word = gw & 127;
    int v = adj[row * NN + word * 32 + lane];
    unsigned m = __ballot_sync(0xffffffffu, v > 0);
    if (lane == 0) g_adjbits[gw] = m;
}

// ---------------------------------------------------------------------------
// Generic tiled SGEMM: C[M,Nc] = A[M,K] @ B[K,Nc] (+ bias). BM=64, BK=32.
// threads = (BM/TM)*(BN/TN) = 256.
// ---------------------------------------------------------------------------
template <int BN, int TM, int TN>
__global__ void gemm_bias_kernel(const float* __restrict__ A,
                                 const float* __restrict__ B,
                                 const float* __restrict__ bias,
                                 float* __restrict__ C,
                                 int M, int K, int Nc) {
    const int BM = 64, BK = 32;
    __shared__ float sA[BK][BM + 4];
    __shared__ float sB[BK][BN + 4];

    int tid = threadIdx.x;
    const int CT = BN / TN;            // threads along columns
    int tx = tid % CT;
    int ty = tid / CT;

    int row0 = blockIdx.x * BM;
    int c0 = blockIdx.y * BN;

    float acc[TM][TN];
#pragma unroll
    for (int i = 0; i < TM; i++)
#pragma unroll
        for (int j = 0; j < TN; j++) acc[i][j] = 0.f;

    for (int k0 = 0; k0 < K; k0 += BK) {
        __syncthreads();
        // load A tile (BMxBK), store transposed
        for (int v = tid; v < BM * BK / 4; v += 256) {
            int idx = v * 4;
            int r = idx / BK, kk = idx % BK;
            float4 f = *reinterpret_cast<const float4*>(&A[(size_t)(row0 + r) * K + k0 + kk]);
            sA[kk + 0][r] = f.x; sA[kk + 1][r] = f.y;
            sA[kk + 2][r] = f.z; sA[kk + 3][r] = f.w;
        }
        // load B tile (BKxBN)
        for (int v = tid; v < BK * BN / 4; v += 256) {
            int idx = v * 4;
            int kk = idx / BN, c = idx % BN;
            float4 f = *reinterpret_cast<const float4*>(&B[(size_t)(k0 + kk) * Nc + c0 + c]);
            *reinterpret_cast<float4*>(&sB[kk][c]) = f;
        }
        __syncthreads();

#pragma unroll
        for (int kk = 0; kk < BK; kk++) {
            float a[TM], b[TN];
#pragma unroll
            for (int i = 0; i < TM; i++) a[i] = sA[kk][ty * TM + i];
#pragma unroll
            for (int j = 0; j < TN; j++) b[j] = sB[kk][tx * TN + j];
#pragma unroll
            for (int i = 0; i < TM; i++)
#pragma unroll
                for (int j = 0; j < TN; j++) acc[i][j] = fmaf(a[i], b[j], acc[i][j]);
        }
    }

#pragma unroll
    for (int j = 0; j < TN; j++) {
        int c = c0 + tx * TN + j;
        float bv = bias ? bias[c] : 0.f;
#pragma unroll
        for (int i = 0; i < TM; i++) {
            int r = row0 + ty * TM + i;
            C[(size_t)r * Nc + c] = acc[i][j] + bv;
        }
    }
}

// ---------------------------------------------------------------------------
// es/ed projection: es[h,i] = dot(H[i, h*F:(h+1)*F], a_src[h]); same for ed.
// One block per node i, one warp per head.
// ---------------------------------------------------------------------------
__global__ void attn_proj_kernel(const float* __restrict__ Hm,
                                 const float* __restrict__ as_,
                                 const float* __restrict__ ad_,
                                 float* __restrict__ es, float* __restrict__ ed,
                                 int F) {
    int i = blockIdx.x;
    int w = threadIdx.x >> 5, l = threadIdx.x & 31;
    const float* hp = Hm + (size_t)i * (HH * F) + w * F;
    const float* sp = as_ + w * F;
    const float* dp = ad_ + w * F;
    float s = 0.f, d = 0.f;
    for (int f = l; f < F; f += 32) {
        float v = hp[f];
        s += v * sp[f];
        d += v * dp[f];
    }
#pragma unroll
    for (int o = 16; o; o >>= 1) {
        s += __shfl_down_sync(0xffffffffu, s, o);
        d += __shfl_down_sync(0xffffffffu, d, o);
    }
    if (l == 0) { es[w * NN + i] = s; ed[w * NN + i] = d; }
}

// per-head max of ed (upper bound for softmax shift)
__global__ void maxed_kernel(const float* __restrict__ ed, float* __restrict__ mx) {
    int h = blockIdx.x;
    float m = -1e30f;
    for (int i = threadIdx.x; i < NN; i += 256) m = fmaxf(m, ed[h * NN + i]);
    __shared__ float sm_[256];
    sm_[threadIdx.x] = m;
    __syncthreads();
    for (int s = 128; s; s >>= 1) {
        if (threadIdx.x < s) sm_[threadIdx.x] = fmaxf(sm_[threadIdx.x], sm_[threadIdx.x + s]);
        __syncthreads();
    }
    if (threadIdx.x == 0) mx[h] = sm_[0];
}

// ---------------------------------------------------------------------------
// Fused masked-softmax attention aggregation (flash-style, single pass):
//   Out[i, h*F+f] = sum_j p(i,j) * H[j, h*F+f] / sum_j p(i,j)
//   p = adj(i,j) ? exp(lrelu(es_i+ed_j) - lrelu(es_i+max_ed)) : 0
// Block: 64 rows x F cols for one head; j processed in tiles of 32.
// ---------------------------------------------------------------------------
template <int F, int TN>
__global__ void gat_attn_kernel(const float* __restrict__ Hm,
                                const float* __restrict__ es,
                                const float* __restrict__ ed,
                                const float* __restrict__ maxed,
                                float* __restrict__ Out) {
    const int BM = 64, BJ = 32, TM = 4;
    int h = blockIdx.y;
    int i0 = blockIdx.x * BM;
    int tid = threadIdx.x;

    __shared__ float sh[BJ][F];          // j-tile features
    __shared__ float sp[BM][BJ + 1];     // attention weights tile
    __shared__ float ses[BM], sm[BM], ssum[BM];

    if (tid < BM) {
        float e = es[h * NN + i0 + tid];
        ses[tid] = e;
        float z = e + maxed[h];
        sm[tid] = z > 0.f ? z : 0.2f * z;
        ssum[tid] = 0.f;
    }

    float acc[TM][TN];
#pragma unroll
    for (int i = 0; i < TM; i++)
#pragma unroll
        for (int j = 0; j < TN; j++) acc[i][j] = 0.f;

    int ty = tid / 16, tx = tid % 16;        // 16x16 thread grid for MAC
    int prow = tid >> 2, pquad = tid & 3;    // 64x4 grid for p-gen (8 j each)
    const float* edh = ed + h * NN;

    for (int jt = 0; jt < NN / BJ; jt++) {
        __syncthreads();  // prev MAC done with sh/sp; init visible on iter 0

        // load H j-tile into smem (coalesced float4)
        const int NF4 = BJ * F / 4;
        for (int v = tid; v < NF4; v += 256) {
            int r = v / (F / 4), c4 = v % (F / 4);
            float4 f = *reinterpret_cast<const float4*>(
                &Hm[(size_t)(jt * BJ + r) * (HH * F) + h * F + c4 * 4]);
            *reinterpret_cast<float4*>(&sh[r][c4 * 4]) = f;
        }

        // generate attention weights p for this tile
        {
            unsigned word = g_adjbits[(size_t)(i0 + prow) * 128 + jt];
            float esr = ses[prow], mr = sm[prow];
            float psum = 0.f;
#pragma unroll
            for (int jj = 0; jj < 8; jj++) {
                int j = pquad * 8 + jj;
                float e = esr + edh[jt * BJ + j];
                float lr = e > 0.f ? e : 0.2f * e;
                float p = ((word >> j) & 1u) ? __expf(lr - mr) : 0.f;
                sp[prow][j] = p;
                psum += p;
            }
            atomicAdd(&ssum[prow], psum);
        }
        __syncthreads();

        // MAC: acc += P(64x32) @ sh(32xF)
#pragma unroll
        for (int kk = 0; kk < BJ; kk++) {
            float a[TM];
#pragma unroll
            for (int i = 0; i < TM; i++) a[i] = sp[ty * TM + i][kk];
            float b[TN];
#pragma unroll
            for (int j = 0; j < TN; j += 4) {
                if (TN >= 4) {
                    float4 f = *reinterpret_cast<const float4*>(&sh[kk][tx * TN + j]);
                    b[j] = f.x; b[j + 1] = f.y; b[j + 2] = f.z; b[j + 3] = f.w;
                }
            }
            if (TN < 4) {
#pragma unroll
                for (int j = 0; j < TN; j++) b[j] = sh[kk][tx * TN + j];
            }
#pragma unroll
            for (int i = 0; i < TM; i++)
#pragma unroll
                for (int j = 0; j < TN; j++) acc[i][j] = fmaf(a[i], b[j], acc[i][j]);
        }
    }
    __syncthreads();

#pragma unroll
    for (int i = 0; i < TM; i++) {
        int r = ty * TM + i;
        float rinv = 1.f / ssum[r];
#pragma unroll
        for (int j = 0; j < TN; j++) {
            Out[(size_t)(i0 + r) * (HH * F) + h * F + tx * TN + j] = acc[i][j] * rinv;
        }
    }
}

// ---------------------------------------------------------------------------
// BatchNorm (population stats over axis 0) + ELU. One block per column.
// ---------------------------------------------------------------------------
__global__ void bn_elu_kernel(const float* __restrict__ Y,
                              const float* __restrict__ gamma,
                              const float* __restrict__ beta,
                              float* __restrict__ Out, int C) {
    int c = blockIdx.x;
    float s1 = 0.f, s2 = 0.f;
    for (int i = threadIdx.x; i < NN; i += 256) {
        float v = Y[(size_t)i * C + c];
        s1 += v;
        s2 += v * v;
    }
    __shared__ float r1[256], r2[256];
    r1[threadIdx.x] = s1; r2[threadIdx.x] = s2;
    __syncthreads();
    for (int s = 128; s; s >>= 1) {
        if (threadIdx.x < s) {
            r1[threadIdx.x] += r1[threadIdx.x + s];
            r2[threadIdx.x] += r2[threadIdx.x + s];
        }
        __syncthreads();
    }
    float mean = r1[0] * (1.f / NN);
    float var = r2[0] * (1.f / NN) - mean * mean;
    float inv = rsqrtf(var + 1e-5f);
    float g = gamma[c], b = beta[c];
    for (int i = threadIdx.x; i < NN; i += 256) {
        float v = Y[(size_t)i * C + c];
        float z = (v - mean) * inv * g + b;
        Out[(size_t)i * C + c] = z > 0.f ? z : (__expf(z) - 1.f);
    }
}

// ---------------------------------------------------------------------------
extern "C" void kernel_launch(void* const* d_in, const int* in_sizes, int n_in,
                              void* d_out, int out_size) {
    const float* x   = (const float*)d_in[0];
    const int*   adj = (const int*)d_in[1];
    const float* W1  = (const float*)d_in[2];
    const float* a1s = (const float*)d_in[3];
    const float* a1d = (const float*)d_in[4];
    const float* lw1 = (const float*)d_in[5];
    const float* lb1 = (const float*)d_in[6];
    const float* g1  = (const float*)d_in[7];
    const float* be1 = (const float*)d_in[8];
    const float* W2  = (const float*)d_in[9];
    const float* a2s = (const float*)d_in[10];
    const float* a2d = (const float*)d_in[11];
    const float* lw2 = (const float*)d_in[12];
    const float* lb2 = (const float*)d_in[13];
    const float* g2  = (const float*)d_in[14];
    const float* be2 = (const float*)d_in[15];
    float* out = (float*)d_out;

    float *p_h1, *p_es1, *p_ed1, *p_mx1, *p_x1, *p_y1, *p_x2;
    float *p_h2, *p_es2, *p_ed2, *p_mx2, *p_x3, *p_y2;
    cudaGetSymbolAddress((void**)&p_h1, g_h1);
    cudaGetSymbolAddress((void**)&p_es1, g_es1);
    cudaGetSymbolAddress((void**)&p_ed1, g_ed1);
    cudaGetSymbolAddress((void**)&p_mx1, g_maxed1);
    cudaGetSymbolAddress((void**)&p_x1, g_x1);
    cudaGetSymbolAddress((void**)&p_y1, g_y1);
    cudaGetSymbolAddress((void**)&p_x2, g_x2);
    cudaGetSymbolAddress((void**)&p_h2, g_h2);
    cudaGetSymbolAddress((void**)&p_es2, g_es2);
    cudaGetSymbolAddress((void**)&p_ed2, g_ed2);
    cudaGetSymbolAddress((void**)&p_mx2, g_maxed2);
    cudaGetSymbolAddress((void**)&p_x3, g_x3);
    cudaGetSymbolAddress((void**)&p_y2, g_y2);

    // 1) pack adjacency into bitmask (read adj once: 64 MB)
    pack_adj_kernel<<<NN * 128 / 8, 256>>>(adj);

    // 2) h1 = x @ W1   [4096,512]@[512,512]
    gemm_bias_kernel<64, 4, 4><<<dim3(64, 8), 256>>>(x, W1, nullptr, p_h1, NN, 512, 512);

    // 3) es/ed projections + per-head max
    attn_proj_kernel<<<NN, 128>>>(p_h1, a1s, a1d, p_es1, p_ed1, 128);
    maxed_kernel<<<HH, 256>>>(p_ed1, p_mx1);

    // 4) layer-1 attention aggregation -> x1 [4096,512]
    gat_attn_kernel<128, 8><<<dim3(64, HH), 256>>>(p_h1, p_es1, p_ed1, p_mx1, p_x1);

    // 5) y1 = x1 @ lw1 + lb1 ; x2 = BN_ELU(y1)  [4096,64]
    gemm_bias_kernel<64, 4, 4><<<dim3(64, 1), 256>>>(p_x1, lw1, lb1, p_y1, NN, 512, 64);
    bn_elu_kernel<<<64, 256>>>(p_y1, g1, be1, p_x2, 64);

    // 6) h2 = x2 @ W2  [4096,64]@[64,128]
    gemm_bias_kernel<64, 4, 4><<<dim3(64, 2), 256>>>(p_x2, W2, nullptr, p_h2, NN, 64, 128);

    // 7) layer-2 attention
    attn_proj_kernel<<<NN, 128>>>(p_h2, a2s, a2d, p_es2, p_ed2, 32);
    maxed_kernel<<<HH, 256>>>(p_ed2, p_mx2);
    gat_attn_kernel<32, 2><<<dim3(64, HH), 256>>>(p_h2, p_es2, p_ed2, p_mx2, p_x3);

    // 8) y2 = x3 @ lw2 + lb2 ; out = BN_ELU(y2)  [4096,16]
    gemm_bias_kernel<16, 4, 1><<<dim3(64, 1), 256>>>(p_x3, lw2, lb2, p_y2, NN, 128, 16);
    bn_elu_kernel<<<16, 256>>>(p_y2, g2, be2, out, 16);
}

// round 3
// speedup vs baseline: 2.1370x; 2.1370x over previous
#include <cuda_runtime.h>
#include <cuda_bf16.h>
#include <cstdint>

#define NN 4096
#define HH 4

// ---------------------------------------------------------------------------
// scratch (static device allocations only)
// ---------------------------------------------------------------------------
__device__ unsigned g_adjbits[NN * 128];          // 2 MB bitmask
__device__ float g_h1[NN * 512];
__device__ float g_es1[HH * NN], g_ed1[HH * NN], g_maxed1[HH];
__device__ float g_x1[NN * 512];
__device__ float g_y1[NN * 64];
__device__ float g_x2[NN * 64];
__device__ float g_h2[NN * 128];
__device__ float g_es2[HH * NN], g_ed2[HH * NN], g_maxed2[HH];
__device__ float g_x3[NN * 128];
__device__ float g_y2[NN * 16];
// transposed split-bf16 feature matrices: [HF][NN] raw-bf16 as ushort
__device__ unsigned short g_ht1_hi[512 * NN], g_ht1_lo[512 * NN];
__device__ unsigned short g_ht2_hi[128 * NN], g_ht2_lo[128 * NN];

// ---------------------------------------------------------------------------
// helpers
// ---------------------------------------------------------------------------
__device__ __forceinline__ uint32_t smem_u32(const void* p) {
    uint32_t a;
    asm("{ .reg .u64 t; cvta.to.shared.u64 t, %1; cvt.u32.u64 %0, t; }"
        : "=r"(a) : "l"(p));
    return a;
}
__device__ __forceinline__ uint32_t prmt7632(uint32_t a, uint32_t b) {
    uint32_t r;
    asm("prmt.b32 %0, %1, %2, 0x7632;" : "=r"(r) : "r"(a), "r"(b));
    return r;
}

#define CP_ASYNC16(saddr, gptr) \
    asm volatile("cp.async.cg.shared.global [%0], [%1], 16;" \
                 :: "r"((uint32_t)(saddr)), "l"(gptr))
#define CP_COMMIT() asm volatile("cp.async.commit_group;" ::: "memory")
#define CP_WAIT0()  asm volatile("cp.async.wait_group 0;" ::: "memory")

__device__ __forceinline__ void ldsm_x4(uint32_t* r, uint32_t addr) {
    asm volatile("ldmatrix.sync.aligned.m8n8.x4.shared.b16 {%0,%1,%2,%3}, [%4];"
                 : "=r"(r[0]), "=r"(r[1]), "=r"(r[2]), "=r"(r[3]) : "r"(addr));
}
__device__ __forceinline__ void mma16816(float* c, const uint32_t* a,
                                         uint32_t b0, uint32_t b1) {
    asm volatile(
        "mma.sync.aligned.m16n8k16.row.col.f32.bf16.bf16.f32 "
        "{%0,%1,%2,%3}, {%4,%5,%6,%7}, {%8,%9}, {%0,%1,%2,%3};"
        : "+f"(c[0]), "+f"(c[1]), "+f"(c[2]), "+f"(c[3])
        : "r"(a[0]), "r"(a[1]), "r"(a[2]), "r"(a[3]), "r"(b0), "r"(b1));
}

// ---------------------------------------------------------------------------
// adj -> bitmask (one warp per 32-bit word via ballot)
// ---------------------------------------------------------------------------
__global__ void pack_adj_kernel(const int* __restrict__ adj) {
    int gw = blockIdx.x * 8 + (threadIdx.x >> 5);
    int lane = threadIdx.x & 31;
    int row = gw >> 7, word = gw & 127;
    int v = adj[(size_t)row * NN + word * 32 + lane];
    unsigned m = __ballot_sync(0xffffffffu, v > 0);
    if (lane == 0) g_adjbits[gw] = m;
}

// ---------------------------------------------------------------------------
// Tiled fp32 SGEMM (+ optional bias). BK=32, BM=64, 256 threads.
// ---------------------------------------------------------------------------
template <int BN, int TM, int TN>
__global__ void gemm_bias_kernel(const float* __restrict__ A,
                                 const float* __restrict__ B,
                                 const float* __restrict__ bias,
                                 float* __restrict__ C,
                                 int M, int K, int Nc) {
    const int BM = 64, BK = 32;
    __shared__ float sA[BK][BM + 4];
    __shared__ float sB[BK][BN + 4];

    int tid = threadIdx.x;
    const int CT = BN / TN;
    int tx = tid % CT;
    int ty = tid / CT;

    int row0 = blockIdx.x * BM;
    int c0 = blockIdx.y * BN;

    float acc[TM][TN];
#pragma unroll
    for (int i = 0; i < TM; i++)
#pragma unroll
        for (int j = 0; j < TN; j++) acc[i][j] = 0.f;

    for (int k0 = 0; k0 < K; k0 += BK) {
        __syncthreads();
        for (int v = tid; v < BM * BK / 4; v += 256) {
            int idx = v * 4;
            int r = idx >> 5, kk = idx & 31;
            float4 f = *reinterpret_cast<const float4*>(&A[(size_t)(row0 + r) * K + k0 + kk]);
            sA[kk + 0][r] = f.x; sA[kk + 1][r] = f.y;
            sA[kk + 2][r] = f.z; sA[kk + 3][r] = f.w;
        }
        for (int v = tid; v < BK * BN / 4; v += 256) {
            int idx = v * 4;
            int kk = idx / BN, c = idx % BN;
            float4 f = *reinterpret_cast<const float4*>(&B[(size_t)(k0 + kk) * Nc + c0 + c]);
            *reinterpret_cast<float4*>(&sB[kk][c]) = f;
        }
        __syncthreads();

#pragma unroll
        for (int kk = 0; kk < BK; kk++) {
            float a[TM], b[TN];
#pragma unroll
            for (int i = 0; i < TM; i++) a[i] = sA[kk][ty * TM + i];
#pragma unroll
            for (int j = 0; j < TN; j++) b[j] = sB[kk][tx * TN + j];
#pragma unroll
            for (int i = 0; i < TM; i++)
#pragma unroll
                for (int j = 0; j < TN; j++) acc[i][j] = fmaf(a[i], b[j], acc[i][j]);
        }
    }

#pragma unroll
    for (int j = 0; j < TN; j++) {
        int c = c0 + tx * TN + j;
        float bv = bias ? bias[c] : 0.f;
#pragma unroll
        for (int i = 0; i < TM; i++) {
            int r = row0 + ty * TM + i;
            C[(size_t)r * Nc + c] = acc[i][j] + bv;
        }
    }
}

// ---------------------------------------------------------------------------
// es/ed projections (one block per node, one warp per head)
// ---------------------------------------------------------------------------
__global__ void attn_proj_kernel(const float* __restrict__ Hm,
                                 const float* __restrict__ as_,
                                 const float* __restrict__ ad_,
                                 float* __restrict__ es, float* __restrict__ ed,
                                 int F) {
    int i = blockIdx.x;
    int w = threadIdx.x >> 5, l = threadIdx.x & 31;
    const float* hp = Hm + (size_t)i * (HH * F) + w * F;
    const float* sp = as_ + w * F;
    const float* dp = ad_ + w * F;
    float s = 0.f, d = 0.f;
    for (int f = l; f < F; f += 32) {
        float v = hp[f];
        s += v * sp[f];
        d += v * dp[f];
    }
#pragma unroll
    for (int o = 16; o; o >>= 1) {
        s += __shfl_down_sync(0xffffffffu, s, o);
        d += __shfl_down_sync(0xffffffffu, d, o);
    }
    if (l == 0) { es[w * NN + i] = s; ed[w * NN + i] = d; }
}

__global__ void maxed_kernel(const float* __restrict__ ed, float* __restrict__ mx) {
    int h = blockIdx.x;
    float m = -1e30f;
    for (int i = threadIdx.x; i < NN; i += 256) m = fmaxf(m, ed[h * NN + i]);
    __shared__ float sm_[256];
    sm_[threadIdx.x] = m;
    __syncthreads();
    for (int s = 128; s; s >>= 1) {
        if (threadIdx.x < s) sm_[threadIdx.x] = fmaxf(sm_[threadIdx.x], sm_[threadIdx.x + s]);
        __syncthreads();
    }
    if (threadIdx.x == 0) mx[h] = sm_[0];
}

// ---------------------------------------------------------------------------
// Transpose + truncation-split to bf16(hi)/bf16(lo): A[NN,HF] -> hi/lo[HF][NN]
// ---------------------------------------------------------------------------
__global__ void transpose_split_kernel(const float* __restrict__ A,
                                       unsigned short* __restrict__ hi,
                                       unsigned short* __restrict__ lo, int HF) {
    __shared__ float tile[32][33];
    int j0 = blockIdx.x * 32, c0 = blockIdx.y * 32;
    int tx = threadIdx.x, ty = threadIdx.y;
    for (int r = ty; r < 32; r += 8)
        tile[r][tx] = A[(size_t)(j0 + r) * HF + c0 + tx];
    __syncthreads();
    for (int r = ty; r < 32; r += 8) {
        float v = tile[tx][r];                           // element (j0+tx, c0+r)
        uint32_t b = __float_as_uint(v);
        uint32_t hb = b & 0xffff0000u;
        float lv = v - __uint_as_float(hb);
        size_t o = (size_t)(c0 + r) * NN + j0 + tx;
        hi[o] = (unsigned short)(hb >> 16);
        lo[o] = (unsigned short)(__float_as_uint(lv) >> 16);
    }
}

// ---------------------------------------------------------------------------
// Fused GAT attention via mma.sync bf16 (3-term split for fp32 accuracy):
//   acc += Phi@Hhi^T + Phi@Hlo^T + Plo@Hhi^T
// Block: one head, 128 rows; j in tiles of 64; cp.async double-buffered H.
// smem rows padded to 72 bf16 (stride 144B == 16 mod 128 -> ldmatrix
// conflict-free).
// ---------------------------------------------------------------------------
template <int F>
__global__ void __launch_bounds__(256, 1)
gat_attn_mma(const unsigned short* __restrict__ Bhi,
             const unsigned short* __restrict__ Blo,
             const float* __restrict__ es, const float* __restrict__ ed,
             const float* __restrict__ maxed, float* __restrict__ Out) {
    constexpr int KT = 64;
    constexpr int T = NN / KT;                    // 64 tiles
    constexpr int WC = (F == 128) ? 2 : 1;        // warp col groups
    constexpr int MT = WC;                        // m16 tiles per warp
    constexpr int NT = F / (8 * WC);              // n8 tiles per warp
    constexpr uint32_t ROWB = 144;                // 72 bf16 per smem row
    constexpr uint32_t PBYTES = 128 * ROWB;       // 18432
    constexpr uint32_t HBYTES = (uint32_t)F * ROWB;

    extern __shared__ __align__(16) char dsm[];
    uint32_t sb = smem_u32(dsm);
    const uint32_t SUMS = sb;                     // 512 B
    const uint32_t P0 = sb + 512;                 // Phi[2], Plo[2]
    const uint32_t H0 = P0 + 4 * PBYTES;          // Hhi[2], Hlo[2]

    int tid = threadIdx.x;
    int wid = tid >> 5, lane = tid & 31;
    int h = blockIdx.y;
    int i0 = blockIdx.x * 128;

    // warp tile
    int wr = wid / WC, wc = wid % WC;
    int m0 = wr * (16 * MT);
    int n0 = wc * (NT * 8);

    // ldmatrix per-lane address components
    uint32_t pA = (uint32_t)(m0 + (lane & 15)) * ROWB + ((lane >> 4) << 4);
    uint32_t pB = (uint32_t)(((lane >> 4) << 3) + (lane & 7)) * ROWB +
                  (((lane >> 3) & 1) << 4) + (uint32_t)n0 * ROWB;

    // p-gen assignment: 2 threads per row, 32 j each
    int irow = tid >> 1;
    int jhalf = tid & 1;
    float esr = es[h * NN + i0 + irow];
    float zz = esr + maxed[h];
    float mr = fmaxf(zz, 0.2f * zz);
    const float* edh = ed + h * NN;
    float psum = 0.f;
    uint32_t poff = (uint32_t)irow * ROWB + (uint32_t)jhalf * 64;

    float acc[MT][NT][4];
#pragma unroll
    for (int mi = 0; mi < MT; mi++)
#pragma unroll
        for (int nt = 0; nt < NT; nt++)
#pragma unroll
            for (int q = 0; q < 4; q++) acc[mi][nt][q] = 0.f;

    auto load_H = [&](int t, int b) {
        const char* gh = (const char*)Bhi + ((size_t)h * F * NN + (size_t)t * KT) * 2;
        const char* gl = (const char*)Blo + ((size_t)h * F * NN + (size_t)t * KT) * 2;
        uint32_t dh = H0 + (uint32_t)b * HBYTES;
        uint32_t dl = H0 + (uint32_t)(2 + b) * HBYTES;
#pragma unroll
        for (int v = tid; v < F * 8; v += 256) {
            int f = v >> 3;
            uint32_t c = (uint32_t)(v & 7) << 4;
            uint32_t so = (uint32_t)f * ROWB + c;
            CP_ASYNC16(dh + so, gh + (size_t)f * NN * 2 + c);
            CP_ASYNC16(dl + so, gl + (size_t)f * NN * 2 + c);
        }
    };

    auto pgen = [&](int t, int b) {
        uint32_t dh = P0 + (uint32_t)b * PBYTES + poff;
        uint32_t dl = P0 + (uint32_t)(2 + b) * PBYTES + poff;
        unsigned word = g_adjbits[(size_t)(i0 + irow) * 128 + t * 2 + jhalf];
        const float* edp = edh + t * KT + jhalf * 32;
#pragma unroll
        for (int jj = 0; jj < 32; jj += 8) {
            float4 e0 = __ldg((const float4*)(edp + jj));
            float4 e1 = __ldg((const float4*)(edp + jj + 4));
            float ee[8] = {e0.x, e0.y, e0.z, e0.w, e1.x, e1.y, e1.z, e1.w};
            uint32_t hbits[8], lbits[8];
#pragma unroll
            for (int u = 0; u < 8; u++) {
                float e = esr + ee[u];
                float lr = fmaxf(e, 0.2f * e);
                float p = __expf(lr - mr);
                p = ((word >> (jj + u)) & 1u) ? p : 0.f;
                psum += p;
                uint32_t pb = __float_as_uint(p);
                uint32_t hb = pb & 0xffff0000u;
                hbits[u] = hb;
                lbits[u] = __float_as_uint(p - __uint_as_float(hb));
            }
            uint4 hv, lv;
            hv.x = prmt7632(hbits[0], hbits[1]);
            hv.y = prmt7632(hbits[2], hbits[3]);
            hv.z = prmt7632(hbits[4], hbits[5]);
            hv.w = prmt7632(hbits[6], hbits[7]);
            lv.x = prmt7632(lbits[0], lbits[1]);
            lv.y = prmt7632(lbits[2], lbits[3]);
            lv.z = prmt7632(lbits[4], lbits[5]);
            lv.w = prmt7632(lbits[6], lbits[7]);
            asm volatile("st.shared.v4.b32 [%0], {%1,%2,%3,%4};"
                         :: "r"(dh + (uint32_t)jj * 2), "r"(hv.x), "r"(hv.y), "r"(hv.z), "r"(hv.w));
            asm volatile("st.shared.v4.b32 [%0], {%1,%2,%3,%4};"
                         :: "r"(dl + (uint32_t)jj * 2), "r"(lv.x), "r"(lv.y), "r"(lv.z), "r"(lv.w));
        }
    };

    // prologue
    load_H(0, 0);
    CP_COMMIT();
    pgen(0, 0);
    CP_WAIT0();
    __syncthreads();

    for (int t = 0; t < T; t++) {
        int b = t & 1;
        if (t + 1 < T) { load_H(t + 1, b ^ 1); CP_COMMIT(); }

        // ---- MMA on buffer b ----
        uint32_t basePhi = P0 + (uint32_t)b * PBYTES;
        uint32_t basePlo = P0 + (uint32_t)(2 + b) * PBYTES;
        uint32_t baseHhi = H0 + (uint32_t)b * HBYTES;
        uint32_t baseHlo = H0 + (uint32_t)(2 + b) * HBYTES;
#pragma unroll
        for (int kk = 0; kk < 4; kk++) {
            uint32_t ah[MT][4], al[MT][4];
#pragma unroll
            for (int mi = 0; mi < MT; mi++) {
                uint32_t o = pA + (uint32_t)mi * (16 * ROWB) + (uint32_t)kk * 32;
                ldsm_x4(ah[mi], basePhi + o);
                ldsm_x4(al[mi], basePlo + o);
            }
#pragma unroll
            for (int np = 0; np < NT / 2; np++) {
                uint32_t bo = pB + (uint32_t)np * (16 * ROWB) + (uint32_t)kk * 32;
                uint32_t bh[4], bl[4];
                ldsm_x4(bh, baseHhi + bo);
                ldsm_x4(bl, baseHlo + bo);
#pragma unroll
                for (int mi = 0; mi < MT; mi++) {
                    mma16816(acc[mi][np * 2], ah[mi], bh[0], bh[1]);
                    mma16816(acc[mi][np * 2], ah[mi], bl[0], bl[1]);
                    mma16816(acc[mi][np * 2], al[mi], bh[0], bh[1]);
                    mma16816(acc[mi][np * 2 + 1], ah[mi], bh[2], bh[3]);
                    mma16816(acc[mi][np * 2 + 1], ah[mi], bl[2], bl[3]);
                    mma16816(acc[mi][np * 2 + 1], al[mi], bh[2], bh[3]);
                }
            }
        }

        if (t + 1 < T) pgen(t + 1, b ^ 1);
        CP_WAIT0();
        __syncthreads();
    }

    // row sums
    float tot = psum + __shfl_xor_sync(0xffffffffu, psum, 1);
    if (jhalf == 0) *(float*)(dsm + (poff - (uint32_t)jhalf * 64) / ROWB * 0 + 0 + 4 * irow) = tot;
    __syncthreads();

    // epilogue: normalize + store
    int g = lane >> 2, tg = lane & 3;
#pragma unroll
    for (int mi = 0; mi < MT; mi++) {
        int r0 = m0 + mi * 16 + g;
        int r1 = r0 + 8;
        float rinv0 = 1.f / *(const float*)(dsm + 4 * r0);
        float rinv1 = 1.f / *(const float*)(dsm + 4 * r1);
        float* o0 = Out + (size_t)(i0 + r0) * (HH * F) + h * F;
        float* o1 = Out + (size_t)(i0 + r1) * (HH * F) + h * F;
#pragma unroll
        for (int nt = 0; nt < NT; nt++) {
            int cn = n0 + nt * 8 + tg * 2;
            float2 v0 = make_float2(acc[mi][nt][0] * rinv0, acc[mi][nt][1] * rinv0);
            float2 v1 = make_float2(acc[mi][nt][2] * rinv1, acc[mi][nt][3] * rinv1);
            *(float2*)(o0 + cn) = v0;
            *(float2*)(o1 + cn) = v1;
        }
    }
}

// ---------------------------------------------------------------------------
// BatchNorm (population stats) + ELU. One block per column.
// ---------------------------------------------------------------------------
__global__ void bn_elu_kernel(const float* __restrict__ Y,
                              const float* __restrict__ gamma,
                              const float* __restrict__ beta,
                              float* __restrict__ Out, int C) {
    int c = blockIdx.x;
    float s1 = 0.f, s2 = 0.f;
    for (int i = threadIdx.x; i < NN; i += 256) {
        float v = Y[(size_t)i * C + c];
        s1 += v;
        s2 += v * v;
    }
    __shared__ float r1[256], r2[256];
    r1[threadIdx.x] = s1; r2[threadIdx.x] = s2;
    __syncthreads();
    for (int s = 128; s; s >>= 1) {
        if (threadIdx.x < s) {
            r1[threadIdx.x] += r1[threadIdx.x + s];
            r2[threadIdx.x] += r2[threadIdx.x + s];
        }
        __syncthreads();
    }
    float mean = r1[0] * (1.f / NN);
    float var = r2[0] * (1.f / NN) - mean * mean;
    float inv = rsqrtf(var + 1e-5f);
    float g = gamma[c], b = beta[c];
    for (int i = threadIdx.x; i < NN; i += 256) {
        float v = Y[(size_t)i * C + c];
        float z = (v - mean) * inv * g + b;
        Out[(size_t)i * C + c] = z > 0.f ? z : (__expf(z) - 1.f);
    }
}

// ---------------------------------------------------------------------------
extern "C" void kernel_launch(void* const* d_in, const int* in_sizes, int n_in,
                              void* d_out, int out_size) {
    const float* x   = (const float*)d_in[0];
    const int*   adj = (const int*)d_in[1];
    const float* W1  = (const float*)d_in[2];
    const float* a1s = (const float*)d_in[3];
    const float* a1d = (const float*)d_in[4];
    const float* lw1 = (const float*)d_in[5];
    const float* lb1 = (const float*)d_in[6];
    const float* g1  = (const float*)d_in[7];
    const float* be1 = (const float*)d_in[8];
    const float* W2  = (const float*)d_in[9];
    const float* a2s = (const float*)d_in[10];
    const float* a2d = (const float*)d_in[11];
    const float* lw2 = (const float*)d_in[12];
    const float* lb2 = (const float*)d_in[13];
    const float* g2  = (const float*)d_in[14];
    const float* be2 = (const float*)d_in[15];
    float* out = (float*)d_out;

    float *p_h1, *p_es1, *p_ed1, *p_mx1, *p_x1, *p_y1, *p_x2;
    float *p_h2, *p_es2, *p_ed2, *p_mx2, *p_x3, *p_y2;
    unsigned short *p_t1h, *p_t1l, *p_t2h, *p_t2l;
    cudaGetSymbolAddress((void**)&p_h1, g_h1);
    cudaGetSymbolAddress((void**)&p_es1, g_es1);
    cudaGetSymbolAddress((void**)&p_ed1, g_ed1);
    cudaGetSymbolAddress((void**)&p_mx1, g_maxed1);
    cudaGetSymbolAddress((void**)&p_x1, g_x1);
    cudaGetSymbolAddress((void**)&p_y1, g_y1);
    cudaGetSymbolAddress((void**)&p_x2, g_x2);
    cudaGetSymbolAddress((void**)&p_h2, g_h2);
    cudaGetSymbolAddress((void**)&p_es2, g_es2);
    cudaGetSymbolAddress((void**)&p_ed2, g_ed2);
    cudaGetSymbolAddress((void**)&p_mx2, g_maxed2);
    cudaGetSymbolAddress((void**)&p_x3, g_x3);
    cudaGetSymbolAddress((void**)&p_y2, g_y2);
    cudaGetSymbolAddress((void**)&p_t1h, g_ht1_hi);
    cudaGetSymbolAddress((void**)&p_t1l, g_ht1_lo);
    cudaGetSymbolAddress((void**)&p_t2h, g_ht2_hi);
    cudaGetSymbolAddress((void**)&p_t2l, g_ht2_lo);

    const int SMEM1 = 512 + 4 * (128 * 144) + 4 * (128 * 144);  // 147968
    const int SMEM2 = 512 + 4 * (128 * 144) + 4 * (32 * 144);   // 92672
    cudaFuncSetAttribute(gat_attn_mma<128>, cudaFuncAttributeMaxDynamicSharedMemorySize, SMEM1);
    cudaFuncSetAttribute(gat_attn_mma<32>,  cudaFuncAttributeMaxDynamicSharedMemorySize, SMEM2);

    // 1) adjacency bitmask
    pack_adj_kernel<<<NN * 128 / 8, 256>>>(adj);

    // 2) h1 = x @ W1   [4096,512]@[512,512]
    gemm_bias_kernel<64, 4, 4><<<dim3(64, 8), 256>>>(x, W1, nullptr, p_h1, NN, 512, 512);

    // 3) projections + shift + transposed split features
    attn_proj_kernel<<<NN, 128>>>(p_h1, a1s, a1d, p_es1, p_ed1, 128);
    maxed_kernel<<<HH, 256>>>(p_ed1, p_mx1);
    transpose_split_kernel<<<dim3(128, 16), dim3(32, 8)>>>(p_h1, p_t1h, p_t1l, 512);

    // 4) layer-1 attention (mma.sync) -> x1 [4096,512]
    gat_attn_mma<128><<<dim3(32, HH), 256, SMEM1>>>(p_t1h, p_t1l, p_es1, p_ed1, p_mx1, p_x1);

    // 5) y1 = x1 @ lw1 + lb1 ; x2 = BN_ELU(y1)
    gemm_bias_kernel<64, 4, 4><<<dim3(64, 1), 256>>>(p_x1, lw1, lb1, p_y1, NN, 512, 64);
    bn_elu_kernel<<<64, 256>>>(p_y1, g1, be1, p_x2, 64);

    // 6) h2 = x2 @ W2  [4096,64]@[64,128]
    gemm_bias_kernel<64, 4, 4><<<dim3(64, 2), 256>>>(p_x2, W2, nullptr, p_h2, NN, 64, 128);

    // 7) layer-2 attention
    attn_proj_kernel<<<NN, 128>>>(p_h2, a2s, a2d, p_es2, p_ed2, 32);
    maxed_kernel<<<HH, 256>>>(p_ed2, p_mx2);
    transpose_split_kernel<<<dim3(128, 4), dim3(32, 8)>>>(p_h2, p_t2h, p_t2l, 128);
    gat_attn_mma<32><<<dim3(32, HH), 256, SMEM2>>>(p_t2h, p_t2l, p_es2, p_ed2, p_mx2, p_x3);

    // 8) y2 = x3 @ lw2 + lb2 ; out = BN_ELU(y2)
    gemm_bias_kernel<16, 4, 1><<<dim3(64, 1), 256>>>(p_x3, lw2, lb2, p_y2, NN, 128, 16);
    bn_elu_kernel<<<16, 256>>>(p_y2, g2, be2, out, 16);
}

// round 6
// speedup vs baseline: 2.4651x; 1.1536x over previous
#include <cuda_runtime.h>
#include <cuda_bf16.h>
#include <cstdint>

#define NN 4096
#define HH 4
typedef unsigned short u16;

// ---------------------------------------------------------------------------
// scratch (static device allocations only)
// ---------------------------------------------------------------------------
__device__ unsigned g_adjbits[NN * 128];
__device__ float g_h1[NN * 512];
__device__ float g_es1[HH * NN], g_ed1[HH * NN], g_maxed1[HH];
__device__ float g_x1[NN * 512];
__device__ float g_y1[NN * 64];
__device__ float g_x2[NN * 64];
__device__ float g_h2[NN * 128];
__device__ float g_es2[HH * NN], g_ed2[HH * NN], g_maxed2[HH];
__device__ float g_x3[NN * 128];
__device__ float g_y2[NN * 16];
// transposed split-bf16 feature matrices: [HF][NN]
__device__ u16 g_ht1_hi[512 * NN], g_ht1_lo[512 * NN];
__device__ u16 g_ht2_hi[128 * NN], g_ht2_lo[128 * NN];
// split activations (row-major, K-contig for GEMM A side)
__device__ u16 g_xhi[NN * 512], g_xlo[NN * 512];
__device__ u16 g_x1hi[NN * 512], g_x1lo[NN * 512];
__device__ u16 g_x2hi[NN * 64], g_x2lo[NN * 64];
// split transposed weights [N][K]
__device__ u16 g_w1thi[512 * 512], g_w1tlo[512 * 512];
__device__ u16 g_lw1thi[64 * 512], g_lw1tlo[64 * 512];
__device__ u16 g_w2thi[128 * 64], g_w2tlo[128 * 64];

// ---------------------------------------------------------------------------
// helpers
// ---------------------------------------------------------------------------
__device__ __forceinline__ uint32_t smem_u32(const void* p) {
    uint32_t a;
    asm("{ .reg .u64 t; cvta.to.shared.u64 t, %1; cvt.u32.u64 %0, t; }"
        : "=r"(a) : "l"(p));
    return a;
}
__device__ __forceinline__ uint32_t prmt7632(uint32_t a, uint32_t b) {
    uint32_t r;
    asm("prmt.b32 %0, %1, %2, 0x7632;" : "=r"(r) : "r"(a), "r"(b));
    return r;
}

#define CP_ASYNC16(saddr, gptr) \
    asm volatile("cp.async.cg.shared.global [%0], [%1], 16;" \
                 :: "r"((uint32_t)(saddr)), "l"(gptr))
#define CP_COMMIT() asm volatile("cp.async.commit_group;" ::: "memory")
#define CP_WAIT0()  asm volatile("cp.async.wait_group 0;" ::: "memory")
#define CP_WAIT1()  asm volatile("cp.async.wait_group 1;" ::: "memory")

__device__ __forceinline__ void ldsm_x4(uint32_t* r, uint32_t addr) {
    asm volatile("ldmatrix.sync.aligned.m8n8.x4.shared.b16 {%0,%1,%2,%3}, [%4];"
                 : "=r"(r[0]), "=r"(r[1]), "=r"(r[2]), "=r"(r[3]) : "r"(addr));
}
__device__ __forceinline__ void mma16816(float* c, const uint32_t* a,
                                         uint32_t b0, uint32_t b1) {
    asm volatile(
        "mma.sync.aligned.m16n8k16.row.col.f32.bf16.bf16.f32 "
        "{%0,%1,%2,%3}, {%4,%5,%6,%7}, {%8,%9}, {%0,%1,%2,%3};"
        : "+f"(c[0]), "+f"(c[1]), "+f"(c[2]), "+f"(c[3])
        : "r"(a[0]), "r"(a[1]), "r"(a[2]), "r"(a[3]), "r"(b0), "r"(b1));
}

// pack two floats' bf16 truncations (hi) and residual truncations (lo)
__device__ __forceinline__ void pack_split(float a, float b,
                                           uint32_t& h, uint32_t& l) {
    uint32_t ab = __float_as_uint(a), bb = __float_as_uint(b);
    float la = a - __uint_as_float(ab & 0xffff0000u);
    float lb = b - __uint_as_float(bb & 0xffff0000u);
    h = prmt7632(ab, bb);
    l = prmt7632(__float_as_uint(la), __float_as_uint(lb));
}

// ---------------------------------------------------------------------------
// adj -> bitmask
// ---------------------------------------------------------------------------
__global__ void pack_adj_kernel(const int* __restrict__ adj) {
    int gw = blockIdx.x * 8 + (threadIdx.x >> 5);
    int lane = threadIdx.x & 31;
    int row = gw >> 7, word = gw & 127;
    int v = adj[(size_t)row * NN + word * 32 + lane];
    unsigned m = __ballot_sync(0xffffffffu, v > 0);
    if (lane == 0) g_adjbits[gw] = m;
}

// ---------------------------------------------------------------------------
// elementwise split: A[n] fp32 -> hi/lo bf16 (row-major preserved)
// ---------------------------------------------------------------------------
__global__ void split_kernel(const float* __restrict__ A,
                             u16* __restrict__ hi, u16* __restrict__ lo, int n4) {
    int i = blockIdx.x * 256 + threadIdx.x;
    if (i >= n4) return;
    float4 v = ((const float4*)A)[i];
    uint32_t h0, l0, h1, l1;
    pack_split(v.x, v.y, h0, l0);
    pack_split(v.z, v.w, h1, l1);
    ((uint2*)hi)[i] = make_uint2(h0, h1);
    ((uint2*)lo)[i] = make_uint2(l0, l1);
}

// ---------------------------------------------------------------------------
// transpose + split: A[R,C] fp32 -> hi/lo[C][R] bf16
// ---------------------------------------------------------------------------
__global__ void transpose_split_kernel(const float* __restrict__ A,
                                       u16* __restrict__ hi, u16* __restrict__ lo,
                                       int R, int C) {
    __shared__ float tile[32][33];
    int j0 = blockIdx.x * 32, c0 = blockIdx.y * 32;
    int tx = threadIdx.x, ty = threadIdx.y;
    for (int r = ty; r < 32; r += 8)
        tile[r][tx] = A[(size_t)(j0 + r) * C + c0 + tx];
    __syncthreads();
    for (int r = ty; r < 32; r += 8) {
        float v = tile[tx][r];                       // element (j0+tx, c0+r)
        uint32_t b = __float_as_uint(v);
        uint32_t hb = b & 0xffff0000u;
        float lv = v - __uint_as_float(hb);
        size_t o = (size_t)(c0 + r) * R + j0 + tx;
        hi[o] = (u16)(hb >> 16);
        lo[o] = (u16)(__float_as_uint(lv) >> 16);
    }
}

// ---------------------------------------------------------------------------
// Split-bf16 tensor GEMM: C[M,Nc] = A[M,K] @ BT[Nc,K]^T (+bias), 3-term split.
// BM=128, BK=64, 256 threads (8 warps = 4m x 2n).
// ---------------------------------------------------------------------------
template <int BN>
__global__ void __launch_bounds__(256, 1)
gemm_mma(const u16* __restrict__ Ahi, const u16* __restrict__ Alo,
         const u16* __restrict__ Bthi, const u16* __restrict__ Btlo,
         const float* __restrict__ bias, float* __restrict__ C,
         int M, int K, int Nc) {
    constexpr int BM = 128, BK = 64;
    constexpr uint32_t ROWB = 144;
    constexpr uint32_t ABYTES = BM * ROWB;
    constexpr uint32_t BBYTES = (uint32_t)BN * ROWB;
    constexpr uint32_t STAGE = 2 * ABYTES + 2 * BBYTES;
    constexpr int NT = BN / 16;      // n8-tiles per warp (warp covers BN/2 cols)

    extern __shared__ __align__(16) char dsm[];
    uint32_t sb = smem_u32(dsm);

    int tid = threadIdx.x, wid = tid >> 5, lane = tid & 31;
    int m0w = (wid >> 1) * 32;
    int n0w = (wid & 1) * (BN / 2);
    int row0 = blockIdx.x * BM;
    int c0 = blockIdx.y * BN;

    float acc[2][NT][4];
#pragma unroll
    for (int mi = 0; mi < 2; mi++)
#pragma unroll
        for (int nt = 0; nt < NT; nt++)
#pragma unroll
            for (int q = 0; q < 4; q++) acc[mi][nt][q] = 0.f;

    uint32_t pA = (uint32_t)(m0w + (lane & 15)) * ROWB + (uint32_t)((lane >> 4) << 4);
    uint32_t pB = (uint32_t)(((lane >> 4) << 3) + (lane & 7) + n0w) * ROWB +
                  (uint32_t)(((lane >> 3) & 1) << 4);

    const int KT = K / BK;

    auto load_tiles = [&](int kt, int s) {
        uint32_t base = sb + (uint32_t)s * STAGE;
        const char* gah = (const char*)(Ahi + (size_t)row0 * K + kt * BK);
        const char* gal = (const char*)(Alo + (size_t)row0 * K + kt * BK);
        const char* gbh = (const char*)(Bthi + (size_t)c0 * K + kt * BK);
        const char* gbl = (const char*)(Btlo + (size_t)c0 * K + kt * BK);
#pragma unroll
        for (int v = tid; v < BM * 8; v += 256) {
            int r = v >> 3;
            uint32_t c = (uint32_t)(v & 7) << 4;
            uint32_t so = (uint32_t)r * ROWB + c;
            size_t go = (size_t)r * K * 2 + c;
            CP_ASYNC16(base + so, gah + go);
            CP_ASYNC16(base + ABYTES + so, gal + go);
        }
#pragma unroll
        for (int v = tid; v < BN * 8; v += 256) {
            int r = v >> 3;
            uint32_t c = (uint32_t)(v & 7) << 4;
            uint32_t so = (uint32_t)r * ROWB + c;
            size_t go = (size_t)r * K * 2 + c;
            CP_ASYNC16(base + 2 * ABYTES + so, gbh + go);
            CP_ASYNC16(base + 2 * ABYTES + BBYTES + so, gbl + go);
        }
    };

    load_tiles(0, 0);
    CP_COMMIT();
    if (KT > 1) { load_tiles(1, 1); CP_COMMIT(); }

    for (int kt = 0; kt < KT; kt++) {
        int s = kt & 1;
        if (kt + 1 < KT) { CP_WAIT1(); } else { CP_WAIT0(); }
        __syncthreads();

        uint32_t bAhi = sb + (uint32_t)s * STAGE;
        uint32_t bAlo = bAhi + ABYTES;
        uint32_t bBhi = bAlo + ABYTES;
        uint32_t bBlo = bBhi + BBYTES;
#pragma unroll
        for (int kk = 0; kk < 4; kk++) {
            uint32_t ah[2][4], al[2][4];
#pragma unroll
            for (int mi = 0; mi < 2; mi++) {
                uint32_t o = pA + (uint32_t)mi * (16 * ROWB) + (uint32_t)kk * 32;
                ldsm_x4(ah[mi], bAhi + o);
                ldsm_x4(al[mi], bAlo + o);
            }
#pragma unroll
            for (int np = 0; np < NT / 2; np++) {
                uint32_t bo = pB + (uint32_t)np * (16 * ROWB) + (uint32_t)kk * 32;
                uint32_t bh[4], bl[4];
                ldsm_x4(bh, bBhi + bo);
                ldsm_x4(bl, bBlo + bo);
#pragma unroll
                for (int mi = 0; mi < 2; mi++) {
                    mma16816(acc[mi][np * 2], ah[mi], bh[0], bh[1]);
                    mma16816(acc[mi][np * 2], ah[mi], bl[0], bl[1]);
                    mma16816(acc[mi][np * 2], al[mi], bh[0], bh[1]);
                    mma16816(acc[mi][np * 2 + 1], ah[mi], bh[2], bh[3]);
                    mma16816(acc[mi][np * 2 + 1], ah[mi], bl[2], bl[3]);
                    mma16816(acc[mi][np * 2 + 1], al[mi], bh[2], bh[3]);
                }
            }
        }
        __syncthreads();
        if (kt + 2 < KT) { load_tiles(kt + 2, s); CP_COMMIT(); }
    }

    // epilogue
    int g = lane >> 2, tg = lane & 3;
#pragma unroll
    for (int mi = 0; mi < 2; mi++) {
        int r0 = row0 + m0w + mi * 16 + g;
        int r1 = r0 + 8;
#pragma unroll
        for (int nt = 0; nt < NT; nt++) {
            int cn = c0 + n0w + nt * 8 + tg * 2;
            float b0 = bias ? bias[cn] : 0.f;
            float b1 = bias ? bias[cn + 1] : 0.f;
            *(float2*)(&C[(size_t)r0 * Nc + cn]) =
                make_float2(acc[mi][nt][0] + b0, acc[mi][nt][1] + b1);
            *(float2*)(&C[(size_t)r1 * Nc + cn]) =
                make_float2(acc[mi][nt][2] + b0, acc[mi][nt][3] + b1);
        }
    }
}

// ---------------------------------------------------------------------------
// fp32 fallback GEMM for the tiny final layer
// ---------------------------------------------------------------------------
template <int BN, int TM, int TN>
__global__ void gemm_bias_kernel(const float* __restrict__ A,
                                 const float* __restrict__ B,
                                 const float* __restrict__ bias,
                                 float* __restrict__ C,
                                 int M, int K, int Nc) {
    const int BM = 64, BK = 32;
    __shared__ float sA[BK][BM + 4];
    __shared__ float sB[BK][BN + 4];
    int tid = threadIdx.x;
    const int CT = BN / TN;
    int tx = tid % CT, ty = tid / CT;
    int row0 = blockIdx.x * BM, c0 = blockIdx.y * BN;

    float acc[TM][TN];
#pragma unroll
    for (int i = 0; i < TM; i++)
#pragma unroll
        for (int j = 0; j < TN; j++) acc[i][j] = 0.f;

    for (int k0 = 0; k0 < K; k0 += BK) {
        __syncthreads();
        for (int v = tid; v < BM * BK / 4; v += 256) {
            int idx = v * 4;
            int r = idx >> 5, kk = idx & 31;
            float4 f = *reinterpret_cast<const float4*>(&A[(size_t)(row0 + r) * K + k0 + kk]);
            sA[kk + 0][r] = f.x; sA[kk + 1][r] = f.y;
            sA[kk + 2][r] = f.z; sA[kk + 3][r] = f.w;
        }
        for (int v = tid; v < BK * BN / 4; v += 256) {
            int idx = v * 4;
            int kk = idx / BN, c = idx % BN;
            float4 f = *reinterpret_cast<const float4*>(&B[(size_t)(k0 + kk) * Nc + c0 + c]);
            *reinterpret_cast<float4*>(&sB[kk][c]) = f;
        }
        __syncthreads();
#pragma unroll
        for (int kk = 0; kk < BK; kk++) {
            float a[TM], b[TN];
#pragma unroll
            for (int i = 0; i < TM; i++) a[i] = sA[kk][ty * TM + i];
#pragma unroll
            for (int j = 0; j < TN; j++) b[j] = sB[kk][tx * TN + j];
#pragma unroll
            for (int i = 0; i < TM; i++)
#pragma unroll
                for (int j = 0; j < TN; j++) acc[i][j] = fmaf(a[i], b[j], acc[i][j]);
        }
    }
#pragma unroll
    for (int j = 0; j < TN; j++) {
        int c = c0 + tx * TN + j;
        float bv = bias ? bias[c] : 0.f;
#pragma unroll
        for (int i = 0; i < TM; i++)
            C[(size_t)(row0 + ty * TM + i) * Nc + c] = acc[i][j] + bv;
    }
}

// ---------------------------------------------------------------------------
// es/ed projections
// ---------------------------------------------------------------------------
__global__ void attn_proj_kernel(const float* __restrict__ Hm,
                                 const float* __restrict__ as_,
                                 const float* __restrict__ ad_,
                                 float* __restrict__ es, float* __restrict__ ed,
                                 int F) {
    int i = blockIdx.x;
    int w = threadIdx.x >> 5, l = threadIdx.x & 31;
    const float* hp = Hm + (size_t)i * (HH * F) + w * F;
    const float* sp = as_ + w * F;
    const float* dp = ad_ + w * F;
    float s = 0.f, d = 0.f;
    for (int f = l; f < F; f += 32) {
        float v = hp[f];
        s += v * sp[f];
        d += v * dp[f];
    }
#pragma unroll
    for (int o = 16; o; o >>= 1) {
        s += __shfl_down_sync(0xffffffffu, s, o);
        d += __shfl_down_sync(0xffffffffu, d, o);
    }
    if (l == 0) { es[w * NN + i] = s; ed[w * NN + i] = d; }
}

__global__ void maxed_kernel(const float* __restrict__ ed, float* __restrict__ mx) {
    int h = blockIdx.x;
    int tid = threadIdx.x;
    float m = -1e30f;
    for (int i = tid; i < NN; i += 1024) m = fmaxf(m, ed[h * NN + i]);
#pragma unroll
    for (int o = 16; o; o >>= 1) m = fmaxf(m, __shfl_xor_sync(0xffffffffu, m, o));
    __shared__ float sm_[32];
    if ((tid & 31) == 0) sm_[tid >> 5] = m;
    __syncthreads();
    if (tid < 32) {
        float v = sm_[tid];
#pragma unroll
        for (int o = 16; o; o >>= 1) v = fmaxf(v, __shfl_xor_sync(0xffffffffu, v, o));
        if (tid == 0) mx[h] = v;
    }
}

// ---------------------------------------------------------------------------
// Fused GAT attention via mma.sync bf16 (3-term split), optional split output.
// ---------------------------------------------------------------------------
template <int F>
__global__ void __launch_bounds__(256, 1)
gat_attn_mma(const u16* __restrict__ Bhi, const u16* __restrict__ Blo,
             const float* __restrict__ es, const float* __restrict__ ed,
             const float* __restrict__ maxed, float* __restrict__ Out,
             u16* __restrict__ OutHi, u16* __restrict__ OutLo) {
    constexpr int KT = 64;
    constexpr int T = NN / KT;
    constexpr int WC = (F == 128) ? 2 : 1;
    constexpr int MT = WC;
    constexpr int NT = F / (8 * WC);
    constexpr uint32_t ROWB = 144;
    constexpr uint32_t PBYTES = 128 * ROWB;
    constexpr uint32_t HBYTES = (uint32_t)F * ROWB;

    extern __shared__ __align__(16) char dsm[];
    uint32_t sb = smem_u32(dsm);
    const uint32_t P0 = sb + 512;
    const uint32_t H0 = P0 + 4 * PBYTES;

    int tid = threadIdx.x;
    int wid = tid >> 5, lane = tid & 31;
    int h = blockIdx.y;
    int i0 = blockIdx.x * 128;

    int wr = wid / WC, wc = wid % WC;
    int m0 = wr * (16 * MT);
    int n0 = wc * (NT * 8);

    uint32_t pA = (uint32_t)(m0 + (lane & 15)) * ROWB + ((lane >> 4) << 4);
    uint32_t pB = (uint32_t)(((lane >> 4) << 3) + (lane & 7)) * ROWB +
                  (((lane >> 3) & 1) << 4) + (uint32_t)n0 * ROWB;

    int irow = tid >> 1;
    int jhalf = tid & 1;
    float esr = es[h * NN + i0 + irow];
    float zz = esr + maxed[h];
    float mr = fmaxf(zz, 0.2f * zz);
    const float* edh = ed + h * NN;
    float psum = 0.f;
    uint32_t poff = (uint32_t)irow * ROWB + (uint32_t)jhalf * 64;

    float acc[MT][NT][4];
#pragma unroll
    for (int mi = 0; mi < MT; mi++)
#pragma unroll
        for (int nt = 0; nt < NT; nt++)
#pragma unroll
            for (int q = 0; q < 4; q++) acc[mi][nt][q] = 0.f;

    auto load_H = [&](int t, int b) {
        const char* gh = (const char*)Bhi + ((size_t)h * F * NN + (size_t)t * KT) * 2;
        const char* gl = (const char*)Blo + ((size_t)h * F * NN + (size_t)t * KT) * 2;
        uint32_t dh = H0 + (uint32_t)b * HBYTES;
        uint32_t dl = H0 + (uint32_t)(2 + b) * HBYTES;
#pragma unroll
        for (int v = tid; v < F * 8; v += 256) {
            int f = v >> 3;
            uint32_t c = (uint32_t)(v & 7) << 4;
            uint32_t so = (uint32_t)f * ROWB + c;
            CP_ASYNC16(dh + so, gh + (size_t)f * NN * 2 + c);
            CP_ASYNC16(dl + so, gl + (size_t)f * NN * 2 + c);
        }
    };

    auto pgen = [&](int t, int b) {
        uint32_t dh = P0 + (uint32_t)b * PBYTES + poff;
        uint32_t dl = P0 + (uint32_t)(2 + b) * PBYTES + poff;
        unsigned word = g_adjbits[(size_t)(i0 + irow) * 128 + t * 2 + jhalf];
        const float* edp = edh + t * KT + jhalf * 32;
#pragma unroll
        for (int jj = 0; jj < 32; jj += 8) {
            float4 e0 = __ldg((const float4*)(edp + jj));
            float4 e1 = __ldg((const float4*)(edp + jj + 4));
            float ee[8] = {e0.x, e0.y, e0.z, e0.w, e1.x, e1.y, e1.z, e1.w};
            uint32_t hbits[8], lbits[8];
#pragma unroll
            for (int u = 0; u < 8; u++) {
                float e = esr + ee[u];
                float lr = fmaxf(e, 0.2f * e);
                float p = __expf(lr - mr);
                p = ((word >> (jj + u)) & 1u) ? p : 0.f;
                psum += p;
                uint32_t pb = __float_as_uint(p);
                uint32_t hb = pb & 0xffff0000u;
                hbits[u] = hb;
                lbits[u] = __float_as_uint(p - __uint_as_float(hb));
            }
            uint4 hv, lv;
            hv.x = prmt7632(hbits[0], hbits[1]);
            hv.y = prmt7632(hbits[2], hbits[3]);
            hv.z = prmt7632(hbits[4], hbits[5]);
            hv.w = prmt7632(hbits[6], hbits[7]);
            lv.x = prmt7632(lbits[0], lbits[1]);
            lv.y = prmt7632(lbits[2], lbits[3]);
            lv.z = prmt7632(lbits[4], lbits[5]);
            lv.w = prmt7632(lbits[6], lbits[7]);
            asm volatile("st.shared.v4.b32 [%0], {%1,%2,%3,%4};"
                         :: "r"(dh + (uint32_t)jj * 2), "r"(hv.x), "r"(hv.y), "r"(hv.z), "r"(hv.w));
            asm volatile("st.shared.v4.b32 [%0], {%1,%2,%3,%4};"
                         :: "r"(dl + (uint32_t)jj * 2), "r"(lv.x), "r"(lv.y), "r"(lv.z), "r"(lv.w));
        }
    };

    load_H(0, 0);
    CP_COMMIT();
    pgen(0, 0);
    CP_WAIT0();
    __syncthreads();

    for (int t = 0; t < T; t++) {
        int b = t & 1;
        if (t + 1 < T) { load_H(t + 1, b ^ 1); CP_COMMIT(); }

        uint32_t basePhi = P0 + (uint32_t)b * PBYTES;
        uint32_t basePlo = P0 + (uint32_t)(2 + b) * PBYTES;
        uint32_t baseHhi = H0 + (uint32_t)b * HBYTES;
        uint32_t baseHlo = H0 + (uint32_t)(2 + b) * HBYTES;
#pragma unroll
        for (int kk = 0; kk < 4; kk++) {
            uint32_t ah[MT][4], al[MT][4];
#pragma unroll
            for (int mi = 0; mi < MT; mi++) {
                uint32_t o = pA + (uint32_t)mi * (16 * ROWB) + (uint32_t)kk * 32;
                ldsm_x4(ah[mi], basePhi + o);
                ldsm_x4(al[mi], basePlo + o);
            }
#pragma unroll
            for (int np = 0; np < NT / 2; np++) {
                uint32_t bo = pB + (uint32_t)np * (16 * ROWB) + (uint32_t)kk * 32;
                uint32_t bh[4], bl[4];
                ldsm_x4(bh, baseHhi + bo);
                ldsm_x4(bl, baseHlo + bo);
#pragma unroll
                for (int mi = 0; mi < MT; mi++) {
                    mma16816(acc[mi][np * 2], ah[mi], bh[0], bh[1]);
                    mma16816(acc[mi][np * 2], ah[mi], bl[0], bl[1]);
                    mma16816(acc[mi][np * 2], al[mi], bh[0], bh[1]);
                    mma16816(acc[mi][np * 2 + 1], ah[mi], bh[2], bh[3]);
                    mma16816(acc[mi][np * 2 + 1], ah[mi], bl[2], bl[3]);
                    mma16816(acc[mi][np * 2 + 1], al[mi], bh[2], bh[3]);
                }
            }
        }

        if (t + 1 < T) pgen(t + 1, b ^ 1);
        CP_WAIT0();
        __syncthreads();
    }

    // row sums
    float tot = psum + __shfl_xor_sync(0xffffffffu, psum, 1);
    if (jhalf == 0) *(float*)(dsm + 4 * irow) = tot;
    __syncthreads();

    // epilogue: normalize + store (+ optional split)
    int g = lane >> 2, tg = lane & 3;
#pragma unroll
    for (int mi = 0; mi < MT; mi++) {
        int r0 = m0 + mi * 16 + g;
        int r1 = r0 + 8;
        float rinv0 = 1.f / *(const float*)(dsm + 4 * r0);
        float rinv1 = 1.f / *(const float*)(dsm + 4 * r1);
        size_t o0 = (size_t)(i0 + r0) * (HH * F) + h * F;
        size_t o1 = (size_t)(i0 + r1) * (HH * F) + h * F;
#pragma unroll
        for (int nt = 0; nt < NT; nt++) {
            int cn = n0 + nt * 8 + tg * 2;
            float2 v0 = make_float2(acc[mi][nt][0] * rinv0, acc[mi][nt][1] * rinv0);
            float2 v1 = make_float2(acc[mi][nt][2] * rinv1, acc[mi][nt][3] * rinv1);
            *(float2*)(Out + o0 + cn) = v0;
            *(float2*)(Out + o1 + cn) = v1;
            if (OutHi) {
                uint32_t hh, ll;
                pack_split(v0.x, v0.y, hh, ll);
                *(uint32_t*)(OutHi + o0 + cn) = hh;
                *(uint32_t*)(OutLo + o0 + cn) = ll;
                pack_split(v1.x, v1.y, hh, ll);
                *(uint32_t*)(OutHi + o1 + cn) = hh;
                *(uint32_t*)(OutLo + o1 + cn) = ll;
            }
        }
    }
}

// ---------------------------------------------------------------------------
// BatchNorm + ELU (optional split output)
// ---------------------------------------------------------------------------
__global__ void bn_elu_kernel(const float* __restrict__ Y,
                              const float* __restrict__ gamma,
                              const float* __restrict__ beta,
                              float* __restrict__ Out,
                              u16* __restrict__ OutHi, u16* __restrict__ OutLo,
                              int C) {
    int c = blockIdx.x;
    float s1 = 0.f, s2 = 0.f;
    for (int i = threadIdx.x; i < NN; i += 256) {
        float v = Y[(size_t)i * C + c];
        s1 += v;
        s2 += v * v;
    }
    __shared__ float r1[256], r2[256];
    r1[threadIdx.x] = s1; r2[threadIdx.x] = s2;
    __syncthreads();
    for (int s = 128; s; s >>= 1) {
        if (threadIdx.x < s) {
            r1[threadIdx.x] += r1[threadIdx.x + s];
            r2[threadIdx.x] += r2[threadIdx.x + s];
        }
        __syncthreads();
    }
    float mean = r1[0] * (1.f / NN);
    float var = r2[0] * (1.f / NN) - mean * mean;
    float inv = rsqrtf(var + 1e-5f);
    float g = gamma[c], b = beta[c];
    for (int i = threadIdx.x; i < NN; i += 256) {
        float v = Y[(size_t)i * C + c];
        float z = (v - mean) * inv * g + b;
        float o = z > 0.f ? z : (__expf(z) - 1.f);
        Out[(size_t)i * C + c] = o;
        if (OutHi) {
            uint32_t ob = __float_as_uint(o);
            uint32_t hb = ob & 0xffff0000u;
            float lv = o - __uint_as_float(hb);
            OutHi[(size_t)i * C + c] = (u16)(hb >> 16);
            OutLo[(size_t)i * C + c] = (u16)(__float_as_uint(lv) >> 16);
        }
    }
}

// ---------------------------------------------------------------------------
extern "C" void kernel_launch(void* const* d_in, const int* in_sizes, int n_in,
                              void* d_out, int out_size) {
    const float* x   = (const float*)d_in[0];
    const int*   adj = (const int*)d_in[1];
    const float* W1  = (const float*)d_in[2];
    const float* a1s = (const float*)d_in[3];
    const float* a1d = (const float*)d_in[4];
    const float* lw1 = (const float*)d_in[5];
    const float* lb1 = (const float*)d_in[6];
    const float* g1  = (const float*)d_in[7];
    const float* be1 = (const float*)d_in[8];
    const float* W2  = (const float*)d_in[9];
    const float* a2s = (const float*)d_in[10];
    const float* a2d = (const float*)d_in[11];
    const float* lw2 = (const float*)d_in[12];
    const float* lb2 = (const float*)d_in[13];
    const float* g2  = (const float*)d_in[14];
    const float* be2 = (const float*)d_in[15];
    float* out = (float*)d_out;

    float *p_h1, *p_es1, *p_ed1, *p_mx1, *p_x1, *p_y1, *p_x2;
    float *p_h2, *p_es2, *p_ed2, *p_mx2, *p_x3, *p_y2;
    u16 *p_t1h, *p_t1l, *p_t2h, *p_t2l;
    u16 *p_xhi, *p_xlo, *p_x1hi, *p_x1lo, *p_x2hi, *p_x2lo;
    u16 *p_w1th, *p_w1tl, *p_lw1th, *p_lw1tl, *p_w2th, *p_w2tl;
    cudaGetSymbolAddress((void**)&p_h1, g_h1);
    cudaGetSymbolAddress((void**)&p_es1, g_es1);
    cudaGetSymbolAddress((void**)&p_ed1, g_ed1);
    cudaGetSymbolAddress((void**)&p_mx1, g_maxed1);
    cudaGetSymbolAddress((void**)&p_x1, g_x1);
    cudaGetSymbolAddress((void**)&p_y1, g_y1);
    cudaGetSymbolAddress((void**)&p_x2, g_x2);
    cudaGetSymbolAddress((void**)&p_h2, g_h2);
    cudaGetSymbolAddress((void**)&p_es2, g_es2);
    cudaGetSymbolAddress((void**)&p_ed2, g_ed2);
    cudaGetSymbolAddress((void**)&p_mx2, g_maxed2);
    cudaGetSymbolAddress((void**)&p_x3, g_x3);
    cudaGetSymbolAddress((void**)&p_y2, g_y2);
    cudaGetSymbolAddress((void**)&p_t1h, g_ht1_hi);
    cudaGetSymbolAddress((void**)&p_t1l, g_ht1_lo);
    cudaGetSymbolAddress((void**)&p_t2h, g_ht2_hi);
    cudaGetSymbolAddress((void**)&p_t2l, g_ht2_lo);
    cudaGetSymbolAddress((void**)&p_xhi, g_xhi);
    cudaGetSymbolAddress((void**)&p_xlo, g_xlo);
    cudaGetSymbolAddress((void**)&p_x1hi, g_x1hi);
    cudaGetSymbolAddress((void**)&p_x1lo, g_x1lo);
    cudaGetSymbolAddress((void**)&p_x2hi, g_x2hi);
    cudaGetSymbolAddress((void**)&p_x2lo, g_x2lo);
    cudaGetSymbolAddress((void**)&p_w1th, g_w1thi);
    cudaGetSymbolAddress((void**)&p_w1tl, g_w1tlo);
    cudaGetSymbolAddress((void**)&p_lw1th, g_lw1thi);
    cudaGetSymbolAddress((void**)&p_lw1tl, g_lw1tlo);
    cudaGetSymbolAddress((void**)&p_w2th, g_w2thi);
    cudaGetSymbolAddress((void**)&p_w2tl, g_w2tlo);

    const int SMEM1 = 512 + 4 * (128 * 144) + 4 * (128 * 144);  // attn F=128
    const int SMEM2 = 512 + 4 * (128 * 144) + 4 * (32 * 144);   // attn F=32
    const int SMEMG128 = 2 * (2 * 128 * 144 + 2 * 128 * 144);   // gemm BN=128
    const int SMEMG64  = 2 * (2 * 128 * 144 + 2 * 64 * 144);    // gemm BN=64
    cudaFuncSetAttribute(gat_attn_mma<128>, cudaFuncAttributeMaxDynamicSharedMemorySize, SMEM1);
    cudaFuncSetAttribute(gat_attn_mma<32>,  cudaFuncAttributeMaxDynamicSharedMemorySize, SMEM2);
    cudaFuncSetAttribute(gemm_mma<128>, cudaFuncAttributeMaxDynamicSharedMemorySize, SMEMG128);
    cudaFuncSetAttribute(gemm_mma<64>,  cudaFuncAttributeMaxDynamicSharedMemorySize, SMEMG64);

    // prep: bitmask, input split, weight transposes
    pack_adj_kernel<<<NN * 128 / 8, 256>>>(adj);
    split_kernel<<<(NN * 512 / 4 + 255) / 256, 256>>>(x, p_xhi, p_xlo, NN * 512 / 4);
    transpose_split_kernel<<<dim3(16, 16), dim3(32, 8)>>>(W1, p_w1th, p_w1tl, 512, 512);
    transpose_split_kernel<<<dim3(16, 2), dim3(32, 8)>>>(lw1, p_lw1th, p_lw1tl, 512, 64);
    transpose_split_kernel<<<dim3(2, 4), dim3(32, 8)>>>(W2, p_w2th, p_w2tl, 64, 128);

    // h1 = x @ W1   (tensor)
    gemm_mma<128><<<dim3(32, 4), 256, SMEMG128>>>(p_xhi, p_xlo, p_w1th, p_w1tl,
                                                  nullptr, p_h1, NN, 512, 512);

    // projections + shift + transposed split features
    attn_proj_kernel<<<NN, 128>>>(p_h1, a1s, a1d, p_es1, p_ed1, 128);
    maxed_kernel<<<HH, 1024>>>(p_ed1, p_mx1);
    transpose_split_kernel<<<dim3(128, 16), dim3(32, 8)>>>(p_h1, p_t1h, p_t1l, NN, 512);

    // layer-1 attention -> x1 (+ split)
    gat_attn_mma<128><<<dim3(32, HH), 256, SMEM1>>>(p_t1h, p_t1l, p_es1, p_ed1,
                                                    p_mx1, p_x1, p_x1hi, p_x1lo);

    // y1 = x1 @ lw1 + lb1 (tensor); x2 = BN_ELU(y1) (+ split)
    gemm_mma<64><<<dim3(32, 1), 256, SMEMG64>>>(p_x1hi, p_x1lo, p_lw1th, p_lw1tl,
                                                lb1, p_y1, NN, 512, 64);
    bn_elu_kernel<<<64, 256>>>(p_y1, g1, be1, p_x2, p_x2hi, p_x2lo, 64);

    // h2 = x2 @ W2 (tensor)
    gemm_mma<128><<<dim3(32, 1), 256, SMEMG128>>>(p_x2hi, p_x2lo, p_w2th, p_w2tl,
                                                  nullptr, p_h2, NN, 64, 128);

    // layer-2 attention
    attn_proj_kernel<<<NN, 128>>>(p_h2, a2s, a2d, p_es2, p_ed2, 32);
    maxed_kernel<<<HH, 1024>>>(p_ed2, p_mx2);
    transpose_split_kernel<<<dim3(128, 4), dim3(32, 8)>>>(p_h2, p_t2h, p_t2l, NN, 128);
    gat_attn_mma<32><<<dim3(32, HH), 256, SMEM2>>>(p_t2h, p_t2l, p_es2, p_ed2,
                                                   p_mx2, p_x3, nullptr, nullptr);

    // final tiny layer (fp32)
    gemm_bias_kernel<16, 4, 1><<<dim3(64, 1), 256>>>(p_x3, lw2, lb2, p_y2, NN, 128, 16);
    bn_elu_kernel<<<16, 256>>>(p_y2, g2, be2, out, nullptr, nullptr, 16);
}

// round 8
// speedup vs baseline: 2.5399x; 1.0303x over previous
#include <cuda_runtime.h>
#include <cuda_bf16.h>
#include <cstdint>

#define NN 4096
#define HH 4
typedef unsigned short u16;

// ---------------------------------------------------------------------------
// scratch (static device allocations only)
// ---------------------------------------------------------------------------
__device__ unsigned g_adjbits[NN * 128];
__device__ float g_es1[HH * NN], g_ed1[HH * NN];
__device__ float g_es2[HH * NN], g_ed2[HH * NN];
__device__ unsigned g_mx1e[HH], g_mx2e[HH];
__device__ float g_y1[NN * 64];
__device__ float g_x3[NN * 128];
__device__ float g_y2[NN * 16];
// transposed split-bf16 feature matrices: [HF][NN]
__device__ u16 g_ht1_hi[512 * NN], g_ht1_lo[512 * NN];
__device__ u16 g_ht2_hi[128 * NN], g_ht2_lo[128 * NN];
// split activations (row-major, K-contig for GEMM A side)
__device__ u16 g_xhi[NN * 512], g_xlo[NN * 512];
__device__ u16 g_x1hi[NN * 512], g_x1lo[NN * 512];
__device__ u16 g_x2hi[NN * 64], g_x2lo[NN * 64];
// split transposed weights [N][K]
__device__ u16 g_w1thi[512 * 512], g_w1tlo[512 * 512];
__device__ u16 g_lw1thi[64 * 512], g_lw1tlo[64 * 512];
__device__ u16 g_w2thi[128 * 64], g_w2tlo[128 * 64];

// ---------------------------------------------------------------------------
// helpers
// ---------------------------------------------------------------------------
__device__ __forceinline__ uint32_t smem_u32(const void* p) {
    uint32_t a;
    asm("{ .reg .u64 t; cvta.to.shared.u64 t, %1; cvt.u32.u64 %0, t; }"
        : "=r"(a) : "l"(p));
    return a;
}
__device__ __forceinline__ uint32_t prmt7632(uint32_t a, uint32_t b) {
    uint32_t r;
    asm("prmt.b32 %0, %1, %2, 0x7632;" : "=r"(r) : "r"(a), "r"(b));
    return r;
}
// order-preserving float->uint encoding for atomicMax
__device__ __forceinline__ unsigned enc_f(float f) {
    unsigned b = __float_as_uint(f);
    return (b & 0x80000000u) ? ~b : (b | 0x80000000u);
}
__device__ __forceinline__ float dec_f(unsigned k) {
    unsigned b = (k & 0x80000000u) ? (k & 0x7fffffffu) : ~k;
    return __uint_as_float(b);
}
__device__ __forceinline__ void split1(float v, u16& h, u16& l) {
    uint32_t b = __float_as_uint(v);
    uint32_t hb = b & 0xffff0000u;
    h = (u16)(hb >> 16);
    l = (u16)(__float_as_uint(v - __uint_as_float(hb)) >> 16);
}

#define CP_ASYNC16(saddr, gptr) \
    asm volatile("cp.async.cg.shared.global [%0], [%1], 16;" \
                 :: "r"((uint32_t)(saddr)), "l"(gptr))
#define CP_COMMIT() asm volatile("cp.async.commit_group;" ::: "memory")
#define CP_WAIT0()  asm volatile("cp.async.wait_group 0;" ::: "memory")
#define CP_WAIT1()  asm volatile("cp.async.wait_group 1;" ::: "memory")

__device__ __forceinline__ void ldsm_x4(uint32_t* r, uint32_t addr) {
    asm volatile("ldmatrix.sync.aligned.m8n8.x4.shared.b16 {%0,%1,%2,%3}, [%4];"
                 : "=r"(r[0]), "=r"(r[1]), "=r"(r[2]), "=r"(r[3]) : "r"(addr));
}
__device__ __forceinline__ void mma16816(float* c, const uint32_t* a,
                                         uint32_t b0, uint32_t b1) {
    asm volatile(
        "mma.sync.aligned.m16n8k16.row.col.f32.bf16.bf16.f32 "
        "{%0,%1,%2,%3}, {%4,%5,%6,%7}, {%8,%9}, {%0,%1,%2,%3};"
        : "+f"(c[0]), "+f"(c[1]), "+f"(c[2]), "+f"(c[3])
        : "r"(a[0]), "r"(a[1]), "r"(a[2]), "r"(a[3]), "r"(b0), "r"(b1));
}
__device__ __forceinline__ void pack_split(float a, float b,
                                           uint32_t& h, uint32_t& l) {
    uint32_t ab = __float_as_uint(a), bb = __float_as_uint(b);
    float la = a - __uint_as_float(ab & 0xffff0000u);
    float lb = b - __uint_as_float(bb & 0xffff0000u);
    h = prmt7632(ab, bb);
    l = prmt7632(__float_as_uint(la), __float_as_uint(lb));
}

// ---------------------------------------------------------------------------
// launch 1: adj -> bitmask; also init the max-encoders
// ---------------------------------------------------------------------------
__global__ void pack_adj_kernel(const int* __restrict__ adj) {
    if (blockIdx.x == 0 && threadIdx.x < 2 * HH) {
        if (threadIdx.x < HH) g_mx1e[threadIdx.x] = 0u;
        else                  g_mx2e[threadIdx.x - HH] = 0u;
    }
    int gw = blockIdx.x * 8 + (threadIdx.x >> 5);
    int lane = threadIdx.x & 31;
    int row = gw >> 7, word = gw & 127;
    int v = adj[(size_t)row * NN + word * 32 + lane];
    unsigned m = __ballot_sync(0xffffffffu, v > 0);
    if (lane == 0) g_adjbits[gw] = m;
}

// ---------------------------------------------------------------------------
// launch 2: fused prep — split x, transpose-split W1 / lw1 / W2
// ---------------------------------------------------------------------------
__device__ void tsp_tile(const float* __restrict__ A, u16* __restrict__ hi,
                         u16* __restrict__ lo, int R, int C, int bx, int by,
                         int tx, int ty) {
    __shared__ float tile[32][33];
    int j0 = bx * 32, c0 = by * 32;
    for (int r = ty; r < 32; r += 8)
        tile[r][tx] = A[(size_t)(j0 + r) * C + c0 + tx];
    __syncthreads();
    for (int r = ty; r < 32; r += 8) {
        float v = tile[tx][r];
        uint32_t b = __float_as_uint(v);
        uint32_t hb = b & 0xffff0000u;
        float lv = v - __uint_as_float(hb);
        size_t o = (size_t)(c0 + r) * R + j0 + tx;
        hi[o] = (u16)(hb >> 16);
        lo[o] = (u16)(__float_as_uint(lv) >> 16);
    }
}

__global__ void prep_kernel(const float* __restrict__ x,
                            const float* __restrict__ W1,
                            const float* __restrict__ lw1,
                            const float* __restrict__ W2) {
    int b = blockIdx.x;
    int tx = threadIdx.x, ty = threadIdx.y;
    int flat = ty * 32 + tx;
    if (b < 2048) {
        // split x: 524288 float4
        int i = b * 256 + flat;
        float4 v = ((const float4*)x)[i];
        uint32_t h0, l0, h1, l1;
        pack_split(v.x, v.y, h0, l0);
        pack_split(v.z, v.w, h1, l1);
        ((uint2*)g_xhi)[i] = make_uint2(h0, h1);
        ((uint2*)g_xlo)[i] = make_uint2(l0, l1);
    } else if (b < 2048 + 256) {
        int t = b - 2048;
        tsp_tile(W1, g_w1thi, g_w1tlo, 512, 512, t % 16, t / 16, tx, ty);
    } else if (b < 2048 + 256 + 32) {
        int t = b - 2304;
        tsp_tile(lw1, g_lw1thi, g_lw1tlo, 512, 64, t % 16, t / 16, tx, ty);
    } else {
        int t = b - 2336;
        tsp_tile(W2, g_w2thi, g_w2tlo, 64, 128, t % 2, t / 2, tx, ty);
    }
}

// ---------------------------------------------------------------------------
// Fused feature GEMM: h = A @ BT^T (3-term split bf16) with fused epilogue:
//   - transposed split store:   Ht{hi,lo}[(c0+c)][node]
//   - es/ed projections (per head) + global atomicMax(ed) encoder
// BM=128, BN=128, BK=64, 256 threads. PROJF = per-head F (128 or 32).
// ---------------------------------------------------------------------------
template <int PROJF>
__global__ void __launch_bounds__(256, 1)
gemm_h_fused(const u16* __restrict__ Ahi, const u16* __restrict__ Alo,
             const u16* __restrict__ Bthi, const u16* __restrict__ Btlo,
             const float* __restrict__ asrc, const float* __restrict__ adst,
             float* __restrict__ es, float* __restrict__ ed,
             unsigned* __restrict__ menc,
             u16* __restrict__ HtHi, u16* __restrict__ HtLo, int K) {
    constexpr int BM = 128, BN = 128, BK = 64;
    constexpr uint32_t ROWB = 144;
    constexpr uint32_t ABYTES = BM * ROWB;
    constexpr uint32_t BBYTES = BN * ROWB;
    constexpr uint32_t STAGE = 2 * ABYTES + 2 * BBYTES;
    constexpr int NT = BN / 16;
    constexpr int NH = (PROJF == 128) ? 1 : 4;   // heads per block
    constexpr int PH = (PROJF == 128) ? 1 : 2;   // heads per warp-col
    constexpr int PR = 138;                       // staging plane pitch (u16)

    extern __shared__ __align__(16) char dsm[];
    uint32_t sb = smem_u32(dsm);

    int tid = threadIdx.x, wid = tid >> 5, lane = tid & 31;
    int m0w = (wid >> 1) * 32;
    int n0w = (wid & 1) * (BN / 2);
    int row0 = blockIdx.x * BM;
    int c0 = blockIdx.y * BN;

    float acc[2][NT][4];
#pragma unroll
    for (int mi = 0; mi < 2; mi++)
#pragma unroll
        for (int nt = 0; nt < NT; nt++)
#pragma unroll
            for (int q = 0; q < 4; q++) acc[mi][nt][q] = 0.f;

    uint32_t pA = (uint32_t)(m0w + (lane & 15)) * ROWB + (uint32_t)((lane >> 4) << 4);
    uint32_t pB = (uint32_t)(((lane >> 4) << 3) + (lane & 7) + n0w) * ROWB +
                  (uint32_t)(((lane >> 3) & 1) << 4);

    const int KT = K / BK;

    auto load_tiles = [&](int kt, int s) {
        uint32_t base = sb + (uint32_t)s * STAGE;
        const char* gah = (const char*)(Ahi + (size_t)row0 * K + kt * BK);
        const char* gal = (const char*)(Alo + (size_t)row0 * K + kt * BK);
        const char* gbh = (const char*)(Bthi + (size_t)c0 * K + kt * BK);
        const char* gbl = (const char*)(Btlo + (size_t)c0 * K + kt * BK);
#pragma unroll
        for (int v = tid; v < BM * 8; v += 256) {
            int r = v >> 3;
            uint32_t c = (uint32_t)(v & 7) << 4;
            uint32_t so = (uint32_t)r * ROWB + c;
            size_t go = (size_t)r * K * 2 + c;
            CP_ASYNC16(base + so, gah + go);
            CP_ASYNC16(base + ABYTES + so, gal + go);
        }
#pragma unroll
        for (int v = tid; v < BN * 8; v += 256) {
            int r = v >> 3;
            uint32_t c = (uint32_t)(v & 7) << 4;
            uint32_t so = (uint32_t)r * ROWB + c;
            size_t go = (size_t)r * K * 2 + c;
            CP_ASYNC16(base + 2 * ABYTES + so, gbh + go);
            CP_ASYNC16(base + 2 * ABYTES + BBYTES + so, gbl + go);
        }
    };

    load_tiles(0, 0);
    CP_COMMIT();
    if (KT > 1) { load_tiles(1, 1); CP_COMMIT(); }

    for (int kt = 0; kt < KT; kt++) {
        int s = kt & 1;
        if (kt + 1 < KT) { CP_WAIT1(); } else { CP_WAIT0(); }
        __syncthreads();

        uint32_t bAhi = sb + (uint32_t)s * STAGE;
        uint32_t bAlo = bAhi + ABYTES;
        uint32_t bBhi = bAlo + ABYTES;
        uint32_t bBlo = bBhi + BBYTES;
#pragma unroll
        for (int kk = 0; kk < 4; kk++) {
            uint32_t ah[2][4], al[2][4];
#pragma unroll
            for (int mi = 0; mi < 2; mi++) {
                uint32_t o = pA + (uint32_t)mi * (16 * ROWB) + (uint32_t)kk * 32;
                ldsm_x4(ah[mi], bAhi + o);
                ldsm_x4(al[mi], bAlo + o);
            }
#pragma unroll
            for (int np = 0; np < NT / 2; np++) {
                uint32_t bo = pB + (uint32_t)np * (16 * ROWB) + (uint32_t)kk * 32;
                uint32_t bh[4], bl[4];
                ldsm_x4(bh, bBhi + bo);
                ldsm_x4(bl, bBlo + bo);
#pragma unroll
                for (int mi = 0; mi < 2; mi++) {
                    mma16816(acc[mi][np * 2], ah[mi], bh[0], bh[1]);
                    mma16816(acc[mi][np * 2], ah[mi], bl[0], bl[1]);
                    mma16816(acc[mi][np * 2], al[mi], bh[0], bh[1]);
                    mma16816(acc[mi][np * 2 + 1], ah[mi], bh[2], bh[3]);
                    mma16816(acc[mi][np * 2 + 1], ah[mi], bl[2], bl[3]);
                    mma16816(acc[mi][np * 2 + 1], al[mi], bh[2], bh[3]);
                }
            }
        }
        __syncthreads();
        if (kt + 2 < KT) { load_tiles(kt + 2, s); CP_COMMIT(); }
    }

    // ------------------ fused epilogue (smem safe to reuse) ------------------
    float* es_s = (float*)dsm;                       // [128][NH]
    float* ed_s = es_s + 128 * NH;                   // [128][NH]
    u16* hiPlane = (u16*)(ed_s + 128 * NH);          // [128 c][PR r]
    u16* loPlane = hiPlane + 128 * PR;

    for (int i = tid; i < 128 * NH; i += 256) { es_s[i] = 0.f; ed_s[i] = 0.f; }
    __syncthreads();

    int g = lane >> 2, tg = lane & 3;
#pragma unroll
    for (int mi = 0; mi < 2; mi++) {
#pragma unroll
        for (int rp = 0; rp < 2; rp++) {
            int lr = m0w + mi * 16 + g + rp * 8;
            float esa[PH], eda[PH];
#pragma unroll
            for (int p = 0; p < PH; p++) { esa[p] = 0.f; eda[p] = 0.f; }
#pragma unroll
            for (int nt = 0; nt < NT; nt++) {
                int lc = n0w + nt * 8 + tg * 2;
                float a0 = acc[mi][nt][rp * 2 + 0];
                float a1 = acc[mi][nt][rp * 2 + 1];
                // staging (transposed split)
                u16 h0, l0, h1, l1;
                split1(a0, h0, l0);
                split1(a1, h1, l1);
                hiPlane[lc * PR + lr] = h0;
                loPlane[lc * PR + lr] = l0;
                hiPlane[(lc + 1) * PR + lr] = h1;
                loPlane[(lc + 1) * PR + lr] = l1;
                // projections
                int p = (PROJF == 128) ? 0 : (nt >> 2);
                float s0 = asrc[c0 + lc], s1 = asrc[c0 + lc + 1];
                float d0 = adst[c0 + lc], d1 = adst[c0 + lc + 1];
                esa[p] += a0 * s0 + a1 * s1;
                eda[p] += a0 * d0 + a1 * d1;
            }
#pragma unroll
            for (int p = 0; p < PH; p++) {
                int hh = (PROJF == 128) ? 0 : ((n0w >> 5) + p);
                atomicAdd(&es_s[lr * NH + hh], esa[p]);
                atomicAdd(&ed_s[lr * NH + hh], eda[p]);
            }
        }
    }
    __syncthreads();

    // es/ed out
    if (tid < 128) {
        int node = row0 + tid;
#pragma unroll
        for (int hh = 0; hh < NH; hh++) {
            int ghead = (PROJF == 128) ? blockIdx.y : hh;
            es[ghead * NN + node] = es_s[tid * NH + hh];
            ed[ghead * NN + node] = ed_s[tid * NH + hh];
        }
    }
    // block max of ed per head -> global encoder
    if (tid < NH * 32) {
        int hh = tid >> 5, ln = tid & 31;
        float mv = -3e38f;
        for (int r = ln; r < 128; r += 32) mv = fmaxf(mv, ed_s[r * NH + hh]);
#pragma unroll
        for (int o = 16; o; o >>= 1) mv = fmaxf(mv, __shfl_xor_sync(0xffffffffu, mv, o));
        if (ln == 0) {
            int ghead = (PROJF == 128) ? blockIdx.y : hh;
            atomicMax(&menc[ghead], enc_f(mv));
        }
    }
    // transposed split store (coalesced per c-row)
    {
        int c = tid & 127;
        int plane = tid >> 7;
        const uint32_t* src = (const uint32_t*)((plane ? loPlane : hiPlane) + c * PR);
        uint32_t* dst = (uint32_t*)((plane ? HtLo : HtHi) + (size_t)(c0 + c) * NN + row0);
#pragma unroll
        for (int i = 0; i < 64; i++) dst[i] = src[i];
    }
}

// ---------------------------------------------------------------------------
// Plain split-bf16 tensor GEMM (+bias): C = A @ BT^T. BM=128, BK=64.
// ---------------------------------------------------------------------------
template <int BN>
__global__ void __launch_bounds__(256, 1)
gemm_mma(const u16* __restrict__ Ahi, const u16* __restrict__ Alo,
         const u16* __restrict__ Bthi, const u16* __restrict__ Btlo,
         const float* __restrict__ bias, float* __restrict__ C,
         int M, int K, int Nc) {
    constexpr int BM = 128, BK = 64;
    constexpr uint32_t ROWB = 144;
    constexpr uint32_t ABYTES = BM * ROWB;
    constexpr uint32_t BBYTES = (uint32_t)BN * ROWB;
    constexpr uint32_t STAGE = 2 * ABYTES + 2 * BBYTES;
    constexpr int NT = BN / 16;

    extern __shared__ __align__(16) char dsm[];
    uint32_t sb = smem_u32(dsm);

    int tid = threadIdx.x, wid = tid >> 5, lane = tid & 31;
    int m0w = (wid >> 1) * 32;
    int n0w = (wid & 1) * (BN / 2);
    int row0 = blockIdx.x * BM;
    int c0 = blockIdx.y * BN;

    float acc[2][NT][4];
#pragma unroll
    for (int mi = 0; mi < 2; mi++)
#pragma unroll
        for (int nt = 0; nt < NT; nt++)
#pragma unroll
            for (int q = 0; q < 4; q++) acc[mi][nt][q] = 0.f;

    uint32_t pA = (uint32_t)(m0w + (lane & 15)) * ROWB + (uint32_t)((lane >> 4) << 4);
    uint32_t pB = (uint32_t)(((lane >> 4) << 3) + (lane & 7) + n0w) * ROWB +
                  (uint32_t)(((lane >> 3) & 1) << 4);

    const int KT = K / BK;

    auto load_tiles = [&](int kt, int s) {
        uint32_t base = sb + (uint32_t)s * STAGE;
        const char* gah = (const char*)(Ahi + (size_t)row0 * K + kt * BK);
        const char* gal = (const char*)(Alo + (size_t)row0 * K + kt * BK);
        const char* gbh = (const char*)(Bthi + (size_t)c0 * K + kt * BK);
        const char* gbl = (const char*)(Btlo + (size_t)c0 * K + kt * BK);
#pragma unroll
        for (int v = tid; v < BM * 8; v += 256) {
            int r = v >> 3;
            uint32_t c = (uint32_t)(v & 7) << 4;
            uint32_t so = (uint32_t)r * ROWB + c;
            size_t go = (size_t)r * K * 2 + c;
            CP_ASYNC16(base + so, gah + go);
            CP_ASYNC16(base + ABYTES + so, gal + go);
        }
#pragma unroll
        for (int v = tid; v < BN * 8; v += 256) {
            int r = v >> 3;
            uint32_t c = (uint32_t)(v & 7) << 4;
            uint32_t so = (uint32_t)r * ROWB + c;
            size_t go = (size_t)r * K * 2 + c;
            CP_ASYNC16(base + 2 * ABYTES + so, gbh + go);
            CP_ASYNC16(base + 2 * ABYTES + BBYTES + so, gbl + go);
        }
    };

    load_tiles(0, 0);
    CP_COMMIT();
    if (KT > 1) { load_tiles(1, 1); CP_COMMIT(); }

    for (int kt = 0; kt < KT; kt++) {
        int s = kt & 1;
        if (kt + 1 < KT) { CP_WAIT1(); } else { CP_WAIT0(); }
        __syncthreads();

        uint32_t bAhi = sb + (uint32_t)s * STAGE;
        uint32_t bAlo = bAhi + ABYTES;
        uint32_t bBhi = bAlo + ABYTES;
        uint32_t bBlo = bBhi + BBYTES;
#pragma unroll
        for (int kk = 0; kk < 4; kk++) {
            uint32_t ah[2][4], al[2][4];
#pragma unroll
            for (int mi = 0; mi < 2; mi++) {
                uint32_t o = pA + (uint32_t)mi * (16 * ROWB) + (uint32_t)kk * 32;
                ldsm_x4(ah[mi], bAhi + o);
                ldsm_x4(al[mi], bAlo + o);
            }
#pragma unroll
            for (int np = 0; np < NT / 2; np++) {
                uint32_t bo = pB + (uint32_t)np * (16 * ROWB) + (uint32_t)kk * 32;
                uint32_t bh[4], bl[4];
                ldsm_x4(bh, bBhi + bo);
                ldsm_x4(bl, bBlo + bo);
#pragma unroll
                for (int mi = 0; mi < 2; mi++) {
                    mma16816(acc[mi][np * 2], ah[mi], bh[0], bh[1]);
                    mma16816(acc[mi][np * 2], ah[mi], bl[0], bl[1]);
                    mma16816(acc[mi][np * 2], al[mi], bh[0], bh[1]);
                    mma16816(acc[mi][np * 2 + 1], ah[mi], bh[2], bh[3]);
                    mma16816(acc[mi][np * 2 + 1], ah[mi], bl[2], bl[3]);
                    mma16816(acc[mi][np * 2 + 1], al[mi], bh[2], bh[3]);
                }
            }
        }
        __syncthreads();
        if (kt + 2 < KT) { load_tiles(kt + 2, s); CP_COMMIT(); }
    }

    int g = lane >> 2, tg = lane & 3;
#pragma unroll
    for (int mi = 0; mi < 2; mi++) {
        int r0 = row0 + m0w + mi * 16 + g;
        int r1 = r0 + 8;
#pragma unroll
        for (int nt = 0; nt < NT; nt++) {
            int cn = c0 + n0w + nt * 8 + tg * 2;
            float b0 = bias ? bias[cn] : 0.f;
            float b1 = bias ? bias[cn + 1] : 0.f;
            *(float2*)(&C[(size_t)r0 * Nc + cn]) =
                make_float2(acc[mi][nt][0] + b0, acc[mi][nt][1] + b1);
            *(float2*)(&C[(size_t)r1 * Nc + cn]) =
                make_float2(acc[mi][nt][2] + b0, acc[mi][nt][3] + b1);
        }
    }
}

// ---------------------------------------------------------------------------
// fp32 fallback GEMM for the tiny final layer
// ---------------------------------------------------------------------------
template <int BN, int TM, int TN>
__global__ void gemm_bias_kernel(const float* __restrict__ A,
                                 const float* __restrict__ B,
                                 const float* __restrict__ bias,
                                 float* __restrict__ C,
                                 int M, int K, int Nc) {
    const int BM = 64, BK = 32;
    __shared__ float sA[BK][BM + 4];
    __shared__ float sB[BK][BN + 4];
    int tid = threadIdx.x;
    const int CT = BN / TN;
    int tx = tid % CT, ty = tid / CT;
    int row0 = blockIdx.x * BM, c0 = blockIdx.y * BN;

    float acc[TM][TN];
#pragma unroll
    for (int i = 0; i < TM; i++)
#pragma unroll
        for (int j = 0; j < TN; j++) acc[i][j] = 0.f;

    for (int k0 = 0; k0 < K; k0 += BK) {
        __syncthreads();
        for (int v = tid; v < BM * BK / 4; v += 256) {
            int idx = v * 4;
            int r = idx >> 5, kk = idx & 31;
            float4 f = *reinterpret_cast<const float4*>(&A[(size_t)(row0 + r) * K + k0 + kk]);
            sA[kk + 0][r] = f.x; sA[kk + 1][r] = f.y;
            sA[kk + 2][r] = f.z; sA[kk + 3][r] = f.w;
        }
        for (int v = tid; v < BK * BN / 4; v += 256) {
            int idx = v * 4;
            int kk = idx / BN, c = idx % BN;
            float4 f = *reinterpret_cast<const float4*>(&B[(size_t)(k0 + kk) * Nc + c0 + c]);
            *reinterpret_cast<float4*>(&sB[kk][c]) = f;
        }
        __syncthreads();
#pragma unroll
        for (int kk = 0; kk < BK; kk++) {
            float a[TM], b[TN];
#pragma unroll
            for (int i = 0; i < TM; i++) a[i] = sA[kk][ty * TM + i];
#pragma unroll
            for (int j = 0; j < TN; j++) b[j] = sB[kk][tx * TN + j];
#pragma unroll
            for (int i = 0; i < TM; i++)
#pragma unroll
                for (int j = 0; j < TN; j++) acc[i][j] = fmaf(a[i], b[j], acc[i][j]);
        }
    }
#pragma unroll
    for (int j = 0; j < TN; j++) {
        int c = c0 + tx * TN + j;
        float bv = bias ? bias[c] : 0.f;
#pragma unroll
        for (int i = 0; i < TM; i++)
            C[(size_t)(row0 + ty * TM + i) * Nc + c] = acc[i][j] + bv;
    }
}

// ---------------------------------------------------------------------------
// Fused GAT attention via mma.sync bf16 (3-term split), optional outputs.
// ---------------------------------------------------------------------------
template <int F>
__global__ void __launch_bounds__(256, 1)
gat_attn_mma(const u16* __restrict__ Bhi, const u16* __restrict__ Blo,
             const float* __restrict__ es, const float* __restrict__ ed,
             const unsigned* __restrict__ menc, float* __restrict__ Out,
             u16* __restrict__ OutHi, u16* __restrict__ OutLo) {
    constexpr int KT = 64;
    constexpr int T = NN / KT;
    constexpr int WC = (F == 128) ? 2 : 1;
    constexpr int MT = WC;
    constexpr int NT = F / (8 * WC);
    constexpr uint32_t ROWB = 144;
    constexpr uint32_t PBYTES = 128 * ROWB;
    constexpr uint32_t HBYTES = (uint32_t)F * ROWB;

    extern __shared__ __align__(16) char dsm[];
    uint32_t sb = smem_u32(dsm);
    const uint32_t P0 = sb + 512;
    const uint32_t H0 = P0 + 4 * PBYTES;

    int tid = threadIdx.x;
    int wid = tid >> 5, lane = tid & 31;
    int h = blockIdx.y;
    int i0 = blockIdx.x * 128;

    int wr = wid / WC, wc = wid % WC;
    int m0 = wr * (16 * MT);
    int n0 = wc * (NT * 8);

    uint32_t pA = (uint32_t)(m0 + (lane & 15)) * ROWB + ((lane >> 4) << 4);
    uint32_t pB = (uint32_t)(((lane >> 4) << 3) + (lane & 7)) * ROWB +
                  (((lane >> 3) & 1) << 4) + (uint32_t)n0 * ROWB;

    int irow = tid >> 1;
    int jhalf = tid & 1;
    float esr = es[h * NN + i0 + irow];
    float zz = esr + dec_f(menc[h]);
    float mr = fmaxf(zz, 0.2f * zz);
    const float* edh = ed + h * NN;
    float psum = 0.f;
    uint32_t poff = (uint32_t)irow * ROWB + (uint32_t)jhalf * 64;

    float acc[MT][NT][4];
#pragma unroll
    for (int mi = 0; mi < MT; mi++)
#pragma unroll
        for (int nt = 0; nt < NT; nt++)
#pragma unroll
            for (int q = 0; q < 4; q++) acc[mi][nt][q] = 0.f;

    auto load_H = [&](int t, int b) {
        const char* gh = (const char*)Bhi + ((size_t)h * F * NN + (size_t)t * KT) * 2;
        const char* gl = (const char*)Blo + ((size_t)h * F * NN + (size_t)t * KT) * 2;
        uint32_t dh = H0 + (uint32_t)b * HBYTES;
        uint32_t dl = H0 + (uint32_t)(2 + b) * HBYTES;
#pragma unroll
        for (int v = tid; v < F * 8; v += 256) {
            int f = v >> 3;
            uint32_t c = (uint32_t)(v & 7) << 4;
            uint32_t so = (uint32_t)f * ROWB + c;
            CP_ASYNC16(dh + so, gh + (size_t)f * NN * 2 + c);
            CP_ASYNC16(dl + so, gl + (size_t)f * NN * 2 + c);
        }
    };

    auto pgen = [&](int t, int b) {
        uint32_t dh = P0 + (uint32_t)b * PBYTES + poff;
        uint32_t dl = P0 + (uint32_t)(2 + b) * PBYTES + poff;
        unsigned word = g_adjbits[(size_t)(i0 + irow) * 128 + t * 2 + jhalf];
        const float* edp = edh + t * KT + jhalf * 32;
#pragma unroll
        for (int jj = 0; jj < 32; jj += 8) {
            float4 e0 = __ldg((const float4*)(edp + jj));
            float4 e1 = __ldg((const float4*)(edp + jj + 4));
            float ee[8] = {e0.x, e0.y, e0.z, e0.w, e1.x, e1.y, e1.z, e1.w};
            uint32_t hbits[8], lbits[8];
#pragma unroll
            for (int u = 0; u < 8; u++) {
                float e = esr + ee[u];
                float lr = fmaxf(e, 0.2f * e);
                float p = __expf(lr - mr);
                p = ((word >> (jj + u)) & 1u) ? p : 0.f;
                psum += p;
                uint32_t pb = __float_as_uint(p);
                uint32_t hb = pb & 0xffff0000u;
                hbits[u] = hb;
                lbits[u] = __float_as_uint(p - __uint_as_float(hb));
            }
            uint4 hv, lv;
            hv.x = prmt7632(hbits[0], hbits[1]);
            hv.y = prmt7632(hbits[2], hbits[3]);
            hv.z = prmt7632(hbits[4], hbits[5]);
            hv.w = prmt7632(hbits[6], hbits[7]);
            lv.x = prmt7632(lbits[0], lbits[1]);
            lv.y = prmt7632(lbits[2], lbits[3]);
            lv.z = prmt7632(lbits[4], lbits[5]);
            lv.w = prmt7632(lbits[6], lbits[7]);
            asm volatile("st.shared.v4.b32 [%0], {%1,%2,%3,%4};"
                         :: "r"(dh + (uint32_t)jj * 2), "r"(hv.x), "r"(hv.y), "r"(hv.z), "r"(hv.w));
            asm volatile("st.shared.v4.b32 [%0], {%1,%2,%3,%4};"
                         :: "r"(dl + (uint32_t)jj * 2), "r"(lv.x), "r"(lv.y), "r"(lv.z), "r"(lv.w));
        }
    };

    load_H(0, 0);
    CP_COMMIT();
    pgen(0, 0);
    CP_WAIT0();
    __syncthreads();

    for (int t = 0; t < T; t++) {
        int b = t & 1;
        if (t + 1 < T) { load_H(t + 1, b ^ 1); CP_COMMIT(); }

        uint32_t basePhi = P0 + (uint32_t)b * PBYTES;
        uint32_t basePlo = P0 + (uint32_t)(2 + b) * PBYTES;
        uint32_t baseHhi = H0 + (uint32_t)b * HBYTES;
        uint32_t baseHlo = H0 + (uint32_t)(2 + b) * HBYTES;
#pragma unroll
        for (int kk = 0; kk < 4; kk++) {
            uint32_t ah[MT][4], al[MT][4];
#pragma unroll
            for (int mi = 0; mi < MT; mi++) {
                uint32_t o = pA + (uint32_t)mi * (16 * ROWB) + (uint32_t)kk * 32;
                ldsm_x4(ah[mi], basePhi + o);
                ldsm_x4(al[mi], basePlo + o);
            }
#pragma unroll
            for (int np = 0; np < NT / 2; np++) {
                uint32_t bo = pB + (uint32_t)np * (16 * ROWB) + (uint32_t)kk * 32;
                uint32_t bh[4], bl[4];
                ldsm_x4(bh, baseHhi + bo);
                ldsm_x4(bl, baseHlo + bo);
#pragma unroll
                for (int mi = 0; mi < MT; mi++) {
                    mma16816(acc[mi][np * 2], ah[mi], bh[0], bh[1]);
                    mma16816(acc[mi][np * 2], ah[mi], bl[0], bl[1]);
                    mma16816(acc[mi][np * 2], al[mi], bh[0], bh[1]);
                    mma16816(acc[mi][np * 2 + 1], ah[mi], bh[2], bh[3]);
                    mma16816(acc[mi][np * 2 + 1], ah[mi], bl[2], bl[3]);
                    mma16816(acc[mi][np * 2 + 1], al[mi], bh[2], bh[3]);
                }
            }
        }

        if (t + 1 < T) pgen(t + 1, b ^ 1);
        CP_WAIT0();
        __syncthreads();
    }

    float tot = psum + __shfl_xor_sync(0xffffffffu, psum, 1);
    if (jhalf == 0) *(float*)(dsm + 4 * irow) = tot;
    __syncthreads();

    int g = lane >> 2, tg = lane & 3;
#pragma unroll
    for (int mi = 0; mi < MT; mi++) {
        int r0 = m0 + mi * 16 + g;
        int r1 = r0 + 8;
        float rinv0 = 1.f / *(const float*)(dsm + 4 * r0);
        float rinv1 = 1.f / *(const float*)(dsm + 4 * r1);
        size_t o0 = (size_t)(i0 + r0) * (HH * F) + h * F;
        size_t o1 = (size_t)(i0 + r1) * (HH * F) + h * F;
#pragma unroll
        for (int nt = 0; nt < NT; nt++) {
            int cn = n0 + nt * 8 + tg * 2;
            float2 v0 = make_float2(acc[mi][nt][0] * rinv0, acc[mi][nt][1] * rinv0);
            float2 v1 = make_float2(acc[mi][nt][2] * rinv1, acc[mi][nt][3] * rinv1);
            if (Out) {
                *(float2*)(Out + o0 + cn) = v0;
                *(float2*)(Out + o1 + cn) = v1;
            }
            if (OutHi) {
                uint32_t hh, ll;
                pack_split(v0.x, v0.y, hh, ll);
                *(uint32_t*)(OutHi + o0 + cn) = hh;
                *(uint32_t*)(OutLo + o0 + cn) = ll;
                pack_split(v1.x, v1.y, hh, ll);
                *(uint32_t*)(OutHi + o1 + cn) = hh;
                *(uint32_t*)(OutLo + o1 + cn) = ll;
            }
        }
    }
}

// ---------------------------------------------------------------------------
// BatchNorm + ELU (optional fp32 / split outputs)
// ---------------------------------------------------------------------------
__global__ void bn_elu_kernel(const float* __restrict__ Y,
                              const float* __restrict__ gamma,
                              const float* __restrict__ beta,
                              float* __restrict__ Out,
                              u16* __restrict__ OutHi, u16* __restrict__ OutLo,
                              int C) {
    int c = blockIdx.x;
    float s1 = 0.f, s2 = 0.f;
    for (int i = threadIdx.x; i < NN; i += 256) {
        float v = Y[(size_t)i * C + c];
        s1 += v;
        s2 += v * v;
    }
    __shared__ float r1[256], r2[256];
    r1[threadIdx.x] = s1; r2[threadIdx.x] = s2;
    __syncthreads();
    for (int s = 128; s; s >>= 1) {
        if (threadIdx.x < s) {
            r1[threadIdx.x] += r1[threadIdx.x + s];
            r2[threadIdx.x] += r2[threadIdx.x + s];
        }
        __syncthreads();
    }
    float mean = r1[0] * (1.f / NN);
    float var = r2[0] * (1.f / NN) - mean * mean;
    float inv = rsqrtf(var + 1e-5f);
    float g = gamma[c], b = beta[c];
    for (int i = threadIdx.x; i < NN; i += 256) {
        float v = Y[(size_t)i * C + c];
        float z = (v - mean) * inv * g + b;
        float o = z > 0.f ? z : (__expf(z) - 1.f);
        if (Out) Out[(size_t)i * C + c] = o;
        if (OutHi) {
            uint32_t ob = __float_as_uint(o);
            uint32_t hb = ob & 0xffff0000u;
            float lv = o - __uint_as_float(hb);
            OutHi[(size_t)i * C + c] = (u16)(hb >> 16);
            OutLo[(size_t)i * C + c] = (u16)(__float_as_uint(lv) >> 16);
        }
    }
}

// ---------------------------------------------------------------------------
extern "C" void kernel_launch(void* const* d_in, const int* in_sizes, int n_in,
                              void* d_out, int out_size) {
    const float* x   = (const float*)d_in[0];
    const int*   adj = (const int*)d_in[1];
    const float* W1  = (const float*)d_in[2];
    const float* a1s = (const float*)d_in[3];
    const float* a1d = (const float*)d_in[4];
    const float* lw1 = (const float*)d_in[5];
    const float* lb1 = (const float*)d_in[6];
    const float* g1  = (const float*)d_in[7];
    const float* be1 = (const float*)d_in[8];
    const float* W2  = (const float*)d_in[9];
    const float* a2s = (const float*)d_in[10];
    const float* a2d = (const float*)d_in[11];
    const float* lw2 = (const float*)d_in[12];
    const float* lb2 = (const float*)d_in[13];
    const float* g2  = (const float*)d_in[14];
    const float* be2 = (const float*)d_in[15];
    float* out = (float*)d_out;

    float *p_es1, *p_ed1, *p_es2, *p_ed2, *p_y1, *p_x3, *p_y2;
    unsigned *p_mx1e, *p_mx2e;
    u16 *p_t1h, *p_t1l, *p_t2h, *p_t2l;
    u16 *p_xhi, *p_xlo, *p_x1hi, *p_x1lo, *p_x2hi, *p_x2lo;
    u16 *p_w1th, *p_w1tl, *p_lw1th, *p_lw1tl, *p_w2th, *p_w2tl;
    cudaGetSymbolAddress((void**)&p_es1, g_es1);
    cudaGetSymbolAddress((void**)&p_ed1, g_ed1);
    cudaGetSymbolAddress((void**)&p_es2, g_es2);
    cudaGetSymbolAddress((void**)&p_ed2, g_ed2);
    cudaGetSymbolAddress((void**)&p_mx1e, g_mx1e);
    cudaGetSymbolAddress((void**)&p_mx2e, g_mx2e);
    cudaGetSymbolAddress((void**)&p_y1, g_y1);
    cudaGetSymbolAddress((void**)&p_x3, g_x3);
    cudaGetSymbolAddress((void**)&p_y2, g_y2);
    cudaGetSymbolAddress((void**)&p_t1h, g_ht1_hi);
    cudaGetSymbolAddress((void**)&p_t1l, g_ht1_lo);
    cudaGetSymbolAddress((void**)&p_t2h, g_ht2_hi);
    cudaGetSymbolAddress((void**)&p_t2l, g_ht2_lo);
    cudaGetSymbolAddress((void**)&p_xhi, g_xhi);
    cudaGetSymbolAddress((void**)&p_xlo, g_xlo);
    cudaGetSymbolAddress((void**)&p_x1hi, g_x1hi);
    cudaGetSymbolAddress((void**)&p_x1lo, g_x1lo);
    cudaGetSymbolAddress((void**)&p_x2hi, g_x2hi);
    cudaGetSymbolAddress((void**)&p_x2lo, g_x2lo);
    cudaGetSymbolAddress((void**)&p_w1th, g_w1thi);
    cudaGetSymbolAddress((void**)&p_w1tl, g_w1tlo);
    cudaGetSymbolAddress((void**)&p_lw1th, g_lw1thi);
    cudaGetSymbolAddress((void**)&p_lw1tl, g_lw1tlo);
    cudaGetSymbolAddress((void**)&p_w2th, g_w2thi);
    cudaGetSymbolAddress((void**)&p_w2tl, g_w2tlo);

    const int SMEM1 = 512 + 4 * (128 * 144) + 4 * (128 * 144);
    const int SMEM2 = 512 + 4 * (128 * 144) + 4 * (32 * 144);
    const int SMEMG128 = 2 * (2 * 128 * 144 + 2 * 128 * 144);
    const int SMEMG64  = 2 * (2 * 128 * 144 + 2 * 64 * 144);
    cudaFuncSetAttribute(gat_attn_mma<128>, cudaFuncAttributeMaxDynamicSharedMemorySize, SMEM1);
    cudaFuncSetAttribute(gat_attn_mma<32>,  cudaFuncAttributeMaxDynamicSharedMemorySize, SMEM2);
    cudaFuncSetAttribute(gemm_h_fused<128>, cudaFuncAttributeMaxDynamicSharedMemorySize, SMEMG128);
    cudaFuncSetAttribute(gemm_h_fused<32>,  cudaFuncAttributeMaxDynamicSharedMemorySize, SMEMG128);
    cudaFuncSetAttribute(gemm_mma<64>,  cudaFuncAttributeMaxDynamicSharedMemorySize, SMEMG64);

    // 1) adjacency bitmask + max-encoder init
    pack_adj_kernel<<<NN * 128 / 8, 256>>>(adj);
    // 2) fused prep: split x, transpose-split W1 / lw1 / W2
    prep_kernel<<<2344, dim3(32, 8)>>>(x, W1, lw1, W2);
    // 3) h1 GEMM fused: transposed split ht1 + es1/ed1 + max encoders
    gemm_h_fused<128><<<dim3(32, 4), 256, SMEMG128>>>(
        p_xhi, p_xlo, p_w1th, p_w1tl, a1s, a1d, p_es1, p_ed1, p_mx1e,
        p_t1h, p_t1l, 512);
    // 4) layer-1 attention -> x1 split only   [PROFILED LAUNCH]
    gat_attn_mma<128><<<dim3(32, HH), 256, SMEM1>>>(
        p_t1h, p_t1l, p_es1, p_ed1, p_mx1e, nullptr, p_x1hi, p_x1lo);
    // 5) y1 = x1 @ lw1 + lb1
    gemm_mma<64><<<dim3(32, 1), 256, SMEMG64>>>(p_x1hi, p_x1lo, p_lw1th, p_lw1tl,
                                                lb1, p_y1, NN, 512, 64);
    // 6) x2 = BN_ELU(y1), split only
    bn_elu_kernel<<<64, 256>>>(p_y1, g1, be1, nullptr, p_x2hi, p_x2lo, 64);
    // 7) h2 GEMM fused: ht2 + es2/ed2 + max encoders
    gemm_h_fused<32><<<dim3(32, 1), 256, SMEMG128>>>(
        p_x2hi, p_x2lo, p_w2th, p_w2tl, a2s, a2d, p_es2, p_ed2, p_mx2e,
        p_t2h, p_t2l, 64);
    // 8) layer-2 attention -> x3 fp32
    gat_attn_mma<32><<<dim3(32, HH), 256, SMEM2>>>(
        p_t2h, p_t2l, p_es2, p_ed2, p_mx2e, p_x3, nullptr, nullptr);
    // 9) final tiny layer
    gemm_bias_kernel<16, 4, 1><<<dim3(64, 1), 256>>>(p_x3, lw2, lb2, p_y2, NN, 128, 16);
    // 10) out
    bn_elu_kernel<<<16, 256>>>(p_y2, g2, be2, out, nullptr, nullptr, 16);
}

// round 9
// speedup vs baseline: 2.6297x; 1.0354x over previous
#include <cuda_runtime.h>
#include <cuda_bf16.h>
#include <cstdint>

#define NN 4096
#define HH 4
typedef unsigned short u16;

// ---------------------------------------------------------------------------
// scratch (static device allocations only)
// ---------------------------------------------------------------------------
__device__ unsigned g_adjbits[NN * 128];
__device__ float g_es1[HH * NN], g_ed1[HH * NN];
__device__ float g_es2[HH * NN], g_ed2[HH * NN];
__device__ unsigned g_mx1e[HH], g_mx2e[HH];
__device__ float g_y1[NN * 64];
__device__ float g_x3[NN * 128];
__device__ float g_y2[NN * 16];
// transposed split-bf16 feature matrices: [HF][NN]
__device__ u16 g_ht1_hi[512 * NN], g_ht1_lo[512 * NN];
__device__ u16 g_ht2_hi[128 * NN], g_ht2_lo[128 * NN];
// split activations (row-major, K-contig for GEMM A side)
__device__ u16 g_xhi[NN * 512], g_xlo[NN * 512];
__device__ u16 g_x1hi[NN * 512], g_x1lo[NN * 512];
__device__ u16 g_x2hi[NN * 64], g_x2lo[NN * 64];
// split transposed weights [N][K]
__device__ u16 g_w1thi[512 * 512], g_w1tlo[512 * 512];
__device__ u16 g_lw1thi[64 * 512], g_lw1tlo[64 * 512];
__device__ u16 g_w2thi[128 * 64], g_w2tlo[128 * 64];

// ---------------------------------------------------------------------------
// helpers
// ---------------------------------------------------------------------------
__device__ __forceinline__ uint32_t smem_u32(const void* p) {
    uint32_t a;
    asm("{ .reg .u64 t; cvta.to.shared.u64 t, %1; cvt.u32.u64 %0, t; }"
        : "=r"(a) : "l"(p));
    return a;
}
__device__ __forceinline__ uint32_t prmt7632(uint32_t a, uint32_t b) {
    uint32_t r;
    asm("prmt.b32 %0, %1, %2, 0x7632;" : "=r"(r) : "r"(a), "r"(b));
    return r;
}
// order-preserving float->uint encoding for atomicMax
__device__ __forceinline__ unsigned enc_f(float f) {
    unsigned b = __float_as_uint(f);
    return (b & 0x80000000u) ? ~b : (b | 0x80000000u);
}
__device__ __forceinline__ float dec_f(unsigned k) {
    unsigned b = (k & 0x80000000u) ? (k & 0x7fffffffu) : ~k;
    return __uint_as_float(b);
}
__device__ __forceinline__ void split1(float v, u16& h, u16& l) {
    uint32_t b = __float_as_uint(v);
    uint32_t hb = b & 0xffff0000u;
    h = (u16)(hb >> 16);
    l = (u16)(__float_as_uint(v - __uint_as_float(hb)) >> 16);
}

#define CP_ASYNC16(saddr, gptr) \
    asm volatile("cp.async.cg.shared.global [%0], [%1], 16;" \
                 :: "r"((uint32_t)(saddr)), "l"(gptr))
#define CP_COMMIT() asm volatile("cp.async.commit_group;" ::: "memory")
#define CP_WAIT0()  asm volatile("cp.async.wait_group 0;" ::: "memory")
#define CP_WAIT1()  asm volatile("cp.async.wait_group 1;" ::: "memory")

__device__ __forceinline__ void ldsm_x4(uint32_t* r, uint32_t addr) {
    asm volatile("ldmatrix.sync.aligned.m8n8.x4.shared.b16 {%0,%1,%2,%3}, [%4];"
                 : "=r"(r[0]), "=r"(r[1]), "=r"(r[2]), "=r"(r[3]) : "r"(addr));
}
__device__ __forceinline__ void mma16816(float* c, const uint32_t* a,
                                         uint32_t b0, uint32_t b1) {
    asm volatile(
        "mma.sync.aligned.m16n8k16.row.col.f32.bf16.bf16.f32 "
        "{%0,%1,%2,%3}, {%4,%5,%6,%7}, {%8,%9}, {%0,%1,%2,%3};"
        : "+f"(c[0]), "+f"(c[1]), "+f"(c[2]), "+f"(c[3])
        : "r"(a[0]), "r"(a[1]), "r"(a[2]), "r"(a[3]), "r"(b0), "r"(b1));
}
__device__ __forceinline__ void pack_split(float a, float b,
                                           uint32_t& h, uint32_t& l) {
    uint32_t ab = __float_as_uint(a), bb = __float_as_uint(b);
    float la = a - __uint_as_float(ab & 0xffff0000u);
    float lb = b - __uint_as_float(bb & 0xffff0000u);
    h = prmt7632(ab, bb);
    l = prmt7632(__float_as_uint(la), __float_as_uint(lb));
}

// ---------------------------------------------------------------------------
// launch 1: adj -> bitmask; also init the max-encoders
// ---------------------------------------------------------------------------
__global__ void pack_adj_kernel(const int* __restrict__ adj) {
    if (blockIdx.x == 0 && threadIdx.x < 2 * HH) {
        if (threadIdx.x < HH) g_mx1e[threadIdx.x] = 0u;
        else                  g_mx2e[threadIdx.x - HH] = 0u;
    }
    int gw = blockIdx.x * 8 + (threadIdx.x >> 5);
    int lane = threadIdx.x & 31;
    int row = gw >> 7, word = gw & 127;
    int v = adj[(size_t)row * NN + word * 32 + lane];
    unsigned m = __ballot_sync(0xffffffffu, v > 0);
    if (lane == 0) g_adjbits[gw] = m;
}

// ---------------------------------------------------------------------------
// launch 2: fused prep — split x, transpose-split W1 / lw1 / W2
// ---------------------------------------------------------------------------
__device__ void tsp_tile(const float* __restrict__ A, u16* __restrict__ hi,
                         u16* __restrict__ lo, int R, int C, int bx, int by,
                         int tx, int ty) {
    __shared__ float tile[32][33];
    int j0 = bx * 32, c0 = by * 32;
    for (int r = ty; r < 32; r += 8)
        tile[r][tx] = A[(size_t)(j0 + r) * C + c0 + tx];
    __syncthreads();
    for (int r = ty; r < 32; r += 8) {
        float v = tile[tx][r];
        uint32_t b = __float_as_uint(v);
        uint32_t hb = b & 0xffff0000u;
        float lv = v - __uint_as_float(hb);
        size_t o = (size_t)(c0 + r) * R + j0 + tx;
        hi[o] = (u16)(hb >> 16);
        lo[o] = (u16)(__float_as_uint(lv) >> 16);
    }
}

__global__ void prep_kernel(const float* __restrict__ x,
                            const float* __restrict__ W1,
                            const float* __restrict__ lw1,
                            const float* __restrict__ W2) {
    int b = blockIdx.x;
    int tx = threadIdx.x, ty = threadIdx.y;
    int flat = ty * 32 + tx;
    if (b < 2048) {
        int i = b * 256 + flat;
        float4 v = ((const float4*)x)[i];
        uint32_t h0, l0, h1, l1;
        pack_split(v.x, v.y, h0, l0);
        pack_split(v.z, v.w, h1, l1);
        ((uint2*)g_xhi)[i] = make_uint2(h0, h1);
        ((uint2*)g_xlo)[i] = make_uint2(l0, l1);
    } else if (b < 2048 + 256) {
        int t = b - 2048;
        tsp_tile(W1, g_w1thi, g_w1tlo, 512, 512, t % 16, t / 16, tx, ty);
    } else if (b < 2048 + 256 + 32) {
        int t = b - 2304;
        tsp_tile(lw1, g_lw1thi, g_lw1tlo, 512, 64, t % 16, t / 16, tx, ty);
    } else {
        int t = b - 2336;
        tsp_tile(W2, g_w2thi, g_w2tlo, 64, 128, t % 2, t / 2, tx, ty);
    }
}

// ---------------------------------------------------------------------------
// Fused feature GEMM: h = A @ BT^T (3-term split bf16) with fused epilogue.
// ---------------------------------------------------------------------------
template <int PROJF>
__global__ void __launch_bounds__(256, 1)
gemm_h_fused(const u16* __restrict__ Ahi, const u16* __restrict__ Alo,
             const u16* __restrict__ Bthi, const u16* __restrict__ Btlo,
             const float* __restrict__ asrc, const float* __restrict__ adst,
             float* __restrict__ es, float* __restrict__ ed,
             unsigned* __restrict__ menc,
             u16* __restrict__ HtHi, u16* __restrict__ HtLo, int K) {
    constexpr int BM = 128, BN = 128, BK = 64;
    constexpr uint32_t ROWB = 144;
    constexpr uint32_t ABYTES = BM * ROWB;
    constexpr uint32_t BBYTES = BN * ROWB;
    constexpr uint32_t STAGE = 2 * ABYTES + 2 * BBYTES;
    constexpr int NT = BN / 16;
    constexpr int NH = (PROJF == 128) ? 1 : 4;
    constexpr int PH = (PROJF == 128) ? 1 : 2;
    constexpr int PR = 138;

    extern __shared__ __align__(16) char dsm[];
    uint32_t sb = smem_u32(dsm);

    int tid = threadIdx.x, wid = tid >> 5, lane = tid & 31;
    int m0w = (wid >> 1) * 32;
    int n0w = (wid & 1) * (BN / 2);
    int row0 = blockIdx.x * BM;
    int c0 = blockIdx.y * BN;

    float acc[2][NT][4];
#pragma unroll
    for (int mi = 0; mi < 2; mi++)
#pragma unroll
        for (int nt = 0; nt < NT; nt++)
#pragma unroll
            for (int q = 0; q < 4; q++) acc[mi][nt][q] = 0.f;

    uint32_t pA = (uint32_t)(m0w + (lane & 15)) * ROWB + (uint32_t)((lane >> 4) << 4);
    uint32_t pB = (uint32_t)(((lane >> 4) << 3) + (lane & 7) + n0w) * ROWB +
                  (uint32_t)(((lane >> 3) & 1) << 4);

    const int KT = K / BK;

    auto load_tiles = [&](int kt, int s) {
        uint32_t base = sb + (uint32_t)s * STAGE;
        const char* gah = (const char*)(Ahi + (size_t)row0 * K + kt * BK);
        const char* gal = (const char*)(Alo + (size_t)row0 * K + kt * BK);
        const char* gbh = (const char*)(Bthi + (size_t)c0 * K + kt * BK);
        const char* gbl = (const char*)(Btlo + (size_t)c0 * K + kt * BK);
#pragma unroll
        for (int v = tid; v < BM * 8; v += 256) {
            int r = v >> 3;
            uint32_t c = (uint32_t)(v & 7) << 4;
            uint32_t so = (uint32_t)r * ROWB + c;
            size_t go = (size_t)r * K * 2 + c;
            CP_ASYNC16(base + so, gah + go);
            CP_ASYNC16(base + ABYTES + so, gal + go);
        }
#pragma unroll
        for (int v = tid; v < BN * 8; v += 256) {
            int r = v >> 3;
            uint32_t c = (uint32_t)(v & 7) << 4;
            uint32_t so = (uint32_t)r * ROWB + c;
            size_t go = (size_t)r * K * 2 + c;
            CP_ASYNC16(base + 2 * ABYTES + so, gbh + go);
            CP_ASYNC16(base + 2 * ABYTES + BBYTES + so, gbl + go);
        }
    };

    load_tiles(0, 0);
    CP_COMMIT();
    if (KT > 1) { load_tiles(1, 1); CP_COMMIT(); }

    for (int kt = 0; kt < KT; kt++) {
        int s = kt & 1;
        if (kt + 1 < KT) { CP_WAIT1(); } else { CP_WAIT0(); }
        __syncthreads();

        uint32_t bAhi = sb + (uint32_t)s * STAGE;
        uint32_t bAlo = bAhi + ABYTES;
        uint32_t bBhi = bAlo + ABYTES;
        uint32_t bBlo = bBhi + BBYTES;
#pragma unroll
        for (int kk = 0; kk < 4; kk++) {
            uint32_t ah[2][4], al[2][4];
#pragma unroll
            for (int mi = 0; mi < 2; mi++) {
                uint32_t o = pA + (uint32_t)mi * (16 * ROWB) + (uint32_t)kk * 32;
                ldsm_x4(ah[mi], bAhi + o);
                ldsm_x4(al[mi], bAlo + o);
            }
#pragma unroll
            for (int np = 0; np < NT / 2; np++) {
                uint32_t bo = pB + (uint32_t)np * (16 * ROWB) + (uint32_t)kk * 32;
                uint32_t bh[4], bl[4];
                ldsm_x4(bh, bBhi + bo);
                ldsm_x4(bl, bBlo + bo);
#pragma unroll
                for (int mi = 0; mi < 2; mi++) {
                    mma16816(acc[mi][np * 2], ah[mi], bh[0], bh[1]);
                    mma16816(acc[mi][np * 2], ah[mi], bl[0], bl[1]);
                    mma16816(acc[mi][np * 2], al[mi], bh[0], bh[1]);
                    mma16816(acc[mi][np * 2 + 1], ah[mi], bh[2], bh[3]);
                    mma16816(acc[mi][np * 2 + 1], ah[mi], bl[2], bl[3]);
                    mma16816(acc[mi][np * 2 + 1], al[mi], bh[2], bh[3]);
                }
            }
        }
        __syncthreads();
        if (kt + 2 < KT) { load_tiles(kt + 2, s); CP_COMMIT(); }
    }

    // ------------------ fused epilogue ------------------
    float* es_s = (float*)dsm;
    float* ed_s = es_s + 128 * NH;
    u16* hiPlane = (u16*)(ed_s + 128 * NH);
    u16* loPlane = hiPlane + 128 * PR;

    for (int i = tid; i < 128 * NH; i += 256) { es_s[i] = 0.f; ed_s[i] = 0.f; }
    __syncthreads();

    int g = lane >> 2, tg = lane & 3;
#pragma unroll
    for (int mi = 0; mi < 2; mi++) {
#pragma unroll
        for (int rp = 0; rp < 2; rp++) {
            int lr = m0w + mi * 16 + g + rp * 8;
            float esa[PH], eda[PH];
#pragma unroll
            for (int p = 0; p < PH; p++) { esa[p] = 0.f; eda[p] = 0.f; }
#pragma unroll
            for (int nt = 0; nt < NT; nt++) {
                int lc = n0w + nt * 8 + tg * 2;
                float a0 = acc[mi][nt][rp * 2 + 0];
                float a1 = acc[mi][nt][rp * 2 + 1];
                u16 h0, l0, h1, l1;
                split1(a0, h0, l0);
                split1(a1, h1, l1);
                hiPlane[lc * PR + lr] = h0;
                loPlane[lc * PR + lr] = l0;
                hiPlane[(lc + 1) * PR + lr] = h1;
                loPlane[(lc + 1) * PR + lr] = l1;
                int p = (PROJF == 128) ? 0 : (nt >> 2);
                float s0 = asrc[c0 + lc], s1 = asrc[c0 + lc + 1];
                float d0 = adst[c0 + lc], d1 = adst[c0 + lc + 1];
                esa[p] += a0 * s0 + a1 * s1;
                eda[p] += a0 * d0 + a1 * d1;
            }
#pragma unroll
            for (int p = 0; p < PH; p++) {
                int hh = (PROJF == 128) ? 0 : ((n0w >> 5) + p);
                atomicAdd(&es_s[lr * NH + hh], esa[p]);
                atomicAdd(&ed_s[lr * NH + hh], eda[p]);
            }
        }
    }
    __syncthreads();

    if (tid < 128) {
        int node = row0 + tid;
#pragma unroll
        for (int hh = 0; hh < NH; hh++) {
            int ghead = (PROJF == 128) ? blockIdx.y : hh;
            es[ghead * NN + node] = es_s[tid * NH + hh];
            ed[ghead * NN + node] = ed_s[tid * NH + hh];
        }
    }
    if (tid < NH * 32) {
        int hh = tid >> 5, ln = tid & 31;
        float mv = -3e38f;
        for (int r = ln; r < 128; r += 32) mv = fmaxf(mv, ed_s[r * NH + hh]);
#pragma unroll
        for (int o = 16; o; o >>= 1) mv = fmaxf(mv, __shfl_xor_sync(0xffffffffu, mv, o));
        if (ln == 0) {
            int ghead = (PROJF == 128) ? blockIdx.y : hh;
            atomicMax(&menc[ghead], enc_f(mv));
        }
    }
    {
        int c = tid & 127;
        int plane = tid >> 7;
        const uint32_t* src = (const uint32_t*)((plane ? loPlane : hiPlane) + c * PR);
        uint32_t* dst = (uint32_t*)((plane ? HtLo : HtHi) + (size_t)(c0 + c) * NN + row0);
#pragma unroll
        for (int i = 0; i < 64; i++) dst[i] = src[i];
    }
}

// ---------------------------------------------------------------------------
// Plain split-bf16 tensor GEMM (+bias): C = A @ BT^T. BM=128, BK=64.
// ---------------------------------------------------------------------------
template <int BN>
__global__ void __launch_bounds__(256, 1)
gemm_mma(const u16* __restrict__ Ahi, const u16* __restrict__ Alo,
         const u16* __restrict__ Bthi, const u16* __restrict__ Btlo,
         const float* __restrict__ bias, float* __restrict__ C,
         int M, int K, int Nc) {
    constexpr int BM = 128, BK = 64;
    constexpr uint32_t ROWB = 144;
    constexpr uint32_t ABYTES = BM * ROWB;
    constexpr uint32_t BBYTES = (uint32_t)BN * ROWB;
    constexpr uint32_t STAGE = 2 * ABYTES + 2 * BBYTES;
    constexpr int NT = BN / 16;

    extern __shared__ __align__(16) char dsm[];
    uint32_t sb = smem_u32(dsm);

    int tid = threadIdx.x, wid = tid >> 5, lane = tid & 31;
    int m0w = (wid >> 1) * 32;
    int n0w = (wid & 1) * (BN / 2);
    int row0 = blockIdx.x * BM;
    int c0 = blockIdx.y * BN;

    float acc[2][NT][4];
#pragma unroll
    for (int mi = 0; mi < 2; mi++)
#pragma unroll
        for (int nt = 0; nt < NT; nt++)
#pragma unroll
            for (int q = 0; q < 4; q++) acc[mi][nt][q] = 0.f;

    uint32_t pA = (uint32_t)(m0w + (lane & 15)) * ROWB + (uint32_t)((lane >> 4) << 4);
    uint32_t pB = (uint32_t)(((lane >> 4) << 3) + (lane & 7) + n0w) * ROWB +
                  (uint32_t)(((lane >> 3) & 1) << 4);

    const int KT = K / BK;

    auto load_tiles = [&](int kt, int s) {
        uint32_t base = sb + (uint32_t)s * STAGE;
        const char* gah = (const char*)(Ahi + (size_t)row0 * K + kt * BK);
        const char* gal = (const char*)(Alo + (size_t)row0 * K + kt * BK);
        const char* gbh = (const char*)(Bthi + (size_t)c0 * K + kt * BK);
        const char* gbl = (const char*)(Btlo + (size_t)c0 * K + kt * BK);
#pragma unroll
        for (int v = tid; v < BM * 8; v += 256) {
            int r = v >> 3;
            uint32_t c = (uint32_t)(v & 7) << 4;
            uint32_t so = (uint32_t)r * ROWB + c;
            size_t go = (size_t)r * K * 2 + c;
            CP_ASYNC16(base + so, gah + go);
            CP_ASYNC16(base + ABYTES + so, gal + go);
        }
#pragma unroll
        for (int v = tid; v < BN * 8; v += 256) {
            int r = v >> 3;
            uint32_t c = (uint32_t)(v & 7) << 4;
            uint32_t so = (uint32_t)r * ROWB + c;
            size_t go = (size_t)r * K * 2 + c;
            CP_ASYNC16(base + 2 * ABYTES + so, gbh + go);
            CP_ASYNC16(base + 2 * ABYTES + BBYTES + so, gbl + go);
        }
    };

    load_tiles(0, 0);
    CP_COMMIT();
    if (KT > 1) { load_tiles(1, 1); CP_COMMIT(); }

    for (int kt = 0; kt < KT; kt++) {
        int s = kt & 1;
        if (kt + 1 < KT) { CP_WAIT1(); } else { CP_WAIT0(); }
        __syncthreads();

        uint32_t bAhi = sb + (uint32_t)s * STAGE;
        uint32_t bAlo = bAhi + ABYTES;
        uint32_t bBhi = bAlo + ABYTES;
        uint32_t bBlo = bBhi + BBYTES;
#pragma unroll
        for (int kk = 0; kk < 4; kk++) {
            uint32_t ah[2][4], al[2][4];
#pragma unroll
            for (int mi = 0; mi < 2; mi++) {
                uint32_t o = pA + (uint32_t)mi * (16 * ROWB) + (uint32_t)kk * 32;
                ldsm_x4(ah[mi], bAhi + o);
                ldsm_x4(al[mi], bAlo + o);
            }
#pragma unroll
            for (int np = 0; np < NT / 2; np++) {
                uint32_t bo = pB + (uint32_t)np * (16 * ROWB) + (uint32_t)kk * 32;
                uint32_t bh[4], bl[4];
                ldsm_x4(bh, bBhi + bo);
                ldsm_x4(bl, bBlo + bo);
#pragma unroll
                for (int mi = 0; mi < 2; mi++) {
                    mma16816(acc[mi][np * 2], ah[mi], bh[0], bh[1]);
                    mma16816(acc[mi][np * 2], ah[mi], bl[0], bl[1]);
                    mma16816(acc[mi][np * 2], al[mi], bh[0], bh[1]);
                    mma16816(acc[mi][np * 2 + 1], ah[mi], bh[2], bh[3]);
                    mma16816(acc[mi][np * 2 + 1], ah[mi], bl[2], bl[3]);
                    mma16816(acc[mi][np * 2 + 1], al[mi], bh[2], bh[3]);
                }
            }
        }
        __syncthreads();
        if (kt + 2 < KT) { load_tiles(kt + 2, s); CP_COMMIT(); }
    }

    int g = lane >> 2, tg = lane & 3;
#pragma unroll
    for (int mi = 0; mi < 2; mi++) {
        int r0 = row0 + m0w + mi * 16 + g;
        int r1 = r0 + 8;
#pragma unroll
        for (int nt = 0; nt < NT; nt++) {
            int cn = c0 + n0w + nt * 8 + tg * 2;
            float b0 = bias ? bias[cn] : 0.f;
            float b1 = bias ? bias[cn + 1] : 0.f;
            *(float2*)(&C[(size_t)r0 * Nc + cn]) =
                make_float2(acc[mi][nt][0] + b0, acc[mi][nt][1] + b1);
            *(float2*)(&C[(size_t)r1 * Nc + cn]) =
                make_float2(acc[mi][nt][2] + b0, acc[mi][nt][3] + b1);
        }
    }
}

// ---------------------------------------------------------------------------
// fp32 fallback GEMM for the tiny final layer
// ---------------------------------------------------------------------------
template <int BN, int TM, int TN>
__global__ void gemm_bias_kernel(const float* __restrict__ A,
                                 const float* __restrict__ B,
                                 const float* __restrict__ bias,
                                 float* __restrict__ C,
                                 int M, int K, int Nc) {
    const int BM = 64, BK = 32;
    __shared__ float sA[BK][BM + 4];
    __shared__ float sB[BK][BN + 4];
    int tid = threadIdx.x;
    const int CT = BN / TN;
    int tx = tid % CT, ty = tid / CT;
    int row0 = blockIdx.x * BM, c0 = blockIdx.y * BN;

    float acc[TM][TN];
#pragma unroll
    for (int i = 0; i < TM; i++)
#pragma unroll
        for (int j = 0; j < TN; j++) acc[i][j] = 0.f;

    for (int k0 = 0; k0 < K; k0 += BK) {
        __syncthreads();
        for (int v = tid; v < BM * BK / 4; v += 256) {
            int idx = v * 4;
            int r = idx >> 5, kk = idx & 31;
            float4 f = *reinterpret_cast<const float4*>(&A[(size_t)(row0 + r) * K + k0 + kk]);
            sA[kk + 0][r] = f.x; sA[kk + 1][r] = f.y;
            sA[kk + 2][r] = f.z; sA[kk + 3][r] = f.w;
        }
        for (int v = tid; v < BK * BN / 4; v += 256) {
            int idx = v * 4;
            int kk = idx / BN, c = idx % BN;
            float4 f = *reinterpret_cast<const float4*>(&B[(size_t)(k0 + kk) * Nc + c0 + c]);
            *reinterpret_cast<float4*>(&sB[kk][c]) = f;
        }
        __syncthreads();
#pragma unroll
        for (int kk = 0; kk < BK; kk++) {
            float a[TM], b[TN];
#pragma unroll
            for (int i = 0; i < TM; i++) a[i] = sA[kk][ty * TM + i];
#pragma unroll
            for (int j = 0; j < TN; j++) b[j] = sB[kk][tx * TN + j];
#pragma unroll
            for (int i = 0; i < TM; i++)
#pragma unroll
                for (int j = 0; j < TN; j++) acc[i][j] = fmaf(a[i], b[j], acc[i][j]);
        }
    }
#pragma unroll
    for (int j = 0; j < TN; j++) {
        int c = c0 + tx * TN + j;
        float bv = bias ? bias[c] : 0.f;
#pragma unroll
        for (int i = 0; i < TM; i++)
            C[(size_t)(row0 + ty * TM + i) * Nc + c] = acc[i][j] + bv;
    }
}

// ---------------------------------------------------------------------------
// Fused GAT attention via mma.sync bf16 (3-term split).
// BM=64 rows per block (grid = 64 x HH), 256 threads, 2 CTAs/SM.
// Warp tile: MT=1 (16 rows, wr=wid>>1), WC=2 (wc=wid&1), NT=F/16 n8-tiles.
// ---------------------------------------------------------------------------
template <int F>
__global__ void __launch_bounds__(256, 2)
gat_attn_mma(const u16* __restrict__ Bhi, const u16* __restrict__ Blo,
             const float* __restrict__ es, const float* __restrict__ ed,
             const unsigned* __restrict__ menc, float* __restrict__ Out,
             u16* __restrict__ OutHi, u16* __restrict__ OutLo) {
    constexpr int BM = 64;
    constexpr int KT = 64;
    constexpr int T = NN / KT;
    constexpr int NT = F / 16;                 // n8 tiles per warp
    constexpr uint32_t ROWB = 144;
    constexpr uint32_t PBYTES = BM * ROWB;     // 9216
    constexpr uint32_t HBYTES = (uint32_t)F * ROWB;

    extern __shared__ __align__(16) char dsm[];
    uint32_t sb = smem_u32(dsm);
    const uint32_t P0 = sb + 512;
    const uint32_t H0 = P0 + 4 * PBYTES;

    int tid = threadIdx.x;
    int wid = tid >> 5, lane = tid & 31;
    int h = blockIdx.y;
    int i0 = blockIdx.x * BM;

    int wr = wid >> 1, wc = wid & 1;
    int m0 = wr * 16;
    int n0 = wc * (NT * 8);

    uint32_t pA = (uint32_t)(m0 + (lane & 15)) * ROWB + ((lane >> 4) << 4);
    uint32_t pB = (uint32_t)(((lane >> 4) << 3) + (lane & 7)) * ROWB +
                  (((lane >> 3) & 1) << 4) + (uint32_t)n0 * ROWB;

    // p-gen: 4 threads per row, 16 j each
    int irow = tid >> 2;
    int jq = tid & 3;
    float esr = es[h * NN + i0 + irow];
    float zz = esr + dec_f(menc[h]);
    float mr = fmaxf(zz, 0.2f * zz);
    const float* edh = ed + h * NN;
    float psum = 0.f;
    uint32_t poff = (uint32_t)irow * ROWB + (uint32_t)jq * 32;

    float acc[NT][4];
#pragma unroll
    for (int nt = 0; nt < NT; nt++)
#pragma unroll
        for (int q = 0; q < 4; q++) acc[nt][q] = 0.f;

    auto load_H = [&](int t, int b) {
        const char* gh = (const char*)Bhi + ((size_t)h * F * NN + (size_t)t * KT) * 2;
        const char* gl = (const char*)Blo + ((size_t)h * F * NN + (size_t)t * KT) * 2;
        uint32_t dh = H0 + (uint32_t)b * HBYTES;
        uint32_t dl = H0 + (uint32_t)(2 + b) * HBYTES;
#pragma unroll
        for (int v = tid; v < F * 8; v += 256) {
            int f = v >> 3;
            uint32_t c = (uint32_t)(v & 7) << 4;
            uint32_t so = (uint32_t)f * ROWB + c;
            CP_ASYNC16(dh + so, gh + (size_t)f * NN * 2 + c);
            CP_ASYNC16(dl + so, gl + (size_t)f * NN * 2 + c);
        }
    };

    auto pgen = [&](int t, int b) {
        uint32_t dh = P0 + (uint32_t)b * PBYTES + poff;
        uint32_t dl = P0 + (uint32_t)(2 + b) * PBYTES + poff;
        unsigned w = g_adjbits[(size_t)(i0 + irow) * 128 + t * 2 + (jq >> 1)]
                     >> ((jq & 1) * 16);
        const float* edp = edh + t * KT + jq * 16;
#pragma unroll
        for (int jj = 0; jj < 16; jj += 8) {
            float4 e0 = __ldg((const float4*)(edp + jj));
            float4 e1 = __ldg((const float4*)(edp + jj + 4));
            float ee[8] = {e0.x, e0.y, e0.z, e0.w, e1.x, e1.y, e1.z, e1.w};
            uint32_t hbits[8], lbits[8];
#pragma unroll
            for (int u = 0; u < 8; u++) {
                float e = esr + ee[u];
                float lr = fmaxf(e, 0.2f * e);
                float p = __expf(lr - mr);
                p = ((w >> (jj + u)) & 1u) ? p : 0.f;
                psum += p;
                uint32_t pb = __float_as_uint(p);
                uint32_t hb = pb & 0xffff0000u;
                hbits[u] = hb;
                lbits[u] = __float_as_uint(p - __uint_as_float(hb));
            }
            uint4 hv, lv;
            hv.x = prmt7632(hbits[0], hbits[1]);
            hv.y = prmt7632(hbits[2], hbits[3]);
            hv.z = prmt7632(hbits[4], hbits[5]);
            hv.w = prmt7632(hbits[6], hbits[7]);
            lv.x = prmt7632(lbits[0], lbits[1]);
            lv.y = prmt7632(lbits[2], lbits[3]);
            lv.z = prmt7632(lbits[4], lbits[5]);
            lv.w = prmt7632(lbits[6], lbits[7]);
            asm volatile("st.shared.v4.b32 [%0], {%1,%2,%3,%4};"
                         :: "r"(dh + (uint32_t)jj * 2), "r"(hv.x), "r"(hv.y), "r"(hv.z), "r"(hv.w));
            asm volatile("st.shared.v4.b32 [%0], {%1,%2,%3,%4};"
                         :: "r"(dl + (uint32_t)jj * 2), "r"(lv.x), "r"(lv.y), "r"(lv.z), "r"(lv.w));
        }
    };

    load_H(0, 0);
    CP_COMMIT();
    pgen(0, 0);
    CP_WAIT0();
    __syncthreads();

    for (int t = 0; t < T; t++) {
        int b = t & 1;
        if (t + 1 < T) { load_H(t + 1, b ^ 1); CP_COMMIT(); }

        uint32_t basePhi = P0 + (uint32_t)b * PBYTES;
        uint32_t basePlo = P0 + (uint32_t)(2 + b) * PBYTES;
        uint32_t baseHhi = H0 + (uint32_t)b * HBYTES;
        uint32_t baseHlo = H0 + (uint32_t)(2 + b) * HBYTES;
#pragma unroll
        for (int kk = 0; kk < 4; kk++) {
            uint32_t ah[4], al[4];
            uint32_t o = pA + (uint32_t)kk * 32;
            ldsm_x4(ah, basePhi + o);
            ldsm_x4(al, basePlo + o);
#pragma unroll
            for (int np = 0; np < NT / 2; np++) {
                uint32_t bo = pB + (uint32_t)np * (16 * ROWB) + (uint32_t)kk * 32;
                uint32_t bh[4], bl[4];
                ldsm_x4(bh, baseHhi + bo);
                ldsm_x4(bl, baseHlo + bo);
                mma16816(acc[np * 2], ah, bh[0], bh[1]);
                mma16816(acc[np * 2], ah, bl[0], bl[1]);
                mma16816(acc[np * 2], al, bh[0], bh[1]);
                mma16816(acc[np * 2 + 1], ah, bh[2], bh[3]);
                mma16816(acc[np * 2 + 1], ah, bl[2], bl[3]);
                mma16816(acc[np * 2 + 1], al, bh[2], bh[3]);
            }
        }

        if (t + 1 < T) pgen(t + 1, b ^ 1);
        CP_WAIT0();
        __syncthreads();
    }

    // row sums: reduce over the 4 threads of each row
    float tot = psum;
    tot += __shfl_xor_sync(0xffffffffu, tot, 1);
    tot += __shfl_xor_sync(0xffffffffu, tot, 2);
    if (jq == 0) *(float*)(dsm + 4 * irow) = tot;
    __syncthreads();

    // epilogue
    int g = lane >> 2, tg = lane & 3;
    {
        int r0 = m0 + g;
        int r1 = r0 + 8;
        float rinv0 = 1.f / *(const float*)(dsm + 4 * r0);
        float rinv1 = 1.f / *(const float*)(dsm + 4 * r1);
        size_t o0 = (size_t)(i0 + r0) * (HH * F) + h * F;
        size_t o1 = (size_t)(i0 + r1) * (HH * F) + h * F;
#pragma unroll
        for (int nt = 0; nt < NT; nt++) {
            int cn = n0 + nt * 8 + tg * 2;
            float2 v0 = make_float2(acc[nt][0] * rinv0, acc[nt][1] * rinv0);
            float2 v1 = make_float2(acc[nt][2] * rinv1, acc[nt][3] * rinv1);
            if (Out) {
                *(float2*)(Out + o0 + cn) = v0;
                *(float2*)(Out + o1 + cn) = v1;
            }
            if (OutHi) {
                uint32_t hh, ll;
                pack_split(v0.x, v0.y, hh, ll);
                *(uint32_t*)(OutHi + o0 + cn) = hh;
                *(uint32_t*)(OutLo + o0 + cn) = ll;
                pack_split(v1.x, v1.y, hh, ll);
                *(uint32_t*)(OutHi + o1 + cn) = hh;
                *(uint32_t*)(OutLo + o1 + cn) = ll;
            }
        }
    }
}

// ---------------------------------------------------------------------------
// BatchNorm + ELU (optional fp32 / split outputs)
// ---------------------------------------------------------------------------
__global__ void bn_elu_kernel(const float* __restrict__ Y,
                              const float* __restrict__ gamma,
                              const float* __restrict__ beta,
                              float* __restrict__ Out,
                              u16* __restrict__ OutHi, u16* __restrict__ OutLo,
                              int C) {
    int c = blockIdx.x;
    float s1 = 0.f, s2 = 0.f;
    for (int i = threadIdx.x; i < NN; i += 256) {
        float v = Y[(size_t)i * C + c];
        s1 += v;
        s2 += v * v;
    }
    __shared__ float r1[256], r2[256];
    r1[threadIdx.x] = s1; r2[threadIdx.x] = s2;
    __syncthreads();
    for (int s = 128; s; s >>= 1) {
        if (threadIdx.x < s) {
            r1[threadIdx.x] += r1[threadIdx.x + s];
            r2[threadIdx.x] += r2[threadIdx.x + s];
        }
        __syncthreads();
    }
    float mean = r1[0] * (1.f / NN);
    float var = r2[0] * (1.f / NN) - mean * mean;
    float inv = rsqrtf(var + 1e-5f);
    float g = gamma[c], b = beta[c];
    for (int i = threadIdx.x; i < NN; i += 256) {
        float v = Y[(size_t)i * C + c];
        float z = (v - mean) * inv * g + b;
        float o = z > 0.f ? z : (__expf(z) - 1.f);
        if (Out) Out[(size_t)i * C + c] = o;
        if (OutHi) {
            uint32_t ob = __float_as_uint(o);
            uint32_t hb = ob & 0xffff0000u;
            float lv = o - __uint_as_float(hb);
            OutHi[(size_t)i * C + c] = (u16)(hb >> 16);
            OutLo[(size_t)i * C + c] = (u16)(__float_as_uint(lv) >> 16);
        }
    }
}

// ---------------------------------------------------------------------------
extern "C" void kernel_launch(void* const* d_in, const int* in_sizes, int n_in,
                              void* d_out, int out_size) {
    const float* x   = (const float*)d_in[0];
    const int*   adj = (const int*)d_in[1];
    const float* W1  = (const float*)d_in[2];
    const float* a1s = (const float*)d_in[3];
    const float* a1d = (const float*)d_in[4];
    const float* lw1 = (const float*)d_in[5];
    const float* lb1 = (const float*)d_in[6];
    const float* g1  = (const float*)d_in[7];
    const float* be1 = (const float*)d_in[8];
    const float* W2  = (const float*)d_in[9];
    const float* a2s = (const float*)d_in[10];
    const float* a2d = (const float*)d_in[11];
    const float* lw2 = (const float*)d_in[12];
    const float* lb2 = (const float*)d_in[13];
    const float* g2  = (const float*)d_in[14];
    const float* be2 = (const float*)d_in[15];
    float* out = (float*)d_out;

    float *p_es1, *p_ed1, *p_es2, *p_ed2, *p_y1, *p_x3, *p_y2;
    unsigned *p_mx1e, *p_mx2e;
    u16 *p_t1h, *p_t1l, *p_t2h, *p_t2l;
    u16 *p_xhi, *p_xlo, *p_x1hi, *p_x1lo, *p_x2hi, *p_x2lo;
    u16 *p_w1th, *p_w1tl, *p_lw1th, *p_lw1tl, *p_w2th, *p_w2tl;
    cudaGetSymbolAddress((void**)&p_es1, g_es1);
    cudaGetSymbolAddress((void**)&p_ed1, g_ed1);
    cudaGetSymbolAddress((void**)&p_es2, g_es2);
    cudaGetSymbolAddress((void**)&p_ed2, g_ed2);
    cudaGetSymbolAddress((void**)&p_mx1e, g_mx1e);
    cudaGetSymbolAddress((void**)&p_mx2e, g_mx2e);
    cudaGetSymbolAddress((void**)&p_y1, g_y1);
    cudaGetSymbolAddress((void**)&p_x3, g_x3);
    cudaGetSymbolAddress((void**)&p_y2, g_y2);
    cudaGetSymbolAddress((void**)&p_t1h, g_ht1_hi);
    cudaGetSymbolAddress((void**)&p_t1l, g_ht1_lo);
    cudaGetSymbolAddress((void**)&p_t2h, g_ht2_hi);
    cudaGetSymbolAddress((void**)&p_t2l, g_ht2_lo);
    cudaGetSymbolAddress((void**)&p_xhi, g_xhi);
    cudaGetSymbolAddress((void**)&p_xlo, g_xlo);
    cudaGetSymbolAddress((void**)&p_x1hi, g_x1hi);
    cudaGetSymbolAddress((void**)&p_x1lo, g_x1lo);
    cudaGetSymbolAddress((void**)&p_x2hi, g_x2hi);
    cudaGetSymbolAddress((void**)&p_x2lo, g_x2lo);
    cudaGetSymbolAddress((void**)&p_w1th, g_w1thi);
    cudaGetSymbolAddress((void**)&p_w1tl, g_w1tlo);
    cudaGetSymbolAddress((void**)&p_lw1th, g_lw1thi);
    cudaGetSymbolAddress((void**)&p_lw1tl, g_lw1tlo);
    cudaGetSymbolAddress((void**)&p_w2th, g_w2thi);
    cudaGetSymbolAddress((void**)&p_w2tl, g_w2tlo);

    const int SMEM1 = 512 + 4 * (64 * 144) + 4 * (128 * 144);   // 111104
    const int SMEM2 = 512 + 4 * (64 * 144) + 4 * (32 * 144);    // 55808
    const int SMEMG128 = 2 * (2 * 128 * 144 + 2 * 128 * 144);
    const int SMEMG64  = 2 * (2 * 128 * 144 + 2 * 64 * 144);
    cudaFuncSetAttribute(gat_attn_mma<128>, cudaFuncAttributeMaxDynamicSharedMemorySize, SMEM1);
    cudaFuncSetAttribute(gat_attn_mma<32>,  cudaFuncAttributeMaxDynamicSharedMemorySize, SMEM2);
    cudaFuncSetAttribute(gemm_h_fused<128>, cudaFuncAttributeMaxDynamicSharedMemorySize, SMEMG128);
    cudaFuncSetAttribute(gemm_h_fused<32>,  cudaFuncAttributeMaxDynamicSharedMemorySize, SMEMG128);
    cudaFuncSetAttribute(gemm_mma<64>,  cudaFuncAttributeMaxDynamicSharedMemorySize, SMEMG64);

    // 1) adjacency bitmask + max-encoder init
    pack_adj_kernel<<<NN * 128 / 8, 256>>>(adj);
    // 2) fused prep: split x, transpose-split W1 / lw1 / W2
    prep_kernel<<<2344, dim3(32, 8)>>>(x, W1, lw1, W2);
    // 3) h1 GEMM fused: transposed split ht1 + es1/ed1 + max encoders
    gemm_h_fused<128><<<dim3(32, 4), 256, SMEMG128>>>(
        p_xhi, p_xlo, p_w1th, p_w1tl, a1s, a1d, p_es1, p_ed1, p_mx1e,
        p_t1h, p_t1l, 512);
    // 4) layer-1 attention -> x1 split only   [PROFILED LAUNCH]
    gat_attn_mma<128><<<dim3(64, HH), 256, SMEM1>>>(
        p_t1h, p_t1l, p_es1, p_ed1, p_mx1e, nullptr, p_x1hi, p_x1lo);
    // 5) y1 = x1 @ lw1 + lb1
    gemm_mma<64><<<dim3(32, 1), 256, SMEMG64>>>(p_x1hi, p_x1lo, p_lw1th, p_lw1tl,
                                                lb1, p_y1, NN, 512, 64);
    // 6) x2 = BN_ELU(y1), split only
    bn_elu_kernel<<<64, 256>>>(p_y1, g1, be1, nullptr, p_x2hi, p_x2lo, 64);
    // 7) h2 GEMM fused: ht2 + es2/ed2 + max encoders
    gemm_h_fused<32><<<dim3(32, 1), 256, SMEMG128>>>(
        p_x2hi, p_x2lo, p_w2th, p_w2tl, a2s, a2d, p_es2, p_ed2, p_mx2e,
        p_t2h, p_t2l, 64);
    // 8) layer-2 attention -> x3 fp32
    gat_attn_mma<32><<<dim3(64, HH), 256, SMEM2>>>(
        p_t2h, p_t2l, p_es2, p_ed2, p_mx2e, p_x3, nullptr, nullptr);
    // 9) final tiny layer
    gemm_bias_kernel<16, 4, 1><<<dim3(64, 1), 256>>>(p_x3, lw2, lb2, p_y2, NN, 128, 16);
    // 10) out
    bn_elu_kernel<<<16, 256>>>(p_y2, g2, be2, out, nullptr, nullptr, 16);
}

// round 10
// speedup vs baseline: 2.7185x; 1.0338x over previous
#include <cuda_runtime.h>
#include <cuda_bf16.h>
#include <cstdint>

#define NN 4096
#define HH 4
typedef unsigned short u16;

// ---------------------------------------------------------------------------
// scratch (static device allocations only)
// ---------------------------------------------------------------------------
__device__ unsigned g_adjbits[NN * 128];
__device__ float g_es1[HH * NN], g_ed1[HH * NN];
__device__ float g_es2[HH * NN], g_ed2[HH * NN];
__device__ unsigned g_mx1e[HH], g_mx2e[HH];
__device__ float g_y1[NN * 64];
__device__ float g_x3[NN * 128];
__device__ float g_y2[NN * 16];
// split-j attention accumulators + psums
__device__ float g_x1acc[2 * NN * 512];
__device__ float g_ps1[2 * HH * NN];
__device__ float g_x3acc[2 * NN * 128];
__device__ float g_ps2[2 * HH * NN];
// transposed split-bf16 feature matrices: [HF][NN]
__device__ u16 g_ht1_hi[512 * NN], g_ht1_lo[512 * NN];
__device__ u16 g_ht2_hi[128 * NN], g_ht2_lo[128 * NN];
// split activations (row-major, K-contig for GEMM A side)
__device__ u16 g_xhi[NN * 512], g_xlo[NN * 512];
__device__ u16 g_x1hi[NN * 512], g_x1lo[NN * 512];
__device__ u16 g_x2hi[NN * 64], g_x2lo[NN * 64];
// split transposed weights [N][K]
__device__ u16 g_w1thi[512 * 512], g_w1tlo[512 * 512];
__device__ u16 g_lw1thi[64 * 512], g_lw1tlo[64 * 512];
__device__ u16 g_w2thi[128 * 64], g_w2tlo[128 * 64];

// ---------------------------------------------------------------------------
// helpers
// ---------------------------------------------------------------------------
__device__ __forceinline__ uint32_t smem_u32(const void* p) {
    uint32_t a;
    asm("{ .reg .u64 t; cvta.to.shared.u64 t, %1; cvt.u32.u64 %0, t; }"
        : "=r"(a) : "l"(p));
    return a;
}
__device__ __forceinline__ uint32_t prmt7632(uint32_t a, uint32_t b) {
    uint32_t r;
    asm("prmt.b32 %0, %1, %2, 0x7632;" : "=r"(r) : "r"(a), "r"(b));
    return r;
}
__device__ __forceinline__ unsigned enc_f(float f) {
    unsigned b = __float_as_uint(f);
    return (b & 0x80000000u) ? ~b : (b | 0x80000000u);
}
__device__ __forceinline__ float dec_f(unsigned k) {
    unsigned b = (k & 0x80000000u) ? (k & 0x7fffffffu) : ~k;
    return __uint_as_float(b);
}
__device__ __forceinline__ void split1(float v, u16& h, u16& l) {
    uint32_t b = __float_as_uint(v);
    uint32_t hb = b & 0xffff0000u;
    h = (u16)(hb >> 16);
    l = (u16)(__float_as_uint(v - __uint_as_float(hb)) >> 16);
}

#define CP_ASYNC16(saddr, gptr) \
    asm volatile("cp.async.cg.shared.global [%0], [%1], 16;" \
                 :: "r"((uint32_t)(saddr)), "l"(gptr))
#define CP_COMMIT() asm volatile("cp.async.commit_group;" ::: "memory")
#define CP_WAIT0()  asm volatile("cp.async.wait_group 0;" ::: "memory")
#define CP_WAIT1()  asm volatile("cp.async.wait_group 1;" ::: "memory")

__device__ __forceinline__ void ldsm_x4(uint32_t* r, uint32_t addr) {
    asm volatile("ldmatrix.sync.aligned.m8n8.x4.shared.b16 {%0,%1,%2,%3}, [%4];"
                 : "=r"(r[0]), "=r"(r[1]), "=r"(r[2]), "=r"(r[3]) : "r"(addr));
}
__device__ __forceinline__ void mma16816(float* c, const uint32_t* a,
                                         uint32_t b0, uint32_t b1) {
    asm volatile(
        "mma.sync.aligned.m16n8k16.row.col.f32.bf16.bf16.f32 "
        "{%0,%1,%2,%3}, {%4,%5,%6,%7}, {%8,%9}, {%0,%1,%2,%3};"
        : "+f"(c[0]), "+f"(c[1]), "+f"(c[2]), "+f"(c[3])
        : "r"(a[0]), "r"(a[1]), "r"(a[2]), "r"(a[3]), "r"(b0), "r"(b1));
}
__device__ __forceinline__ void pack_split(float a, float b,
                                           uint32_t& h, uint32_t& l) {
    uint32_t ab = __float_as_uint(a), bb = __float_as_uint(b);
    float la = a - __uint_as_float(ab & 0xffff0000u);
    float lb = b - __uint_as_float(bb & 0xffff0000u);
    h = prmt7632(ab, bb);
    l = prmt7632(__float_as_uint(la), __float_as_uint(lb));
}

// ---------------------------------------------------------------------------
// launch 1: adj -> bitmask; also init the max-encoders
// ---------------------------------------------------------------------------
__global__ void pack_adj_kernel(const int* __restrict__ adj) {
    if (blockIdx.x == 0 && threadIdx.x < 2 * HH) {
        if (threadIdx.x < HH) g_mx1e[threadIdx.x] = 0u;
        else                  g_mx2e[threadIdx.x - HH] = 0u;
    }
    int gw = blockIdx.x * 8 + (threadIdx.x >> 5);
    int lane = threadIdx.x & 31;
    int row = gw >> 7, word = gw & 127;
    int v = adj[(size_t)row * NN + word * 32 + lane];
    unsigned m = __ballot_sync(0xffffffffu, v > 0);
    if (lane == 0) g_adjbits[gw] = m;
}

// ---------------------------------------------------------------------------
// launch 2: fused prep — split x, transpose-split W1 / lw1 / W2
// ---------------------------------------------------------------------------
__device__ void tsp_tile(const float* __restrict__ A, u16* __restrict__ hi,
                         u16* __restrict__ lo, int R, int C, int bx, int by,
                         int tx, int ty) {
    __shared__ float tile[32][33];
    int j0 = bx * 32, c0 = by * 32;
    for (int r = ty; r < 32; r += 8)
        tile[r][tx] = A[(size_t)(j0 + r) * C + c0 + tx];
    __syncthreads();
    for (int r = ty; r < 32; r += 8) {
        float v = tile[tx][r];
        uint32_t b = __float_as_uint(v);
        uint32_t hb = b & 0xffff0000u;
        float lv = v - __uint_as_float(hb);
        size_t o = (size_t)(c0 + r) * R + j0 + tx;
        hi[o] = (u16)(hb >> 16);
        lo[o] = (u16)(__float_as_uint(lv) >> 16);
    }
}

__global__ void prep_kernel(const float* __restrict__ x,
                            const float* __restrict__ W1,
                            const float* __restrict__ lw1,
                            const float* __restrict__ W2) {
    int b = blockIdx.x;
    int tx = threadIdx.x, ty = threadIdx.y;
    int flat = ty * 32 + tx;
    if (b < 2048) {
        int i = b * 256 + flat;
        float4 v = ((const float4*)x)[i];
        uint32_t h0, l0, h1, l1;
        pack_split(v.x, v.y, h0, l0);
        pack_split(v.z, v.w, h1, l1);
        ((uint2*)g_xhi)[i] = make_uint2(h0, h1);
        ((uint2*)g_xlo)[i] = make_uint2(l0, l1);
    } else if (b < 2048 + 256) {
        int t = b - 2048;
        tsp_tile(W1, g_w1thi, g_w1tlo, 512, 512, t % 16, t / 16, tx, ty);
    } else if (b < 2048 + 256 + 32) {
        int t = b - 2304;
        tsp_tile(lw1, g_lw1thi, g_lw1tlo, 512, 64, t % 16, t / 16, tx, ty);
    } else {
        int t = b - 2336;
        tsp_tile(W2, g_w2thi, g_w2tlo, 64, 128, t % 2, t / 2, tx, ty);
    }
}

// ---------------------------------------------------------------------------
// Fused feature GEMM: h = A @ BT^T (3-term split bf16) with fused epilogue.
// ---------------------------------------------------------------------------
template <int PROJF>
__global__ void __launch_bounds__(256, 1)
gemm_h_fused(const u16* __restrict__ Ahi, const u16* __restrict__ Alo,
             const u16* __restrict__ Bthi, const u16* __restrict__ Btlo,
             const float* __restrict__ asrc, const float* __restrict__ adst,
             float* __restrict__ es, float* __restrict__ ed,
             unsigned* __restrict__ menc,
             u16* __restrict__ HtHi, u16* __restrict__ HtLo, int K) {
    constexpr int BM = 128, BN = 128, BK = 64;
    constexpr uint32_t ROWB = 144;
    constexpr uint32_t ABYTES = BM * ROWB;
    constexpr uint32_t BBYTES = BN * ROWB;
    constexpr uint32_t STAGE = 2 * ABYTES + 2 * BBYTES;
    constexpr int NT = BN / 16;
    constexpr int NH = (PROJF == 128) ? 1 : 4;
    constexpr int PH = (PROJF == 128) ? 1 : 2;
    constexpr int PR = 138;

    extern __shared__ __align__(16) char dsm[];
    uint32_t sb = smem_u32(dsm);

    int tid = threadIdx.x, wid = tid >> 5, lane = tid & 31;
    int m0w = (wid >> 1) * 32;
    int n0w = (wid & 1) * (BN / 2);
    int row0 = blockIdx.x * BM;
    int c0 = blockIdx.y * BN;

    float acc[2][NT][4];
#pragma unroll
    for (int mi = 0; mi < 2; mi++)
#pragma unroll
        for (int nt = 0; nt < NT; nt++)
#pragma unroll
            for (int q = 0; q < 4; q++) acc[mi][nt][q] = 0.f;

    uint32_t pA = (uint32_t)(m0w + (lane & 15)) * ROWB + (uint32_t)((lane >> 4) << 4);
    uint32_t pB = (uint32_t)(((lane >> 4) << 3) + (lane & 7) + n0w) * ROWB +
                  (uint32_t)(((lane >> 3) & 1) << 4);

    const int KT = K / BK;

    auto load_tiles = [&](int kt, int s) {
        uint32_t base = sb + (uint32_t)s * STAGE;
        const char* gah = (const char*)(Ahi + (size_t)row0 * K + kt * BK);
        const char* gal = (const char*)(Alo + (size_t)row0 * K + kt * BK);
        const char* gbh = (const char*)(Bthi + (size_t)c0 * K + kt * BK);
        const char* gbl = (const char*)(Btlo + (size_t)c0 * K + kt * BK);
#pragma unroll
        for (int v = tid; v < BM * 8; v += 256) {
            int r = v >> 3;
            uint32_t c = (uint32_t)(v & 7) << 4;
            uint32_t so = (uint32_t)r * ROWB + c;
            size_t go = (size_t)r * K * 2 + c;
            CP_ASYNC16(base + so, gah + go);
            CP_ASYNC16(base + ABYTES + so, gal + go);
        }
#pragma unroll
        for (int v = tid; v < BN * 8; v += 256) {
            int r = v >> 3;
            uint32_t c = (uint32_t)(v & 7) << 4;
            uint32_t so = (uint32_t)r * ROWB + c;
            size_t go = (size_t)r * K * 2 + c;
            CP_ASYNC16(base + 2 * ABYTES + so, gbh + go);
            CP_ASYNC16(base + 2 * ABYTES + BBYTES + so, gbl + go);
        }
    };

    load_tiles(0, 0);
    CP_COMMIT();
    if (KT > 1) { load_tiles(1, 1); CP_COMMIT(); }

    for (int kt = 0; kt < KT; kt++) {
        int s = kt & 1;
        if (kt + 1 < KT) { CP_WAIT1(); } else { CP_WAIT0(); }
        __syncthreads();

        uint32_t bAhi = sb + (uint32_t)s * STAGE;
        uint32_t bAlo = bAhi + ABYTES;
        uint32_t bBhi = bAlo + ABYTES;
        uint32_t bBlo = bBhi + BBYTES;
#pragma unroll
        for (int kk = 0; kk < 4; kk++) {
            uint32_t ah[2][4], al[2][4];
#pragma unroll
            for (int mi = 0; mi < 2; mi++) {
                uint32_t o = pA + (uint32_t)mi * (16 * ROWB) + (uint32_t)kk * 32;
                ldsm_x4(ah[mi], bAhi + o);
                ldsm_x4(al[mi], bAlo + o);
            }
#pragma unroll
            for (int np = 0; np < NT / 2; np++) {
                uint32_t bo = pB + (uint32_t)np * (16 * ROWB) + (uint32_t)kk * 32;
                uint32_t bh[4], bl[4];
                ldsm_x4(bh, bBhi + bo);
                ldsm_x4(bl, bBlo + bo);
#pragma unroll
                for (int mi = 0; mi < 2; mi++) {
                    mma16816(acc[mi][np * 2], ah[mi], bh[0], bh[1]);
                    mma16816(acc[mi][np * 2], ah[mi], bl[0], bl[1]);
                    mma16816(acc[mi][np * 2], al[mi], bh[0], bh[1]);
                    mma16816(acc[mi][np * 2 + 1], ah[mi], bh[2], bh[3]);
                    mma16816(acc[mi][np * 2 + 1], ah[mi], bl[2], bl[3]);
                    mma16816(acc[mi][np * 2 + 1], al[mi], bh[2], bh[3]);
                }
            }
        }
        __syncthreads();
        if (kt + 2 < KT) { load_tiles(kt + 2, s); CP_COMMIT(); }
    }

    // ------------------ fused epilogue ------------------
    float* es_s = (float*)dsm;
    float* ed_s = es_s + 128 * NH;
    u16* hiPlane = (u16*)(ed_s + 128 * NH);
    u16* loPlane = hiPlane + 128 * PR;

    for (int i = tid; i < 128 * NH; i += 256) { es_s[i] = 0.f; ed_s[i] = 0.f; }
    __syncthreads();

    int g = lane >> 2, tg = lane & 3;
#pragma unroll
    for (int mi = 0; mi < 2; mi++) {
#pragma unroll
        for (int rp = 0; rp < 2; rp++) {
            int lr = m0w + mi * 16 + g + rp * 8;
            float esa[PH], eda[PH];
#pragma unroll
            for (int p = 0; p < PH; p++) { esa[p] = 0.f; eda[p] = 0.f; }
#pragma unroll
            for (int nt = 0; nt < NT; nt++) {
                int lc = n0w + nt * 8 + tg * 2;
                float a0 = acc[mi][nt][rp * 2 + 0];
                float a1 = acc[mi][nt][rp * 2 + 1];
                u16 h0, l0, h1, l1;
                split1(a0, h0, l0);
                split1(a1, h1, l1);
                hiPlane[lc * PR + lr] = h0;
                loPlane[lc * PR + lr] = l0;
                hiPlane[(lc + 1) * PR + lr] = h1;
                loPlane[(lc + 1) * PR + lr] = l1;
                int p = (PROJF == 128) ? 0 : (nt >> 2);
                float s0 = asrc[c0 + lc], s1 = asrc[c0 + lc + 1];
                float d0 = adst[c0 + lc], d1 = adst[c0 + lc + 1];
                esa[p] += a0 * s0 + a1 * s1;
                eda[p] += a0 * d0 + a1 * d1;
            }
#pragma unroll
            for (int p = 0; p < PH; p++) {
                int hh = (PROJF == 128) ? 0 : ((n0w >> 5) + p);
                atomicAdd(&es_s[lr * NH + hh], esa[p]);
                atomicAdd(&ed_s[lr * NH + hh], eda[p]);
            }
        }
    }
    __syncthreads();

    if (tid < 128) {
        int node = row0 + tid;
#pragma unroll
        for (int hh = 0; hh < NH; hh++) {
            int ghead = (PROJF == 128) ? blockIdx.y : hh;
            es[ghead * NN + node] = es_s[tid * NH + hh];
            ed[ghead * NN + node] = ed_s[tid * NH + hh];
        }
    }
    if (tid < NH * 32) {
        int hh = tid >> 5, ln = tid & 31;
        float mv = -3e38f;
        for (int r = ln; r < 128; r += 32) mv = fmaxf(mv, ed_s[r * NH + hh]);
#pragma unroll
        for (int o = 16; o; o >>= 1) mv = fmaxf(mv, __shfl_xor_sync(0xffffffffu, mv, o));
        if (ln == 0) {
            int ghead = (PROJF == 128) ? blockIdx.y : hh;
            atomicMax(&menc[ghead], enc_f(mv));
        }
    }
    {
        int c = tid & 127;
        int plane = tid >> 7;
        const uint32_t* src = (const uint32_t*)((plane ? loPlane : hiPlane) + c * PR);
        uint32_t* dst = (uint32_t*)((plane ? HtLo : HtHi) + (size_t)(c0 + c) * NN + row0);
#pragma unroll
        for (int i = 0; i < 64; i++) dst[i] = src[i];
    }
}

// ---------------------------------------------------------------------------
// Plain split-bf16 tensor GEMM (+bias): C = A @ BT^T. BM=128, BK=64.
// ---------------------------------------------------------------------------
template <int BN>
__global__ void __launch_bounds__(256, 1)
gemm_mma(const u16* __restrict__ Ahi, const u16* __restrict__ Alo,
         const u16* __restrict__ Bthi, const u16* __restrict__ Btlo,
         const float* __restrict__ bias, float* __restrict__ C,
         int M, int K, int Nc) {
    constexpr int BM = 128, BK = 64;
    constexpr uint32_t ROWB = 144;
    constexpr uint32_t ABYTES = BM * ROWB;
    constexpr uint32_t BBYTES = (uint32_t)BN * ROWB;
    constexpr uint32_t STAGE = 2 * ABYTES + 2 * BBYTES;
    constexpr int NT = BN / 16;

    extern __shared__ __align__(16) char dsm[];
    uint32_t sb = smem_u32(dsm);

    int tid = threadIdx.x, wid = tid >> 5, lane = tid & 31;
    int m0w = (wid >> 1) * 32;
    int n0w = (wid & 1) * (BN / 2);
    int row0 = blockIdx.x * BM;
    int c0 = blockIdx.y * BN;

    float acc[2][NT][4];
#pragma unroll
    for (int mi = 0; mi < 2; mi++)
#pragma unroll
        for (int nt = 0; nt < NT; nt++)
#pragma unroll
            for (int q = 0; q < 4; q++) acc[mi][nt][q] = 0.f;

    uint32_t pA = (uint32_t)(m0w + (lane & 15)) * ROWB + (uint32_t)((lane >> 4) << 4);
    uint32_t pB = (uint32_t)(((lane >> 4) << 3) + (lane & 7) + n0w) * ROWB +
                  (uint32_t)(((lane >> 3) & 1) << 4);

    const int KT = K / BK;

    auto load_tiles = [&](int kt, int s) {
        uint32_t base = sb + (uint32_t)s * STAGE;
        const char* gah = (const char*)(Ahi + (size_t)row0 * K + kt * BK);
        const char* gal = (const char*)(Alo + (size_t)row0 * K + kt * BK);
        const char* gbh = (const char*)(Bthi + (size_t)c0 * K + kt * BK);
        const char* gbl = (const char*)(Btlo + (size_t)c0 * K + kt * BK);
#pragma unroll
        for (int v = tid; v < BM * 8; v += 256) {
            int r = v >> 3;
            uint32_t c = (uint32_t)(v & 7) << 4;
            uint32_t so = (uint32_t)r * ROWB + c;
            size_t go = (size_t)r * K * 2 + c;
            CP_ASYNC16(base + so, gah + go);
            CP_ASYNC16(base + ABYTES + so, gal + go);
        }
#pragma unroll
        for (int v = tid; v < BN * 8; v += 256) {
            int r = v >> 3;
            uint32_t c = (uint32_t)(v & 7) << 4;
            uint32_t so = (uint32_t)r * ROWB + c;
            size_t go = (size_t)r * K * 2 + c;
            CP_ASYNC16(base + 2 * ABYTES + so, gbh + go);
            CP_ASYNC16(base + 2 * ABYTES + BBYTES + so, gbl + go);
        }
    };

    load_tiles(0, 0);
    CP_COMMIT();
    if (KT > 1) { load_tiles(1, 1); CP_COMMIT(); }

    for (int kt = 0; kt < KT; kt++) {
        int s = kt & 1;
        if (kt + 1 < KT) { CP_WAIT1(); } else { CP_WAIT0(); }
        __syncthreads();

        uint32_t bAhi = sb + (uint32_t)s * STAGE;
        uint32_t bAlo = bAhi + ABYTES;
        uint32_t bBhi = bAlo + ABYTES;
        uint32_t bBlo = bBhi + BBYTES;
#pragma unroll
        for (int kk = 0; kk < 4; kk++) {
            uint32_t ah[2][4], al[2][4];
#pragma unroll
            for (int mi = 0; mi < 2; mi++) {
                uint32_t o = pA + (uint32_t)mi * (16 * ROWB) + (uint32_t)kk * 32;
                ldsm_x4(ah[mi], bAhi + o);
                ldsm_x4(al[mi], bAlo + o);
            }
#pragma unroll
            for (int np = 0; np < NT / 2; np++) {
                uint32_t bo = pB + (uint32_t)np * (16 * ROWB) + (uint32_t)kk * 32;
                uint32_t bh[4], bl[4];
                ldsm_x4(bh, bBhi + bo);
                ldsm_x4(bl, bBlo + bo);
#pragma unroll
                for (int mi = 0; mi < 2; mi++) {
                    mma16816(acc[mi][np * 2], ah[mi], bh[0], bh[1]);
                    mma16816(acc[mi][np * 2], ah[mi], bl[0], bl[1]);
                    mma16816(acc[mi][np * 2], al[mi], bh[0], bh[1]);
                    mma16816(acc[mi][np * 2 + 1], ah[mi], bh[2], bh[3]);
                    mma16816(acc[mi][np * 2 + 1], ah[mi], bl[2], bl[3]);
                    mma16816(acc[mi][np * 2 + 1], al[mi], bh[2], bh[3]);
                }
            }
        }
        __syncthreads();
        if (kt + 2 < KT) { load_tiles(kt + 2, s); CP_COMMIT(); }
    }

    int g = lane >> 2, tg = lane & 3;
#pragma unroll
    for (int mi = 0; mi < 2; mi++) {
        int r0 = row0 + m0w + mi * 16 + g;
        int r1 = r0 + 8;
#pragma unroll
        for (int nt = 0; nt < NT; nt++) {
            int cn = c0 + n0w + nt * 8 + tg * 2;
            float b0 = bias ? bias[cn] : 0.f;
            float b1 = bias ? bias[cn + 1] : 0.f;
            *(float2*)(&C[(size_t)r0 * Nc + cn]) =
                make_float2(acc[mi][nt][0] + b0, acc[mi][nt][1] + b1);
            *(float2*)(&C[(size_t)r1 * Nc + cn]) =
                make_float2(acc[mi][nt][2] + b0, acc[mi][nt][3] + b1);
        }
    }
}

// ---------------------------------------------------------------------------
// fp32 fallback GEMM for the tiny final layer
// ---------------------------------------------------------------------------
template <int BN, int TM, int TN>
__global__ void gemm_bias_kernel(const float* __restrict__ A,
                                 const float* __restrict__ B,
                                 const float* __restrict__ bias,
                                 float* __restrict__ C,
                                 int M, int K, int Nc) {
    const int BM = 64, BK = 32;
    __shared__ float sA[BK][BM + 4];
    __shared__ float sB[BK][BN + 4];
    int tid = threadIdx.x;
    const int CT = BN / TN;
    int tx = tid % CT, ty = tid / CT;
    int row0 = blockIdx.x * BM, c0 = blockIdx.y * BN;

    float acc[TM][TN];
#pragma unroll
    for (int i = 0; i < TM; i++)
#pragma unroll
        for (int j = 0; j < TN; j++) acc[i][j] = 0.f;

    for (int k0 = 0; k0 < K; k0 += BK) {
        __syncthreads();
        for (int v = tid; v < BM * BK / 4; v += 256) {
            int idx = v * 4;
            int r = idx >> 5, kk = idx & 31;
            float4 f = *reinterpret_cast<const float4*>(&A[(size_t)(row0 + r) * K + k0 + kk]);
            sA[kk + 0][r] = f.x; sA[kk + 1][r] = f.y;
            sA[kk + 2][r] = f.z; sA[kk + 3][r] = f.w;
        }
        for (int v = tid; v < BK * BN / 4; v += 256) {
            int idx = v * 4;
            int kk = idx / BN, c = idx % BN;
            float4 f = *reinterpret_cast<const float4*>(&B[(size_t)(k0 + kk) * Nc + c0 + c]);
            *reinterpret_cast<float4*>(&sB[kk][c]) = f;
        }
        __syncthreads();
#pragma unroll
        for (int kk = 0; kk < BK; kk++) {
            float a[TM], b[TN];
#pragma unroll
            for (int i = 0; i < TM; i++) a[i] = sA[kk][ty * TM + i];
#pragma unroll
            for (int j = 0; j < TN; j++) b[j] = sB[kk][tx * TN + j];
#pragma unroll
            for (int i = 0; i < TM; i++)
#pragma unroll
                for (int j = 0; j < TN; j++) acc[i][j] = fmaf(a[i], b[j], acc[i][j]);
        }
    }
#pragma unroll
    for (int j = 0; j < TN; j++) {
        int c = c0 + tx * TN + j;
        float bv = bias ? bias[c] : 0.f;
#pragma unroll
        for (int i = 0; i < TM; i++)
            C[(size_t)(row0 + ty * TM + i) * Nc + c] = acc[i][j] + bv;
    }
}

// ---------------------------------------------------------------------------
// Fused GAT attention via mma.sync bf16 (3-term split).
// BM=128, KT=32, split-j: grid = (32, HH, 2); 2 CTAs/SM; MT=2, WC=2, NT=F/16.
// Writes UNNORMALIZED accumulator + per-half psum; combine kernel finishes.
// ---------------------------------------------------------------------------
template <int F>
__global__ void __launch_bounds__(256, 2)
gat_attn_mma(const u16* __restrict__ Bhi, const u16* __restrict__ Blo,
             const float* __restrict__ es, const float* __restrict__ ed,
             const unsigned* __restrict__ menc,
             float* __restrict__ OutAcc,     // [2][NN][HH*F]
             float* __restrict__ Ps) {       // [2][HH][NN]
    constexpr int BM = 128;
    constexpr int KT = 32;
    constexpr int JH = NN / 2;                 // j per half
    constexpr int T = JH / KT;                 // 64 tiles
    constexpr int NT = F / 16;                 // n8 tiles per warp
    constexpr uint32_t ROWB = 80;              // 32 j * 2B + 16 pad
    constexpr uint32_t PBYTES = BM * ROWB;     // 10240
    constexpr uint32_t HBYTES = (uint32_t)F * ROWB;

    extern __shared__ __align__(16) char dsm[];
    uint32_t sb = smem_u32(dsm);
    const uint32_t P0 = sb;
    const uint32_t H0 = P0 + 4 * PBYTES;

    int tid = threadIdx.x;
    int wid = tid >> 5, lane = tid & 31;
    int h = blockIdx.y;
    int i0 = blockIdx.x * BM;
    int half = blockIdx.z;
    int j0g = half * JH;

    OutAcc += (size_t)half * NN * (HH * F);
    Ps += (size_t)half * HH * NN;

    int wr = wid >> 1, wc = wid & 1;
    int m0 = wr * 32;
    int n0 = wc * (NT * 8);

    uint32_t pA = (uint32_t)(m0 + (lane & 15)) * ROWB + ((lane >> 4) << 4);
    uint32_t pB = (uint32_t)(((lane >> 4) << 3) + (lane & 7)) * ROWB +
                  (((lane >> 3) & 1) << 4) + (uint32_t)n0 * ROWB;

    // p-gen: 2 threads per row, 16 j each
    int irow = tid >> 1;
    int jhalf = tid & 1;
    float esr = es[h * NN + i0 + irow];
    float zz = esr + dec_f(menc[h]);
    float mr = fmaxf(zz, 0.2f * zz);
    const float* edh = ed + h * NN + j0g;
    float psum = 0.f;
    uint32_t poff = (uint32_t)irow * ROWB + (uint32_t)jhalf * 32;

    float acc[2][NT][4];
#pragma unroll
    for (int mi = 0; mi < 2; mi++)
#pragma unroll
        for (int nt = 0; nt < NT; nt++)
#pragma unroll
            for (int q = 0; q < 4; q++) acc[mi][nt][q] = 0.f;

    auto load_H = [&](int t, int b) {
        const char* gh = (const char*)Bhi + ((size_t)h * F * NN + j0g + (size_t)t * KT) * 2;
        const char* gl = (const char*)Blo + ((size_t)h * F * NN + j0g + (size_t)t * KT) * 2;
        uint32_t dh = H0 + (uint32_t)b * HBYTES;
        uint32_t dl = H0 + (uint32_t)(2 + b) * HBYTES;
#pragma unroll
        for (int v = tid; v < F * 4; v += 256) {
            int f = v >> 2;
            uint32_t c = (uint32_t)(v & 3) << 4;
            uint32_t so = (uint32_t)f * ROWB + c;
            CP_ASYNC16(dh + so, gh + (size_t)f * NN * 2 + c);
            CP_ASYNC16(dl + so, gl + (size_t)f * NN * 2 + c);
        }
    };

    auto pgen = [&](int t, int b) {
        uint32_t dh = P0 + (uint32_t)b * PBYTES + poff;
        uint32_t dl = P0 + (uint32_t)(2 + b) * PBYTES + poff;
        unsigned w = g_adjbits[(size_t)(i0 + irow) * 128 + half * (JH / 32) + t]
                     >> (jhalf * 16);
        const float* edp = edh + t * KT + jhalf * 16;
#pragma unroll
        for (int jj = 0; jj < 16; jj += 8) {
            float4 e0 = __ldg((const float4*)(edp + jj));
            float4 e1 = __ldg((const float4*)(edp + jj + 4));
            float ee[8] = {e0.x, e0.y, e0.z, e0.w, e1.x, e1.y, e1.z, e1.w};
            uint32_t hbits[8], lbits[8];
#pragma unroll
            for (int u = 0; u < 8; u++) {
                float e = esr + ee[u];
                float lr = fmaxf(e, 0.2f * e);
                float p = __expf(lr - mr);
                p = ((w >> (jj + u)) & 1u) ? p : 0.f;
                psum += p;
                uint32_t pb = __float_as_uint(p);
                uint32_t hb = pb & 0xffff0000u;
                hbits[u] = hb;
                lbits[u] = __float_as_uint(p - __uint_as_float(hb));
            }
            uint4 hv, lv;
            hv.x = prmt7632(hbits[0], hbits[1]);
            hv.y = prmt7632(hbits[2], hbits[3]);
            hv.z = prmt7632(hbits[4], hbits[5]);
            hv.w = prmt7632(hbits[6], hbits[7]);
            lv.x = prmt7632(lbits[0], lbits[1]);
            lv.y = prmt7632(lbits[2], lbits[3]);
            lv.z = prmt7632(lbits[4], lbits[5]);
            lv.w = prmt7632(lbits[6], lbits[7]);
            asm volatile("st.shared.v4.b32 [%0], {%1,%2,%3,%4};"
                         :: "r"(dh + (uint32_t)jj * 2), "r"(hv.x), "r"(hv.y), "r"(hv.z), "r"(hv.w));
            asm volatile("st.shared.v4.b32 [%0], {%1,%2,%3,%4};"
                         :: "r"(dl + (uint32_t)jj * 2), "r"(lv.x), "r"(lv.y), "r"(lv.z), "r"(lv.w));
        }
    };

    load_H(0, 0);
    CP_COMMIT();
    pgen(0, 0);
    CP_WAIT0();
    __syncthreads();

    for (int t = 0; t < T; t++) {
        int b = t & 1;
        if (t + 1 < T) { load_H(t + 1, b ^ 1); CP_COMMIT(); }

        uint32_t basePhi = P0 + (uint32_t)b * PBYTES;
        uint32_t basePlo = P0 + (uint32_t)(2 + b) * PBYTES;
        uint32_t baseHhi = H0 + (uint32_t)b * HBYTES;
        uint32_t baseHlo = H0 + (uint32_t)(2 + b) * HBYTES;
#pragma unroll
        for (int kk = 0; kk < 2; kk++) {
            uint32_t ah[2][4], al[2][4];
#pragma unroll
            for (int mi = 0; mi < 2; mi++) {
                uint32_t o = pA + (uint32_t)mi * (16 * ROWB) + (uint32_t)kk * 32;
                ldsm_x4(ah[mi], basePhi + o);
                ldsm_x4(al[mi], basePlo + o);
            }
#pragma unroll
            for (int np = 0; np < NT / 2; np++) {
                uint32_t bo = pB + (uint32_t)np * (16 * ROWB) + (uint32_t)kk * 32;
                uint32_t bh[4], bl[4];
                ldsm_x4(bh, baseHhi + bo);
                ldsm_x4(bl, baseHlo + bo);
#pragma unroll
                for (int mi = 0; mi < 2; mi++) {
                    mma16816(acc[mi][np * 2], ah[mi], bh[0], bh[1]);
                    mma16816(acc[mi][np * 2], ah[mi], bl[0], bl[1]);
                    mma16816(acc[mi][np * 2], al[mi], bh[0], bh[1]);
                    mma16816(acc[mi][np * 2 + 1], ah[mi], bh[2], bh[3]);
                    mma16816(acc[mi][np * 2 + 1], ah[mi], bl[2], bl[3]);
                    mma16816(acc[mi][np * 2 + 1], al[mi], bh[2], bh[3]);
                }
            }
        }

        if (t + 1 < T) pgen(t + 1, b ^ 1);
        CP_WAIT0();
        __syncthreads();
    }

    // per-half psum (2 threads per row)
    float tot = psum + __shfl_xor_sync(0xffffffffu, psum, 1);
    if (jhalf == 0) Ps[h * NN + i0 + irow] = tot;

    // epilogue: raw accumulator store
    int g = lane >> 2, tg = lane & 3;
#pragma unroll
    for (int mi = 0; mi < 2; mi++) {
        int r0 = m0 + mi * 16 + g;
        int r1 = r0 + 8;
        size_t o0 = (size_t)(i0 + r0) * (HH * F) + h * F;
        size_t o1 = (size_t)(i0 + r1) * (HH * F) + h * F;
#pragma unroll
        for (int nt = 0; nt < NT; nt++) {
            int cn = n0 + nt * 8 + tg * 2;
            *(float2*)(OutAcc + o0 + cn) = make_float2(acc[mi][nt][0], acc[mi][nt][1]);
            *(float2*)(OutAcc + o1 + cn) = make_float2(acc[mi][nt][2], acc[mi][nt][3]);
        }
    }
}

// ---------------------------------------------------------------------------
// combine the two j-halves: out = (a0+a1)/(ps0+ps1); optional split / fp32 out
// ---------------------------------------------------------------------------
template <int F>
__global__ void combine_split_kernel(const float* __restrict__ A,   // [2][NN*HF]
                                     const float* __restrict__ ps,  // [2][HH*NN]
                                     u16* __restrict__ hi, u16* __restrict__ lo,
                                     float* __restrict__ outf) {
    constexpr int HF = HH * F;
    int i4 = blockIdx.x * 256 + threadIdx.x;
    int base = i4 * 4;
    int node = base / HF;
    int c = base - node * HF;
    int h = c / F;
    float4 a0 = ((const float4*)A)[i4];
    float4 a1 = ((const float4*)A)[NN * HF / 4 + i4];
    float rinv = 1.f / (ps[h * NN + node] + ps[HH * NN + h * NN + node]);
    float4 v;
    v.x = (a0.x + a1.x) * rinv;
    v.y = (a0.y + a1.y) * rinv;
    v.z = (a0.z + a1.z) * rinv;
    v.w = (a0.w + a1.w) * rinv;
    if (hi) {
        uint32_t h0, l0, h1, l1;
        pack_split(v.x, v.y, h0, l0);
        pack_split(v.z, v.w, h1, l1);
        ((uint2*)hi)[i4] = make_uint2(h0, h1);
        ((uint2*)lo)[i4] = make_uint2(l0, l1);
    }
    if (outf) ((float4*)outf)[i4] = v;
}

// ---------------------------------------------------------------------------
// BatchNorm + ELU (optional fp32 / split outputs)
// ---------------------------------------------------------------------------
__global__ void bn_elu_kernel(const float* __restrict__ Y,
                              const float* __restrict__ gamma,
                              const float* __restrict__ beta,
                              float* __restrict__ Out,
                              u16* __restrict__ OutHi, u16* __restrict__ OutLo,
                              int C) {
    int c = blockIdx.x;
    float s1 = 0.f, s2 = 0.f;
    for (int i = threadIdx.x; i < NN; i += 256) {
        float v = Y[(size_t)i * C + c];
        s1 += v;
        s2 += v * v;
    }
    __shared__ float r1[256], r2[256];
    r1[threadIdx.x] = s1; r2[threadIdx.x] = s2;
    __syncthreads();
    for (int s = 128; s; s >>= 1) {
        if (threadIdx.x < s) {
            r1[threadIdx.x] += r1[threadIdx.x + s];
            r2[threadIdx.x] += r2[threadIdx.x + s];
        }
        __syncthreads();
    }
    float mean = r1[0] * (1.f / NN);
    float var = r2[0] * (1.f / NN) - mean * mean;
    float inv = rsqrtf(var + 1e-5f);
    float g = gamma[c], b = beta[c];
    for (int i = threadIdx.x; i < NN; i += 256) {
        float v = Y[(size_t)i * C + c];
        float z = (v - mean) * inv * g + b;
        float o = z > 0.f ? z : (__expf(z) - 1.f);
        if (Out) Out[(size_t)i * C + c] = o;
        if (OutHi) {
            uint32_t ob = __float_as_uint(o);
            uint32_t hb = ob & 0xffff0000u;
            float lv = o - __uint_as_float(hb);
            OutHi[(size_t)i * C + c] = (u16)(hb >> 16);
            OutLo[(size_t)i * C + c] = (u16)(__float_as_uint(lv) >> 16);
        }
    }
}

// ---------------------------------------------------------------------------
extern "C" void kernel_launch(void* const* d_in, const int* in_sizes, int n_in,
                              void* d_out, int out_size) {
    const float* x   = (const float*)d_in[0];
    const int*   adj = (const int*)d_in[1];
    const float* W1  = (const float*)d_in[2];
    const float* a1s = (const float*)d_in[3];
    const float* a1d = (const float*)d_in[4];
    const float* lw1 = (const float*)d_in[5];
    const float* lb1 = (const float*)d_in[6];
    const float* g1  = (const float*)d_in[7];
    const float* be1 = (const float*)d_in[8];
    const float* W2  = (const float*)d_in[9];
    const float* a2s = (const float*)d_in[10];
    const float* a2d = (const float*)d_in[11];
    const float* lw2 = (const float*)d_in[12];
    const float* lb2 = (const float*)d_in[13];
    const float* g2  = (const float*)d_in[14];
    const float* be2 = (const float*)d_in[15];
    float* out = (float*)d_out;

    float *p_es1, *p_ed1, *p_es2, *p_ed2, *p_y1, *p_x3, *p_y2;
    float *p_x1acc, *p_ps1, *p_x3acc, *p_ps2;
    unsigned *p_mx1e, *p_mx2e;
    u16 *p_t1h, *p_t1l, *p_t2h, *p_t2l;
    u16 *p_xhi, *p_xlo, *p_x1hi, *p_x1lo, *p_x2hi, *p_x2lo;
    u16 *p_w1th, *p_w1tl, *p_lw1th, *p_lw1tl, *p_w2th, *p_w2tl;
    cudaGetSymbolAddress((void**)&p_es1, g_es1);
    cudaGetSymbolAddress((void**)&p_ed1, g_ed1);
    cudaGetSymbolAddress((void**)&p_es2, g_es2);
    cudaGetSymbolAddress((void**)&p_ed2, g_ed2);
    cudaGetSymbolAddress((void**)&p_mx1e, g_mx1e);
    cudaGetSymbolAddress((void**)&p_mx2e, g_mx2e);
    cudaGetSymbolAddress((void**)&p_y1, g_y1);
    cudaGetSymbolAddress((void**)&p_x3, g_x3);
    cudaGetSymbolAddress((void**)&p_y2, g_y2);
    cudaGetSymbolAddress((void**)&p_x1acc, g_x1acc);
    cudaGetSymbolAddress((void**)&p_ps1, g_ps1);
    cudaGetSymbolAddress((void**)&p_x3acc, g_x3acc);
    cudaGetSymbolAddress((void**)&p_ps2, g_ps2);
    cudaGetSymbolAddress((void**)&p_t1h, g_ht1_hi);
    cudaGetSymbolAddress((void**)&p_t1l, g_ht1_lo);
    cudaGetSymbolAddress((void**)&p_t2h, g_ht2_hi);
    cudaGetSymbolAddress((void**)&p_t2l, g_ht2_lo);
    cudaGetSymbolAddress((void**)&p_xhi, g_xhi);
    cudaGetSymbolAddress((void**)&p_xlo, g_xlo);
    cudaGetSymbolAddress((void**)&p_x1hi, g_x1hi);
    cudaGetSymbolAddress((void**)&p_x1lo, g_x1lo);
    cudaGetSymbolAddress((void**)&p_x2hi, g_x2hi);
    cudaGetSymbolAddress((void**)&p_x2lo, g_x2lo);
    cudaGetSymbolAddress((void**)&p_w1th, g_w1thi);
    cudaGetSymbolAddress((void**)&p_w1tl, g_w1tlo);
    cudaGetSymbolAddress((void**)&p_lw1th, g_lw1thi);
    cudaGetSymbolAddress((void**)&p_lw1tl, g_lw1tlo);
    cudaGetSymbolAddress((void**)&p_w2th, g_w2thi);
    cudaGetSymbolAddress((void**)&p_w2tl, g_w2tlo);

    const int SMEM1 = 4 * (128 * 80) + 4 * (128 * 80);   // 81920
    const int SMEM2 = 4 * (128 * 80) + 4 * (32 * 80);    // 51200
    const int SMEMG128 = 2 * (2 * 128 * 144 + 2 * 128 * 144);
    const int SMEMG64  = 2 * (2 * 128 * 144 + 2 * 64 * 144);
    cudaFuncSetAttribute(gat_attn_mma<128>, cudaFuncAttributeMaxDynamicSharedMemorySize, SMEM1);
    cudaFuncSetAttribute(gat_attn_mma<32>,  cudaFuncAttributeMaxDynamicSharedMemorySize, SMEM2);
    cudaFuncSetAttribute(gemm_h_fused<128>, cudaFuncAttributeMaxDynamicSharedMemorySize, SMEMG128);
    cudaFuncSetAttribute(gemm_h_fused<32>,  cudaFuncAttributeMaxDynamicSharedMemorySize, SMEMG128);
    cudaFuncSetAttribute(gemm_mma<64>,  cudaFuncAttributeMaxDynamicSharedMemorySize, SMEMG64);

    // 1) adjacency bitmask + max-encoder init
    pack_adj_kernel<<<NN * 128 / 8, 256>>>(adj);
    // 2) fused prep: split x, transpose-split W1 / lw1 / W2
    prep_kernel<<<2344, dim3(32, 8)>>>(x, W1, lw1, W2);
    // 3) h1 GEMM fused: transposed split ht1 + es1/ed1 + max encoders
    gemm_h_fused<128><<<dim3(32, 4), 256, SMEMG128>>>(
        p_xhi, p_xlo, p_w1th, p_w1tl, a1s, a1d, p_es1, p_ed1, p_mx1e,
        p_t1h, p_t1l, 512);
    // 4) layer-1 attention (split-j, unnormalized)   [PROFILED LAUNCH]
    gat_attn_mma<128><<<dim3(32, HH, 2), 256, SMEM1>>>(
        p_t1h, p_t1l, p_es1, p_ed1, p_mx1e, p_x1acc, p_ps1);
    // 5) combine halves -> x1 split
    combine_split_kernel<128><<<NN * 512 / 4 / 256, 256>>>(
        p_x1acc, p_ps1, p_x1hi, p_x1lo, nullptr);
    // 6) y1 = x1 @ lw1 + lb1
    gemm_mma<64><<<dim3(32, 1), 256, SMEMG64>>>(p_x1hi, p_x1lo, p_lw1th, p_lw1tl,
                                                lb1, p_y1, NN, 512, 64);
    // 7) x2 = BN_ELU(y1), split only
    bn_elu_kernel<<<64, 256>>>(p_y1, g1, be1, nullptr, p_x2hi, p_x2lo, 64);
    // 8) h2 GEMM fused
    gemm_h_fused<32><<<dim3(32, 1), 256, SMEMG128>>>(
        p_x2hi, p_x2lo, p_w2th, p_w2tl, a2s, a2d, p_es2, p_ed2, p_mx2e,
        p_t2h, p_t2l, 64);
    // 9) layer-2 attention (split-j)
    gat_attn_mma<32><<<dim3(32, HH, 2), 256, SMEM2>>>(
        p_t2h, p_t2l, p_es2, p_ed2, p_mx2e, p_x3acc, p_ps2);
    // 10) combine halves -> x3 fp32
    combine_split_kernel<32><<<NN * 128 / 4 / 256, 256>>>(
        p_x3acc, p_ps2, nullptr, nullptr, p_x3);
    // 11) final tiny layer
    gemm_bias_kernel<16, 4, 1><<<dim3(64, 1), 256>>>(p_x3, lw2, lb2, p_y2, NN, 128, 16);
    // 12) out
    bn_elu_kernel<<<16, 256>>>(p_y2, g2, be2, out, nullptr, nullptr, 16);
}